// round 8
// baseline (speedup 1.0000x reference)
#include <cuda_runtime.h>
#include <cuda_bf16.h>
#include <math.h>
#include <stdint.h>

#define Bz  8
#define Tz  512
#define Hz  768
#define NHz 12
#define HDz 64
#define FFz 3072
#define Lz  12
#define Mz  (Bz*Tz)   // 4096

// ---------------- fp32 scratch ----------------
__device__ float g_q[Mz*Hz];
__device__ float g_k[Mz*Hz];
__device__ float g_v[Mz*Hz];
__device__ float g_proj[Mz*Hz];
__device__ float g_attn[Mz*Hz];
__device__ float g_x[Mz*Hz];

// ---------------- split (hi/lo bf16) activation scratch ----------------
__device__ __nv_bfloat16 g_x_h[Mz*Hz],    g_x_l[Mz*Hz];
__device__ __nv_bfloat16 g_attn_h[Mz*Hz], g_attn_l[Mz*Hz];
__device__ __nv_bfloat16 g_ctx_h[Mz*Hz],  g_ctx_l[Mz*Hz];
__device__ __nv_bfloat16 g_ff_h[Mz*FFz],  g_ff_l[Mz*FFz];

// ---------------- split weight storage ([L][K][N], hi/lo) ----------------
__device__ __nv_bfloat16 g_wq_h[Lz*Hz*Hz],  g_wq_l[Lz*Hz*Hz];
__device__ __nv_bfloat16 g_wk_h[Lz*Hz*Hz],  g_wk_l[Lz*Hz*Hz];
__device__ __nv_bfloat16 g_wv_h[Lz*Hz*Hz],  g_wv_l[Lz*Hz*Hz];
__device__ __nv_bfloat16 g_wao_h[Lz*Hz*Hz], g_wao_l[Lz*Hz*Hz];
__device__ __nv_bfloat16 g_wi_h[Lz*Hz*FFz], g_wi_l[Lz*Hz*FFz];
__device__ __nv_bfloat16 g_wo_h[Lz*Hz*FFz], g_wo_l[Lz*Hz*FFz];

// ---------------- helpers ----------------
__device__ __forceinline__ void split1(float x, __nv_bfloat16& h, __nv_bfloat16& l) {
    h = __float2bfloat16(x);
    l = __float2bfloat16(x - __bfloat162float(h));
}
__device__ __forceinline__ void split2(float x, float y, uint32_t& hi, uint32_t& lo) {
    __nv_bfloat16 xh, xl, yh, yl;
    split1(x, xh, xl); split1(y, yh, yl);
    hi = (uint32_t)__bfloat16_as_ushort(xh) | ((uint32_t)__bfloat16_as_ushort(yh) << 16);
    lo = (uint32_t)__bfloat16_as_ushort(xl) | ((uint32_t)__bfloat16_as_ushort(yl) << 16);
}

// -------- merged prepass: split 7 tensors in ONE launch (keeps ncu -s 5 window clear) --------
struct SplitArgs {
    const float* in[7];
    __nv_bfloat16* h[7];
    __nv_bfloat16* l[7];
    int nblk[7];   // blocks per segment (each block = 256 float4)
};

__global__ __launch_bounds__(256) void split_all_kernel(SplitArgs A)
{
    int b = blockIdx.x;
    int seg = 0;
#pragma unroll
    for (int s = 0; s < 7; s++) {
        if (b < A.nblk[s]) { seg = s; break; }
        b -= A.nblk[s];
    }
    const int i = b * 256 + threadIdx.x;
    float4 v = ((const float4*)A.in[seg])[i];
    uint32_t h01, l01, h23, l23;
    split2(v.x, v.y, h01, l01);
    split2(v.z, v.w, h23, l23);
    ((uint2*)A.h[seg])[i] = make_uint2(h01, h23);
    ((uint2*)A.l[seg])[i] = make_uint2(l01, l23);
}

// ===== bf16x3 mma.sync GEMM: BK=32, 3 stages, XOR-swizzled smem, 2 CTAs/SM =====
#define BM 128
#define BN 128
#define BK2 32

#define PLANE 4096
#define STG_ELEMS (4*PLANE)
#define GEMM_SMEM (3*STG_ELEMS*2)

#define ASOFFZ(s,pl,m,c)  ((s)*STG_ELEMS + (pl)*PLANE + (m)*32  + ((((c) ^ (((m)>>1)&3)))<<3))
#define BSOFFZ(s,pl,kk,c) ((s)*STG_ELEMS + 2*PLANE + (pl)*PLANE + (kk)*128 + ((((c) ^ ((kk)&7)))<<3))

struct GemmArgs {
    const __nv_bfloat16 *Ah, *Al;
    const __nv_bfloat16 *Bh[3], *Bl[3];
    const float* bias[3];
    float* C[3];
    __nv_bfloat16 *Ch, *Cl;
};

__device__ __forceinline__ void cpa16(void* dst, const void* src) {
    uint32_t d = (uint32_t)__cvta_generic_to_shared(dst);
    asm volatile("cp.async.cg.shared.global [%0], [%1], 16;" :: "r"(d), "l"(src));
}
__device__ __forceinline__ void ldsm4(uint32_t* r, const void* p) {
    uint32_t a = (uint32_t)__cvta_generic_to_shared(p);
    asm volatile("ldmatrix.sync.aligned.m8n8.x4.shared.b16 {%0,%1,%2,%3}, [%4];"
                 : "=r"(r[0]), "=r"(r[1]), "=r"(r[2]), "=r"(r[3]) : "r"(a));
}
__device__ __forceinline__ void ldsm4t(uint32_t* r, const void* p) {
    uint32_t a = (uint32_t)__cvta_generic_to_shared(p);
    asm volatile("ldmatrix.sync.aligned.m8n8.x4.trans.shared.b16 {%0,%1,%2,%3}, [%4];"
                 : "=r"(r[0]), "=r"(r[1]), "=r"(r[2]), "=r"(r[3]) : "r"(a));
}
__device__ __forceinline__ void mma16816(float* c, const uint32_t* a, const uint32_t* b) {
    asm volatile(
        "mma.sync.aligned.m16n8k16.row.col.f32.bf16.bf16.f32 "
        "{%0,%1,%2,%3}, {%4,%5,%6,%7}, {%8,%9}, {%0,%1,%2,%3};"
        : "+f"(c[0]), "+f"(c[1]), "+f"(c[2]), "+f"(c[3])
        : "r"(a[0]), "r"(a[1]), "r"(a[2]), "r"(a[3]), "r"(b[0]), "r"(b[1]));
}

template<int MODE>
__global__ __launch_bounds__(256, 2) void gemm_bf16x3(GemmArgs P, int K, int N)
{
    extern __shared__ __align__(16) __nv_bfloat16 sm[];

    const int z = blockIdx.z;
    const __nv_bfloat16* __restrict__ Ah = P.Ah;
    const __nv_bfloat16* __restrict__ Al = P.Al;
    const __nv_bfloat16* __restrict__ Bh = P.Bh[z];
    const __nv_bfloat16* __restrict__ Bl = P.Bl[z];
    const float* __restrict__ bias = P.bias[z];

    const int n0 = blockIdx.x * BN;
    const int m0 = blockIdx.y * BM;
    const int tid  = threadIdx.x;
    const int lane = tid & 31;
    const int warp = tid >> 5;
    const int warpM = warp >> 2;
    const int warpN = warp & 3;

    const int nT = K / BK2;

    auto issue = [&](int t, int s) {
        const int k0 = t * BK2;
#pragma unroll
        for (int p = 0; p < 2; p++) {
            const int idx = tid + p * 256;
            const int ar = idx >> 2, acc_ = idx & 3;
            cpa16(sm + ASOFFZ(s, 0, ar, acc_), Ah + (size_t)(m0 + ar) * K + k0 + acc_ * 8);
            cpa16(sm + ASOFFZ(s, 1, ar, acc_), Al + (size_t)(m0 + ar) * K + k0 + acc_ * 8);
            const int br = idx >> 4, bcc = idx & 15;
            cpa16(sm + BSOFFZ(s, 0, br, bcc), Bh + (size_t)(k0 + br) * N + n0 + bcc * 8);
            cpa16(sm + BSOFFZ(s, 1, br, bcc), Bl + (size_t)(k0 + br) * N + n0 + bcc * 8);
        }
        asm volatile("cp.async.commit_group;" ::: "memory");
    };

    issue(0, 0);
    issue(1, 1);

    float acc[4][4][4] = {};
    int s = 0;

    for (int t = 0; t < nT; t++) {
        if (t + 1 < nT) asm volatile("cp.async.wait_group 1;" ::: "memory");
        else            asm volatile("cp.async.wait_group 0;" ::: "memory");
        __syncthreads();

        // prefetch next-next stage immediately: its prior readers finished before this barrier
        if (t + 2 < nT) {
            int s2 = s + 2; if (s2 >= 3) s2 -= 3;
            issue(t + 2, s2);
        }

#pragma unroll
        for (int sub = 0; sub < 2; sub++) {
            uint32_t ah[4][4], al[4][4], bh[4][2], bl[4][2];
            const int cA = sub * 2 + (lane >> 4);
#pragma unroll
            for (int mi = 0; mi < 4; mi++) {
                const int arow = warpM * 64 + mi * 16 + (lane & 15);
                ldsm4(ah[mi], sm + ASOFFZ(s, 0, arow, cA));
                ldsm4(al[mi], sm + ASOFFZ(s, 1, arow, cA));
            }
            const int brow = sub * 16 + (lane & 15);
#pragma unroll
            for (int pr = 0; pr < 2; pr++) {
                const int cB = warpN * 4 + pr * 2 + (lane >> 4);
                uint32_t tmp[4];
                ldsm4t(tmp, sm + BSOFFZ(s, 0, brow, cB));
                bh[pr * 2][0] = tmp[0]; bh[pr * 2][1] = tmp[1];
                bh[pr * 2 + 1][0] = tmp[2]; bh[pr * 2 + 1][1] = tmp[3];
                ldsm4t(tmp, sm + BSOFFZ(s, 1, brow, cB));
                bl[pr * 2][0] = tmp[0]; bl[pr * 2][1] = tmp[1];
                bl[pr * 2 + 1][0] = tmp[2]; bl[pr * 2 + 1][1] = tmp[3];
            }
#pragma unroll
            for (int mi = 0; mi < 4; mi++)
#pragma unroll
                for (int ni = 0; ni < 4; ni++) {
                    mma16816(acc[mi][ni], ah[mi], bh[ni]);
                    mma16816(acc[mi][ni], ah[mi], bl[ni]);
                    mma16816(acc[mi][ni], al[mi], bh[ni]);
                }
        }
        if (++s == 3) s = 0;
    }

    const int g  = lane >> 2;
    const int tg = lane & 3;
#pragma unroll
    for (int mi = 0; mi < 4; mi++) {
#pragma unroll
        for (int ni = 0; ni < 4; ni++) {
            const int row = m0 + warpM * 64 + mi * 16 + g;
            const int col = n0 + warpN * 32 + ni * 8 + tg * 2;
            const float b0 = bias[col], b1 = bias[col + 1];
            float v0 = acc[mi][ni][0] + b0;
            float v1 = acc[mi][ni][1] + b1;
            float v2 = acc[mi][ni][2] + b0;
            float v3 = acc[mi][ni][3] + b1;
            if (MODE == 1) {
                v0 = 0.5f * v0 * (1.0f + erff(v0 * 0.70710678118654752f));
                v1 = 0.5f * v1 * (1.0f + erff(v1 * 0.70710678118654752f));
                v2 = 0.5f * v2 * (1.0f + erff(v2 * 0.70710678118654752f));
                v3 = 0.5f * v3 * (1.0f + erff(v3 * 0.70710678118654752f));
                uint32_t hw, lw;
                split2(v0, v1, hw, lw);
                *(uint32_t*)(P.Ch + (size_t)row * N + col) = hw;
                *(uint32_t*)(P.Cl + (size_t)row * N + col) = lw;
                split2(v2, v3, hw, lw);
                *(uint32_t*)(P.Ch + (size_t)(row + 8) * N + col) = hw;
                *(uint32_t*)(P.Cl + (size_t)(row + 8) * N + col) = lw;
            } else {
                float* C = P.C[z];
                *(float2*)(C + (size_t)row * N + col)       = make_float2(v0, v1);
                *(float2*)(C + (size_t)(row + 8) * N + col) = make_float2(v2, v3);
            }
        }
    }
}

// ---------------- fused attention (flash-style, fp32, LDS.128 everywhere) ----------------
#define SMP 68   // float4-aligned rows; 272B row stride -> conflict-free LDS.128
__global__ __launch_bounds__(256) void attention_kernel(
    const float* __restrict__ q, const float* __restrict__ k,
    const float* __restrict__ v, const float* __restrict__ mask,
    __nv_bfloat16* __restrict__ ctx_h, __nv_bfloat16* __restrict__ ctx_l)
{
    extern __shared__ float smf[];
    float* Qs  = smf;                 // [64][SMP] rows = q rows, cols = d
    float* Ks  = Qs + 64 * SMP;       // [64][SMP] rows = k rows, cols = d
    float* VsT = Ks + 64 * SMP;       // [64][SMP] rows = d,     cols = k rows (transposed)
    float* Ps  = VsT + 64 * SMP;      // [64][SMP] rows = q rows, cols = k rows
    float* rm = Ps + 64 * SMP;
    float* rl = rm + 64;
    float* rs = rl + 64;
    float* am = rs + 64;

    const int tx = threadIdx.x, ty = threadIdx.y;
    const int tid = ty * 16 + tx;
    const int bh = blockIdx.y;
    const int b = bh / NHz, h = bh % NHz;
    const int i0 = blockIdx.x * 64;
    const float scale = 0.125f;

#pragma unroll
    for (int it = 0; it < 4; it++) {
        int idx = tid + it * 256;
        int row = idx >> 4;
        int d4 = (idx & 15) * 4;
        float4 t = *(const float4*)(q + (size_t)(b * Tz + i0 + row) * Hz + h * HDz + d4);
        *(float4*)&Qs[row * SMP + d4] = t;
    }
    if (tid < 64) { rm[tid] = -1e30f; rl[tid] = 0.0f; }

    float acc[4][4] = {};

    for (int jc = 0; jc < Tz / 64; jc++) {
        const int j0 = jc * 64;
#pragma unroll
        for (int it = 0; it < 4; it++) {
            int idx = tid + it * 256;
            int row = idx >> 4;
            int d4 = (idx & 15) * 4;
            float4 t = *(const float4*)(k + (size_t)(b * Tz + j0 + row) * Hz + h * HDz + d4);
            *(float4*)&Ks[row * SMP + d4] = t;
            float4 tv = *(const float4*)(v + (size_t)(b * Tz + j0 + row) * Hz + h * HDz + d4);
            VsT[(d4 + 0) * SMP + row] = tv.x;
            VsT[(d4 + 1) * SMP + row] = tv.y;
            VsT[(d4 + 2) * SMP + row] = tv.z;
            VsT[(d4 + 3) * SMP + row] = tv.w;
        }
        if (tid < 64) am[tid] = (1.0f - mask[b * Tz + j0 + tid]) * -10000.0f;
        __syncthreads();

        // S = Q @ K^T, vectorized over d
        float s[4][4] = {};
#pragma unroll
        for (int d4 = 0; d4 < 64; d4 += 4) {
            float4 qv[4], kv[4];
#pragma unroll
            for (int i = 0; i < 4; i++) qv[i] = *(float4*)&Qs[(ty + 16 * i) * SMP + d4];
#pragma unroll
            for (int j = 0; j < 4; j++) kv[j] = *(float4*)&Ks[(tx + 16 * j) * SMP + d4];
#pragma unroll
            for (int i = 0; i < 4; i++)
#pragma unroll
                for (int j = 0; j < 4; j++) {
                    s[i][j] = fmaf(qv[i].x, kv[j].x, s[i][j]);
                    s[i][j] = fmaf(qv[i].y, kv[j].y, s[i][j]);
                    s[i][j] = fmaf(qv[i].z, kv[j].z, s[i][j]);
                    s[i][j] = fmaf(qv[i].w, kv[j].w, s[i][j]);
                }
        }
#pragma unroll
        for (int i = 0; i < 4; i++)
#pragma unroll
            for (int j = 0; j < 4; j++)
                Ps[(ty + 16 * i) * SMP + tx + 16 * j] = s[i][j] * scale + am[tx + 16 * j];
        __syncthreads();

        // parallel online softmax: 4 threads per row, float4 I/O
        {
            const int srow = tid >> 2;
            const int ssub = tid & 3;
            float* prow = Ps + srow * SMP + ssub * 16;
            const float mo = rm[srow];
            float4 pv[4];
            float cm = -1e30f;
#pragma unroll
            for (int c = 0; c < 4; c++) {
                pv[c] = *(float4*)&prow[c * 4];
                cm = fmaxf(cm, fmaxf(fmaxf(pv[c].x, pv[c].y), fmaxf(pv[c].z, pv[c].w)));
            }
            cm = fmaxf(cm, __shfl_xor_sync(0xffffffffu, cm, 1));
            cm = fmaxf(cm, __shfl_xor_sync(0xffffffffu, cm, 2));
            const float nm = fmaxf(mo, cm);
            float sum = 0.0f;
#pragma unroll
            for (int c = 0; c < 4; c++) {
                pv[c].x = __expf(pv[c].x - nm);
                pv[c].y = __expf(pv[c].y - nm);
                pv[c].z = __expf(pv[c].z - nm);
                pv[c].w = __expf(pv[c].w - nm);
                sum += pv[c].x + pv[c].y + pv[c].z + pv[c].w;
                *(float4*)&prow[c * 4] = pv[c];
            }
            sum += __shfl_xor_sync(0xffffffffu, sum, 1);
            sum += __shfl_xor_sync(0xffffffffu, sum, 2);
            if (ssub == 0) {
                const float sc = __expf(mo - nm);
                rl[srow] = rl[srow] * sc + sum;
                rm[srow] = nm;
                rs[srow] = sc;
            }
        }
        __syncthreads();

#pragma unroll
        for (int i = 0; i < 4; i++) {
            const float sc = rs[ty + 16 * i];
#pragma unroll
            for (int j = 0; j < 4; j++) acc[i][j] *= sc;
        }
        // O += P @ V, vectorized over jj via transposed V
#pragma unroll
        for (int jj4 = 0; jj4 < 64; jj4 += 4) {
            float4 pv[4], vv[4];
#pragma unroll
            for (int i = 0; i < 4; i++) pv[i] = *(float4*)&Ps[(ty + 16 * i) * SMP + jj4];
#pragma unroll
            for (int j = 0; j < 4; j++) vv[j] = *(float4*)&VsT[(tx + 16 * j) * SMP + jj4];
#pragma unroll
            for (int i = 0; i < 4; i++)
#pragma unroll
                for (int j = 0; j < 4; j++) {
                    acc[i][j] = fmaf(pv[i].x, vv[j].x, acc[i][j]);
                    acc[i][j] = fmaf(pv[i].y, vv[j].y, acc[i][j]);
                    acc[i][j] = fmaf(pv[i].z, vv[j].z, acc[i][j]);
                    acc[i][j] = fmaf(pv[i].w, vv[j].w, acc[i][j]);
                }
        }
        __syncthreads();
    }

#pragma unroll
    for (int i = 0; i < 4; i++) {
        const float inv = 1.0f / rl[ty + 16 * i];
#pragma unroll
        for (int j = 0; j < 4; j++) {
            size_t off = (size_t)(b * Tz + i0 + ty + 16 * i) * Hz + h * HDz + tx + 16 * j;
            float val = acc[i][j] * inv;
            __nv_bfloat16 hv, lv;
            split1(val, hv, lv);
            ctx_h[off] = hv;
            ctx_l[off] = lv;
        }
    }
}

// ---------------- residual + LayerNorm (fp32 + split out) ----------------
__device__ __forceinline__ float block_reduce_sum(float val, float* red) {
    const int lane = threadIdx.x & 31, w = threadIdx.x >> 5;
#pragma unroll
    for (int o = 16; o > 0; o >>= 1) val += __shfl_down_sync(0xffffffffu, val, o);
    if (lane == 0) red[w] = val;
    __syncthreads();
    if (w == 0) {
        float t = (lane < 8) ? red[lane] : 0.0f;
#pragma unroll
        for (int o = 4; o > 0; o >>= 1) t += __shfl_down_sync(0xffffffffu, t, o);
        if (lane == 0) red[0] = t;
    }
    __syncthreads();
    float r = red[0];
    __syncthreads();
    return r;
}

__global__ __launch_bounds__(256) void ln_kernel(
    const float* __restrict__ a, const float* __restrict__ res,
    const float* __restrict__ g, const float* __restrict__ bb,
    float* __restrict__ out,
    __nv_bfloat16* __restrict__ oh, __nv_bfloat16* __restrict__ ol)
{
    __shared__ float buf[Hz];
    __shared__ float red[32];
    const int row = blockIdx.x;
    const float* ap = a + (size_t)row * Hz;
    const float* rp = res + (size_t)row * Hz;

    float ls = 0.0f;
    for (int i = threadIdx.x; i < Hz; i += 256) {
        float vv = ap[i] + rp[i];
        buf[i] = vv;
        ls += vv;
    }
    const float mean = block_reduce_sum(ls, red) * (1.0f / Hz);

    float lq = 0.0f;
    for (int i = threadIdx.x; i < Hz; i += 256) {
        float d = buf[i] - mean;
        lq += d * d;
    }
    const float var = block_reduce_sum(lq, red) * (1.0f / Hz);
    const float rstd = rsqrtf(var + 1e-12f);

    for (int i = threadIdx.x; i < Hz; i += 256) {
        float y = (buf[i] - mean) * rstd * g[i] + bb[i];
        out[(size_t)row * Hz + i] = y;
        __nv_bfloat16 hv, lv;
        split1(y, hv, lv);
        oh[(size_t)row * Hz + i] = hv;
        ol[(size_t)row * Hz + i] = lv;
    }
}

// ---------------- launch ----------------
extern "C" void kernel_launch(void* const* d_in, const int* in_sizes, int n_in,
                              void* d_out, int out_size)
{
    const float* hidden = (const float*)d_in[0];
    const float* mask   = (const float*)d_in[1];
    const float* Wq  = (const float*)d_in[2];   const float* bq  = (const float*)d_in[3];
    const float* Wk  = (const float*)d_in[4];   const float* bk  = (const float*)d_in[5];
    const float* Wv  = (const float*)d_in[6];   const float* bv  = (const float*)d_in[7];
    const float* Wao = (const float*)d_in[8];   const float* bao = (const float*)d_in[9];
    const float* g1  = (const float*)d_in[10];  const float* b1  = (const float*)d_in[11];
    const float* Wi  = (const float*)d_in[12];  const float* bi  = (const float*)d_in[13];
    const float* Wo  = (const float*)d_in[14];  const float* bo  = (const float*)d_in[15];
    const float* g2  = (const float*)d_in[16];  const float* b2  = (const float*)d_in[17];
    float* out = (float*)d_out;

    float *q, *k, *v, *proj, *attn, *xb;
    cudaGetSymbolAddress((void**)&q,    g_q);
    cudaGetSymbolAddress((void**)&k,    g_k);
    cudaGetSymbolAddress((void**)&v,    g_v);
    cudaGetSymbolAddress((void**)&proj, g_proj);
    cudaGetSymbolAddress((void**)&attn, g_attn);
    cudaGetSymbolAddress((void**)&xb,   g_x);

    __nv_bfloat16 *xh, *xl, *ath, *atl, *cth, *ctl, *ffh, *ffl;
    cudaGetSymbolAddress((void**)&xh,  g_x_h);    cudaGetSymbolAddress((void**)&xl,  g_x_l);
    cudaGetSymbolAddress((void**)&ath, g_attn_h); cudaGetSymbolAddress((void**)&atl, g_attn_l);
    cudaGetSymbolAddress((void**)&cth, g_ctx_h);  cudaGetSymbolAddress((void**)&ctl, g_ctx_l);
    cudaGetSymbolAddress((void**)&ffh, g_ff_h);   cudaGetSymbolAddress((void**)&ffl, g_ff_l);

    __nv_bfloat16 *wqh, *wql, *wkh, *wkl, *wvh, *wvl, *waoh, *waol, *wih, *wil, *woh, *wol;
    cudaGetSymbolAddress((void**)&wqh,  g_wq_h);  cudaGetSymbolAddress((void**)&wql,  g_wq_l);
    cudaGetSymbolAddress((void**)&wkh,  g_wk_h);  cudaGetSymbolAddress((void**)&wkl,  g_wk_l);
    cudaGetSymbolAddress((void**)&wvh,  g_wv_h);  cudaGetSymbolAddress((void**)&wvl,  g_wv_l);
    cudaGetSymbolAddress((void**)&waoh, g_wao_h); cudaGetSymbolAddress((void**)&waol, g_wao_l);
    cudaGetSymbolAddress((void**)&wih,  g_wi_h);  cudaGetSymbolAddress((void**)&wil,  g_wi_l);
    cudaGetSymbolAddress((void**)&woh,  g_wo_h);  cudaGetSymbolAddress((void**)&wol,  g_wo_l);

    // merged prepass: ONE launch splits all weights + input
    {
        const int nHH = Lz * Hz * Hz, nHF = Lz * Hz * FFz, nX = Mz * Hz;
        SplitArgs A;
        A.in[0] = Wq;  A.h[0] = wqh;  A.l[0] = wql;  A.nblk[0] = nHH / 1024;
        A.in[1] = Wk;  A.h[1] = wkh;  A.l[1] = wkl;  A.nblk[1] = nHH / 1024;
        A.in[2] = Wv;  A.h[2] = wvh;  A.l[2] = wvl;  A.nblk[2] = nHH / 1024;
        A.in[3] = Wao; A.h[3] = waoh; A.l[3] = waol; A.nblk[3] = nHH / 1024;
        A.in[4] = Wi;  A.h[4] = wih;  A.l[4] = wil;  A.nblk[4] = nHF / 1024;
        A.in[5] = Wo;  A.h[5] = woh;  A.l[5] = wol;  A.nblk[5] = nHF / 1024;
        A.in[6] = hidden; A.h[6] = xh; A.l[6] = xl;  A.nblk[6] = nX / 1024;
        int total = 4 * (nHH / 1024) + 2 * (nHF / 1024) + nX / 1024;
        split_all_kernel<<<total, 256>>>(A);
    }

    const size_t att_smem = (size_t)(4 * 64 * SMP + 4 * 64) * sizeof(float);
    cudaFuncSetAttribute(attention_kernel,
                         cudaFuncAttributeMaxDynamicSharedMemorySize, (int)att_smem);
    cudaFuncSetAttribute(gemm_bf16x3<0>,
                         cudaFuncAttributeMaxDynamicSharedMemorySize, GEMM_SMEM);
    cudaFuncSetAttribute(gemm_bf16x3<1>,
                         cudaFuncAttributeMaxDynamicSharedMemorySize, GEMM_SMEM);

    dim3 gAtt(Tz / 64, Bz * NHz);
    dim3 blkA(16, 16);

    for (int l = 0; l < Lz; l++) {
        const float* xres = (l == 0) ? hidden : xb;
        const size_t oHH = (size_t)l * Hz * Hz;
        const size_t oHF = (size_t)l * Hz * FFz;
        const size_t oH  = (size_t)l * Hz;
        const size_t oF  = (size_t)l * FFz;

        {   // fused QKV
            GemmArgs P = {};
            P.Ah = xh; P.Al = xl;
            P.Bh[0] = wqh + oHH; P.Bl[0] = wql + oHH;
            P.Bh[1] = wkh + oHH; P.Bl[1] = wkl + oHH;
            P.Bh[2] = wvh + oHH; P.Bl[2] = wvl + oHH;
            P.bias[0] = bq + oH; P.bias[1] = bk + oH; P.bias[2] = bv + oH;
            P.C[0] = q; P.C[1] = k; P.C[2] = v;
            gemm_bf16x3<0><<<dim3(Hz / BN, Mz / BM, 3), 256, GEMM_SMEM>>>(P, Hz, Hz);
        }

        attention_kernel<<<gAtt, blkA, att_smem>>>(q, k, v, mask, cth, ctl);

        {   // attention output projection
            GemmArgs P = {};
            P.Ah = cth; P.Al = ctl;
            P.Bh[0] = waoh + oHH; P.Bl[0] = waol + oHH;
            P.bias[0] = bao + oH;
            P.C[0] = proj;
            gemm_bf16x3<0><<<dim3(Hz / BN, Mz / BM, 1), 256, GEMM_SMEM>>>(P, Hz, Hz);
        }
        ln_kernel<<<Mz, 256>>>(proj, xres, g1 + oH, b1 + oH, attn, ath, atl);

        {   // FF1 + GELU (split bf16 out)
            GemmArgs P = {};
            P.Ah = ath; P.Al = atl;
            P.Bh[0] = wih + oHF; P.Bl[0] = wil + oHF;
            P.bias[0] = bi + oF;
            P.Ch = ffh; P.Cl = ffl;
            gemm_bf16x3<1><<<dim3(FFz / BN, Mz / BM, 1), 256, GEMM_SMEM>>>(P, Hz, FFz);
        }
        {   // FF2
            GemmArgs P = {};
            P.Ah = ffh; P.Al = ffl;
            P.Bh[0] = woh + oHF; P.Bl[0] = wol + oHF;
            P.bias[0] = bo + oH;
            P.C[0] = proj;
            gemm_bf16x3<0><<<dim3(Hz / BN, Mz / BM, 1), 256, GEMM_SMEM>>>(P, FFz, Hz);
        }
        ln_kernel<<<Mz, 256>>>(proj, attn, g2 + oH, b2 + oH,
                               (l == Lz - 1) ? out : xb, xh, xl);
    }
}

// round 9
// speedup vs baseline: 1.0206x; 1.0206x over previous
#include <cuda_runtime.h>
#include <cuda_bf16.h>
#include <math.h>
#include <stdint.h>

#define Bz  8
#define Tz  512
#define Hz  768
#define NHz 12
#define HDz 64
#define FFz 3072
#define Lz  12
#define Mz  (Bz*Tz)   // 4096

// ---------------- fp32 scratch ----------------
__device__ float g_q[Mz*Hz];
__device__ float g_k[Mz*Hz];
__device__ float g_v[Mz*Hz];
__device__ float g_proj[Mz*Hz];
__device__ float g_attn[Mz*Hz];
__device__ float g_x[Mz*Hz];

// ---------------- split (hi/lo bf16) activation scratch ----------------
__device__ __nv_bfloat16 g_x_h[Mz*Hz],    g_x_l[Mz*Hz];
__device__ __nv_bfloat16 g_attn_h[Mz*Hz], g_attn_l[Mz*Hz];
__device__ __nv_bfloat16 g_ctx_h[Mz*Hz],  g_ctx_l[Mz*Hz];
__device__ __nv_bfloat16 g_ff_h[Mz*FFz],  g_ff_l[Mz*FFz];

// ---------------- split weight storage ([L][K][N], hi/lo) ----------------
__device__ __nv_bfloat16 g_wq_h[Lz*Hz*Hz],  g_wq_l[Lz*Hz*Hz];
__device__ __nv_bfloat16 g_wk_h[Lz*Hz*Hz],  g_wk_l[Lz*Hz*Hz];
__device__ __nv_bfloat16 g_wv_h[Lz*Hz*Hz],  g_wv_l[Lz*Hz*Hz];
__device__ __nv_bfloat16 g_wao_h[Lz*Hz*Hz], g_wao_l[Lz*Hz*Hz];
__device__ __nv_bfloat16 g_wi_h[Lz*Hz*FFz], g_wi_l[Lz*Hz*FFz];
__device__ __nv_bfloat16 g_wo_h[Lz*Hz*FFz], g_wo_l[Lz*Hz*FFz];

// ---------------- helpers ----------------
__device__ __forceinline__ void split1(float x, __nv_bfloat16& h, __nv_bfloat16& l) {
    h = __float2bfloat16(x);
    l = __float2bfloat16(x - __bfloat162float(h));
}
__device__ __forceinline__ void split2(float x, float y, uint32_t& hi, uint32_t& lo) {
    __nv_bfloat16 xh, xl, yh, yl;
    split1(x, xh, xl); split1(y, yh, yl);
    hi = (uint32_t)__bfloat16_as_ushort(xh) | ((uint32_t)__bfloat16_as_ushort(yh) << 16);
    lo = (uint32_t)__bfloat16_as_ushort(xl) | ((uint32_t)__bfloat16_as_ushort(yl) << 16);
}

// -------- merged prepass: split 7 tensors in ONE launch --------
struct SplitArgs {
    const float* in[7];
    __nv_bfloat16* h[7];
    __nv_bfloat16* l[7];
    int nblk[7];
};

__global__ __launch_bounds__(256) void split_all_kernel(SplitArgs A)
{
    int b = blockIdx.x;
    int seg = 0;
#pragma unroll
    for (int s = 0; s < 7; s++) {
        if (b < A.nblk[s]) { seg = s; break; }
        b -= A.nblk[s];
    }
    const int i = b * 256 + threadIdx.x;
    float4 v = ((const float4*)A.in[seg])[i];
    uint32_t h01, l01, h23, l23;
    split2(v.x, v.y, h01, l01);
    split2(v.z, v.w, h23, l23);
    ((uint2*)A.h[seg])[i] = make_uint2(h01, h23);
    ((uint2*)A.l[seg])[i] = make_uint2(l01, l23);
}

// ===== bf16x3 mma.sync GEMM: BK=32, 3 stages, XOR-swizzled smem, 2 CTAs/SM =====
#define BM 128
#define BN 128
#define BK2 32

#define PLANE 4096
#define STG_ELEMS (4*PLANE)
#define GEMM_SMEM (3*STG_ELEMS*2)

#define ASOFFZ(s,pl,m,c)  ((s)*STG_ELEMS + (pl)*PLANE + (m)*32  + ((((c) ^ (((m)>>1)&3)))<<3))
#define BSOFFZ(s,pl,kk,c) ((s)*STG_ELEMS + 2*PLANE + (pl)*PLANE + (kk)*128 + ((((c) ^ ((kk)&7)))<<3))

struct GemmArgs {
    const __nv_bfloat16 *Ah, *Al;
    const __nv_bfloat16 *Bh[3], *Bl[3];
    const float* bias[3];
    float* C[3];
    __nv_bfloat16 *Ch, *Cl;
};

__device__ __forceinline__ void cpa16(void* dst, const void* src) {
    uint32_t d = (uint32_t)__cvta_generic_to_shared(dst);
    asm volatile("cp.async.cg.shared.global [%0], [%1], 16;" :: "r"(d), "l"(src));
}
__device__ __forceinline__ void ldsm4(uint32_t* r, const void* p) {
    uint32_t a = (uint32_t)__cvta_generic_to_shared(p);
    asm volatile("ldmatrix.sync.aligned.m8n8.x4.shared.b16 {%0,%1,%2,%3}, [%4];"
                 : "=r"(r[0]), "=r"(r[1]), "=r"(r[2]), "=r"(r[3]) : "r"(a));
}
__device__ __forceinline__ void ldsm4t(uint32_t* r, const void* p) {
    uint32_t a = (uint32_t)__cvta_generic_to_shared(p);
    asm volatile("ldmatrix.sync.aligned.m8n8.x4.trans.shared.b16 {%0,%1,%2,%3}, [%4];"
                 : "=r"(r[0]), "=r"(r[1]), "=r"(r[2]), "=r"(r[3]) : "r"(a));
}
__device__ __forceinline__ void mma16816(float* c, const uint32_t* a, const uint32_t* b) {
    asm volatile(
        "mma.sync.aligned.m16n8k16.row.col.f32.bf16.bf16.f32 "
        "{%0,%1,%2,%3}, {%4,%5,%6,%7}, {%8,%9}, {%0,%1,%2,%3};"
        : "+f"(c[0]), "+f"(c[1]), "+f"(c[2]), "+f"(c[3])
        : "r"(a[0]), "r"(a[1]), "r"(a[2]), "r"(a[3]), "r"(b[0]), "r"(b[1]));
}

template<int MODE>
__global__ __launch_bounds__(256, 2) void gemm_bf16x3(GemmArgs P, int K, int N)
{
    extern __shared__ __align__(16) __nv_bfloat16 sm[];

    const int z = blockIdx.z;
    const __nv_bfloat16* __restrict__ Ah = P.Ah;
    const __nv_bfloat16* __restrict__ Al = P.Al;
    const __nv_bfloat16* __restrict__ Bh = P.Bh[z];
    const __nv_bfloat16* __restrict__ Bl = P.Bl[z];
    const float* __restrict__ bias = P.bias[z];

    const int n0 = blockIdx.x * BN;
    const int m0 = blockIdx.y * BM;
    const int tid  = threadIdx.x;
    const int lane = tid & 31;
    const int warp = tid >> 5;
    const int warpM = warp >> 2;
    const int warpN = warp & 3;

    const int nT = K / BK2;

    auto issue = [&](int t, int s) {
        const int k0 = t * BK2;
#pragma unroll
        for (int p = 0; p < 2; p++) {
            const int idx = tid + p * 256;
            const int ar = idx >> 2, acc_ = idx & 3;
            cpa16(sm + ASOFFZ(s, 0, ar, acc_), Ah + (size_t)(m0 + ar) * K + k0 + acc_ * 8);
            cpa16(sm + ASOFFZ(s, 1, ar, acc_), Al + (size_t)(m0 + ar) * K + k0 + acc_ * 8);
            const int br = idx >> 4, bcc = idx & 15;
            cpa16(sm + BSOFFZ(s, 0, br, bcc), Bh + (size_t)(k0 + br) * N + n0 + bcc * 8);
            cpa16(sm + BSOFFZ(s, 1, br, bcc), Bl + (size_t)(k0 + br) * N + n0 + bcc * 8);
        }
        asm volatile("cp.async.commit_group;" ::: "memory");
    };

    issue(0, 0);
    issue(1, 1);

    float acc[4][4][4] = {};
    int s = 0;

    for (int t = 0; t < nT; t++) {
        if (t + 1 < nT) asm volatile("cp.async.wait_group 1;" ::: "memory");
        else            asm volatile("cp.async.wait_group 0;" ::: "memory");
        __syncthreads();

        if (t + 2 < nT) {
            int s2 = s + 2; if (s2 >= 3) s2 -= 3;
            issue(t + 2, s2);
        }

#pragma unroll
        for (int sub = 0; sub < 2; sub++) {
            uint32_t ah[4][4], al[4][4], bh[4][2], bl[4][2];
            const int cA = sub * 2 + (lane >> 4);
#pragma unroll
            for (int mi = 0; mi < 4; mi++) {
                const int arow = warpM * 64 + mi * 16 + (lane & 15);
                ldsm4(ah[mi], sm + ASOFFZ(s, 0, arow, cA));
                ldsm4(al[mi], sm + ASOFFZ(s, 1, arow, cA));
            }
            const int brow = sub * 16 + (lane & 15);
#pragma unroll
            for (int pr = 0; pr < 2; pr++) {
                const int cB = warpN * 4 + pr * 2 + (lane >> 4);
                uint32_t tmp[4];
                ldsm4t(tmp, sm + BSOFFZ(s, 0, brow, cB));
                bh[pr * 2][0] = tmp[0]; bh[pr * 2][1] = tmp[1];
                bh[pr * 2 + 1][0] = tmp[2]; bh[pr * 2 + 1][1] = tmp[3];
                ldsm4t(tmp, sm + BSOFFZ(s, 1, brow, cB));
                bl[pr * 2][0] = tmp[0]; bl[pr * 2][1] = tmp[1];
                bl[pr * 2 + 1][0] = tmp[2]; bl[pr * 2 + 1][1] = tmp[3];
            }
            // term-major ordering: 16 independent accumulators between reuses
#pragma unroll
            for (int mi = 0; mi < 4; mi++)
#pragma unroll
                for (int ni = 0; ni < 4; ni++)
                    mma16816(acc[mi][ni], ah[mi], bh[ni]);
#pragma unroll
            for (int mi = 0; mi < 4; mi++)
#pragma unroll
                for (int ni = 0; ni < 4; ni++)
                    mma16816(acc[mi][ni], ah[mi], bl[ni]);
#pragma unroll
            for (int mi = 0; mi < 4; mi++)
#pragma unroll
                for (int ni = 0; ni < 4; ni++)
                    mma16816(acc[mi][ni], al[mi], bh[ni]);
        }
        if (++s == 3) s = 0;
    }

    const int g  = lane >> 2;
    const int tg = lane & 3;
#pragma unroll
    for (int mi = 0; mi < 4; mi++) {
#pragma unroll
        for (int ni = 0; ni < 4; ni++) {
            const int row = m0 + warpM * 64 + mi * 16 + g;
            const int col = n0 + warpN * 32 + ni * 8 + tg * 2;
            const float b0 = bias[col], b1 = bias[col + 1];
            float v0 = acc[mi][ni][0] + b0;
            float v1 = acc[mi][ni][1] + b1;
            float v2 = acc[mi][ni][2] + b0;
            float v3 = acc[mi][ni][3] + b1;
            if (MODE == 1) {
                v0 = 0.5f * v0 * (1.0f + erff(v0 * 0.70710678118654752f));
                v1 = 0.5f * v1 * (1.0f + erff(v1 * 0.70710678118654752f));
                v2 = 0.5f * v2 * (1.0f + erff(v2 * 0.70710678118654752f));
                v3 = 0.5f * v3 * (1.0f + erff(v3 * 0.70710678118654752f));
                uint32_t hw, lw;
                split2(v0, v1, hw, lw);
                *(uint32_t*)(P.Ch + (size_t)row * N + col) = hw;
                *(uint32_t*)(P.Cl + (size_t)row * N + col) = lw;
                split2(v2, v3, hw, lw);
                *(uint32_t*)(P.Ch + (size_t)(row + 8) * N + col) = hw;
                *(uint32_t*)(P.Cl + (size_t)(row + 8) * N + col) = lw;
            } else {
                float* C = P.C[z];
                *(float2*)(C + (size_t)row * N + col)       = make_float2(v0, v1);
                *(float2*)(C + (size_t)(row + 8) * N + col) = make_float2(v2, v3);
            }
        }
    }
}

// ---------------- fused attention (flash-style, fp32, LDS.128 everywhere) ----------------
#define SMP 68
__global__ __launch_bounds__(256) void attention_kernel(
    const float* __restrict__ q, const float* __restrict__ k,
    const float* __restrict__ v, const float* __restrict__ mask,
    __nv_bfloat16* __restrict__ ctx_h, __nv_bfloat16* __restrict__ ctx_l)
{
    extern __shared__ float smf[];
    float* Qs  = smf;
    float* Ks  = Qs + 64 * SMP;
    float* VsT = Ks + 64 * SMP;
    float* Ps  = VsT + 64 * SMP;
    float* rm = Ps + 64 * SMP;
    float* rl = rm + 64;
    float* rs = rl + 64;
    float* am = rs + 64;

    const int tx = threadIdx.x, ty = threadIdx.y;
    const int tid = ty * 16 + tx;
    const int bh = blockIdx.y;
    const int b = bh / NHz, h = bh % NHz;
    const int i0 = blockIdx.x * 64;
    const float scale = 0.125f;

#pragma unroll
    for (int it = 0; it < 4; it++) {
        int idx = tid + it * 256;
        int row = idx >> 4;
        int d4 = (idx & 15) * 4;
        float4 t = *(const float4*)(q + (size_t)(b * Tz + i0 + row) * Hz + h * HDz + d4);
        *(float4*)&Qs[row * SMP + d4] = t;
    }
    if (tid < 64) { rm[tid] = -1e30f; rl[tid] = 0.0f; }

    float acc[4][4] = {};

    for (int jc = 0; jc < Tz / 64; jc++) {
        const int j0 = jc * 64;
#pragma unroll
        for (int it = 0; it < 4; it++) {
            int idx = tid + it * 256;
            int row = idx >> 4;
            int d4 = (idx & 15) * 4;
            float4 t = *(const float4*)(k + (size_t)(b * Tz + j0 + row) * Hz + h * HDz + d4);
            *(float4*)&Ks[row * SMP + d4] = t;
            float4 tv = *(const float4*)(v + (size_t)(b * Tz + j0 + row) * Hz + h * HDz + d4);
            VsT[(d4 + 0) * SMP + row] = tv.x;
            VsT[(d4 + 1) * SMP + row] = tv.y;
            VsT[(d4 + 2) * SMP + row] = tv.z;
            VsT[(d4 + 3) * SMP + row] = tv.w;
        }
        if (tid < 64) am[tid] = (1.0f - mask[b * Tz + j0 + tid]) * -10000.0f;
        __syncthreads();

        float s[4][4] = {};
#pragma unroll
        for (int d4 = 0; d4 < 64; d4 += 4) {
            float4 qv[4], kv[4];
#pragma unroll
            for (int i = 0; i < 4; i++) qv[i] = *(float4*)&Qs[(ty + 16 * i) * SMP + d4];
#pragma unroll
            for (int j = 0; j < 4; j++) kv[j] = *(float4*)&Ks[(tx + 16 * j) * SMP + d4];
#pragma unroll
            for (int i = 0; i < 4; i++)
#pragma unroll
                for (int j = 0; j < 4; j++) {
                    s[i][j] = fmaf(qv[i].x, kv[j].x, s[i][j]);
                    s[i][j] = fmaf(qv[i].y, kv[j].y, s[i][j]);
                    s[i][j] = fmaf(qv[i].z, kv[j].z, s[i][j]);
                    s[i][j] = fmaf(qv[i].w, kv[j].w, s[i][j]);
                }
        }
#pragma unroll
        for (int i = 0; i < 4; i++)
#pragma unroll
            for (int j = 0; j < 4; j++)
                Ps[(ty + 16 * i) * SMP + tx + 16 * j] = s[i][j] * scale + am[tx + 16 * j];
        __syncthreads();

        {
            const int srow = tid >> 2;
            const int ssub = tid & 3;
            float* prow = Ps + srow * SMP + ssub * 16;
            const float mo = rm[srow];
            float4 pv[4];
            float cm = -1e30f;
#pragma unroll
            for (int c = 0; c < 4; c++) {
                pv[c] = *(float4*)&prow[c * 4];
                cm = fmaxf(cm, fmaxf(fmaxf(pv[c].x, pv[c].y), fmaxf(pv[c].z, pv[c].w)));
            }
            cm = fmaxf(cm, __shfl_xor_sync(0xffffffffu, cm, 1));
            cm = fmaxf(cm, __shfl_xor_sync(0xffffffffu, cm, 2));
            const float nm = fmaxf(mo, cm);
            float sum = 0.0f;
#pragma unroll
            for (int c = 0; c < 4; c++) {
                pv[c].x = __expf(pv[c].x - nm);
                pv[c].y = __expf(pv[c].y - nm);
                pv[c].z = __expf(pv[c].z - nm);
                pv[c].w = __expf(pv[c].w - nm);
                sum += pv[c].x + pv[c].y + pv[c].z + pv[c].w;
                *(float4*)&prow[c * 4] = pv[c];
            }
            sum += __shfl_xor_sync(0xffffffffu, sum, 1);
            sum += __shfl_xor_sync(0xffffffffu, sum, 2);
            if (ssub == 0) {
                const float sc = __expf(mo - nm);
                rl[srow] = rl[srow] * sc + sum;
                rm[srow] = nm;
                rs[srow] = sc;
            }
        }
        __syncthreads();

#pragma unroll
        for (int i = 0; i < 4; i++) {
            const float sc = rs[ty + 16 * i];
#pragma unroll
            for (int j = 0; j < 4; j++) acc[i][j] *= sc;
        }
#pragma unroll
        for (int jj4 = 0; jj4 < 64; jj4 += 4) {
            float4 pv[4], vv[4];
#pragma unroll
            for (int i = 0; i < 4; i++) pv[i] = *(float4*)&Ps[(ty + 16 * i) * SMP + jj4];
#pragma unroll
            for (int j = 0; j < 4; j++) vv[j] = *(float4*)&VsT[(tx + 16 * j) * SMP + jj4];
#pragma unroll
            for (int i = 0; i < 4; i++)
#pragma unroll
                for (int j = 0; j < 4; j++) {
                    acc[i][j] = fmaf(pv[i].x, vv[j].x, acc[i][j]);
                    acc[i][j] = fmaf(pv[i].y, vv[j].y, acc[i][j]);
                    acc[i][j] = fmaf(pv[i].z, vv[j].z, acc[i][j]);
                    acc[i][j] = fmaf(pv[i].w, vv[j].w, acc[i][j]);
                }
        }
        __syncthreads();
    }

#pragma unroll
    for (int i = 0; i < 4; i++) {
        const float inv = 1.0f / rl[ty + 16 * i];
#pragma unroll
        for (int j = 0; j < 4; j++) {
            size_t off = (size_t)(b * Tz + i0 + ty + 16 * i) * Hz + h * HDz + tx + 16 * j;
            float val = acc[i][j] * inv;
            __nv_bfloat16 hv, lv;
            split1(val, hv, lv);
            ctx_h[off] = hv;
            ctx_l[off] = lv;
        }
    }
}

// ---------------- residual + LayerNorm (fp32 + split out) ----------------
__device__ __forceinline__ float block_reduce_sum(float val, float* red) {
    const int lane = threadIdx.x & 31, w = threadIdx.x >> 5;
#pragma unroll
    for (int o = 16; o > 0; o >>= 1) val += __shfl_down_sync(0xffffffffu, val, o);
    if (lane == 0) red[w] = val;
    __syncthreads();
    if (w == 0) {
        float t = (lane < 8) ? red[lane] : 0.0f;
#pragma unroll
        for (int o = 4; o > 0; o >>= 1) t += __shfl_down_sync(0xffffffffu, t, o);
        if (lane == 0) red[0] = t;
    }
    __syncthreads();
    float r = red[0];
    __syncthreads();
    return r;
}

__global__ __launch_bounds__(256) void ln_kernel(
    const float* __restrict__ a, const float* __restrict__ res,
    const float* __restrict__ g, const float* __restrict__ bb,
    float* __restrict__ out,
    __nv_bfloat16* __restrict__ oh, __nv_bfloat16* __restrict__ ol)
{
    __shared__ float buf[Hz];
    __shared__ float red[32];
    const int row = blockIdx.x;
    const float* ap = a + (size_t)row * Hz;
    const float* rp = res + (size_t)row * Hz;

    float ls = 0.0f;
    for (int i = threadIdx.x; i < Hz; i += 256) {
        float vv = ap[i] + rp[i];
        buf[i] = vv;
        ls += vv;
    }
    const float mean = block_reduce_sum(ls, red) * (1.0f / Hz);

    float lq = 0.0f;
    for (int i = threadIdx.x; i < Hz; i += 256) {
        float d = buf[i] - mean;
        lq += d * d;
    }
    const float var = block_reduce_sum(lq, red) * (1.0f / Hz);
    const float rstd = rsqrtf(var + 1e-12f);

    for (int i = threadIdx.x; i < Hz; i += 256) {
        float y = (buf[i] - mean) * rstd * g[i] + bb[i];
        out[(size_t)row * Hz + i] = y;
        __nv_bfloat16 hv, lv;
        split1(y, hv, lv);
        oh[(size_t)row * Hz + i] = hv;
        ol[(size_t)row * Hz + i] = lv;
    }
}

// ---------------- launch ----------------
extern "C" void kernel_launch(void* const* d_in, const int* in_sizes, int n_in,
                              void* d_out, int out_size)
{
    const float* hidden = (const float*)d_in[0];
    const float* mask   = (const float*)d_in[1];
    const float* Wq  = (const float*)d_in[2];   const float* bq  = (const float*)d_in[3];
    const float* Wk  = (const float*)d_in[4];   const float* bk  = (const float*)d_in[5];
    const float* Wv  = (const float*)d_in[6];   const float* bv  = (const float*)d_in[7];
    const float* Wao = (const float*)d_in[8];   const float* bao = (const float*)d_in[9];
    const float* g1  = (const float*)d_in[10];  const float* b1  = (const float*)d_in[11];
    const float* Wi  = (const float*)d_in[12];  const float* bi  = (const float*)d_in[13];
    const float* Wo  = (const float*)d_in[14];  const float* bo  = (const float*)d_in[15];
    const float* g2  = (const float*)d_in[16];  const float* b2  = (const float*)d_in[17];
    float* out = (float*)d_out;

    float *q, *k, *v, *proj, *attn, *xb;
    cudaGetSymbolAddress((void**)&q,    g_q);
    cudaGetSymbolAddress((void**)&k,    g_k);
    cudaGetSymbolAddress((void**)&v,    g_v);
    cudaGetSymbolAddress((void**)&proj, g_proj);
    cudaGetSymbolAddress((void**)&attn, g_attn);
    cudaGetSymbolAddress((void**)&xb,   g_x);

    __nv_bfloat16 *xh, *xl, *ath, *atl, *cth, *ctl, *ffh, *ffl;
    cudaGetSymbolAddress((void**)&xh,  g_x_h);    cudaGetSymbolAddress((void**)&xl,  g_x_l);
    cudaGetSymbolAddress((void**)&ath, g_attn_h); cudaGetSymbolAddress((void**)&atl, g_attn_l);
    cudaGetSymbolAddress((void**)&cth, g_ctx_h);  cudaGetSymbolAddress((void**)&ctl, g_ctx_l);
    cudaGetSymbolAddress((void**)&ffh, g_ff_h);   cudaGetSymbolAddress((void**)&ffl, g_ff_l);

    __nv_bfloat16 *wqh, *wql, *wkh, *wkl, *wvh, *wvl, *waoh, *waol, *wih, *wil, *woh, *wol;
    cudaGetSymbolAddress((void**)&wqh,  g_wq_h);  cudaGetSymbolAddress((void**)&wql,  g_wq_l);
    cudaGetSymbolAddress((void**)&wkh,  g_wk_h);  cudaGetSymbolAddress((void**)&wkl,  g_wk_l);
    cudaGetSymbolAddress((void**)&wvh,  g_wv_h);  cudaGetSymbolAddress((void**)&wvl,  g_wv_l);
    cudaGetSymbolAddress((void**)&waoh, g_wao_h); cudaGetSymbolAddress((void**)&waol, g_wao_l);
    cudaGetSymbolAddress((void**)&wih,  g_wi_h);  cudaGetSymbolAddress((void**)&wil,  g_wi_l);
    cudaGetSymbolAddress((void**)&woh,  g_wo_h);  cudaGetSymbolAddress((void**)&wol,  g_wo_l);

    // merged prepass: ONE launch splits all weights + input
    {
        const int nHH = Lz * Hz * Hz, nHF = Lz * Hz * FFz, nX = Mz * Hz;
        SplitArgs A;
        A.in[0] = Wq;  A.h[0] = wqh;  A.l[0] = wql;  A.nblk[0] = nHH / 1024;
        A.in[1] = Wk;  A.h[1] = wkh;  A.l[1] = wkl;  A.nblk[1] = nHH / 1024;
        A.in[2] = Wv;  A.h[2] = wvh;  A.l[2] = wvl;  A.nblk[2] = nHH / 1024;
        A.in[3] = Wao; A.h[3] = waoh; A.l[3] = waol; A.nblk[3] = nHH / 1024;
        A.in[4] = Wi;  A.h[4] = wih;  A.l[4] = wil;  A.nblk[4] = nHF / 1024;
        A.in[5] = Wo;  A.h[5] = woh;  A.l[5] = wol;  A.nblk[5] = nHF / 1024;
        A.in[6] = hidden; A.h[6] = xh; A.l[6] = xl;  A.nblk[6] = nX / 1024;
        int total = 4 * (nHH / 1024) + 2 * (nHF / 1024) + nX / 1024;
        split_all_kernel<<<total, 256>>>(A);
    }

    const size_t att_smem = (size_t)(4 * 64 * SMP + 4 * 64) * sizeof(float);
    cudaFuncSetAttribute(attention_kernel,
                         cudaFuncAttributeMaxDynamicSharedMemorySize, (int)att_smem);
    cudaFuncSetAttribute(gemm_bf16x3<0>,
                         cudaFuncAttributeMaxDynamicSharedMemorySize, GEMM_SMEM);
    cudaFuncSetAttribute(gemm_bf16x3<1>,
                         cudaFuncAttributeMaxDynamicSharedMemorySize, GEMM_SMEM);

    dim3 gAtt(Tz / 64, Bz * NHz);
    dim3 blkA(16, 16);

    for (int l = 0; l < Lz; l++) {
        const float* xres = (l == 0) ? hidden : xb;
        const size_t oHH = (size_t)l * Hz * Hz;
        const size_t oHF = (size_t)l * Hz * FFz;
        const size_t oH  = (size_t)l * Hz;
        const size_t oF  = (size_t)l * FFz;

        {   // fused QKV
            GemmArgs P = {};
            P.Ah = xh; P.Al = xl;
            P.Bh[0] = wqh + oHH; P.Bl[0] = wql + oHH;
            P.Bh[1] = wkh + oHH; P.Bl[1] = wkl + oHH;
            P.Bh[2] = wvh + oHH; P.Bl[2] = wvl + oHH;
            P.bias[0] = bq + oH; P.bias[1] = bk + oH; P.bias[2] = bv + oH;
            P.C[0] = q; P.C[1] = k; P.C[2] = v;
            gemm_bf16x3<0><<<dim3(Hz / BN, Mz / BM, 3), 256, GEMM_SMEM>>>(P, Hz, Hz);
        }

        attention_kernel<<<gAtt, blkA, att_smem>>>(q, k, v, mask, cth, ctl);

        {   // attention output projection
            GemmArgs P = {};
            P.Ah = cth; P.Al = ctl;
            P.Bh[0] = waoh + oHH; P.Bl[0] = waol + oHH;
            P.bias[0] = bao + oH;
            P.C[0] = proj;
            gemm_bf16x3<0><<<dim3(Hz / BN, Mz / BM, 1), 256, GEMM_SMEM>>>(P, Hz, Hz);
        }
        ln_kernel<<<Mz, 256>>>(proj, xres, g1 + oH, b1 + oH, attn, ath, atl);

        {   // FF1 + GELU (split bf16 out)
            GemmArgs P = {};
            P.Ah = ath; P.Al = atl;
            P.Bh[0] = wih + oHF; P.Bl[0] = wil + oHF;
            P.bias[0] = bi + oF;
            P.Ch = ffh; P.Cl = ffl;
            gemm_bf16x3<1><<<dim3(FFz / BN, Mz / BM, 1), 256, GEMM_SMEM>>>(P, Hz, FFz);
        }
        {   // FF2
            GemmArgs P = {};
            P.Ah = ffh; P.Al = ffl;
            P.Bh[0] = woh + oHF; P.Bl[0] = wol + oHF;
            P.bias[0] = bo + oH;
            P.C[0] = proj;
            gemm_bf16x3<0><<<dim3(Hz / BN, Mz / BM, 1), 256, GEMM_SMEM>>>(P, FFz, Hz);
        }
        ln_kernel<<<Mz, 256>>>(proj, attn, g2 + oH, b2 + oH,
                               (l == Lz - 1) ? out : xb, xh, xl);
    }
}

// round 10
// speedup vs baseline: 1.1067x; 1.0843x over previous
#include <cuda_runtime.h>
#include <cuda_bf16.h>
#include <math.h>
#include <stdint.h>

#define Bz  8
#define Tz  512
#define Hz  768
#define NHz 12
#define HDz 64
#define FFz 3072
#define Lz  12
#define Mz  (Bz*Tz)   // 4096

// ---------------- fp32 scratch ----------------
__device__ float g_q[Mz*Hz];
__device__ float g_k[Mz*Hz];
__device__ float g_v[Mz*Hz];
__device__ float g_proj[Mz*Hz];    // partial 0
__device__ float g_proj2[Mz*Hz];   // partial 1
__device__ float g_attn[Mz*Hz];
__device__ float g_x[Mz*Hz];

// ---------------- split (hi/lo bf16) activation scratch ----------------
__device__ __nv_bfloat16 g_x_h[Mz*Hz],    g_x_l[Mz*Hz];
__device__ __nv_bfloat16 g_attn_h[Mz*Hz], g_attn_l[Mz*Hz];
__device__ __nv_bfloat16 g_ctx_h[Mz*Hz],  g_ctx_l[Mz*Hz];
__device__ __nv_bfloat16 g_ff_h[Mz*FFz],  g_ff_l[Mz*FFz];

// ---------------- split weight storage ([L][K][N], hi/lo) ----------------
__device__ __nv_bfloat16 g_wq_h[Lz*Hz*Hz],  g_wq_l[Lz*Hz*Hz];
__device__ __nv_bfloat16 g_wk_h[Lz*Hz*Hz],  g_wk_l[Lz*Hz*Hz];
__device__ __nv_bfloat16 g_wv_h[Lz*Hz*Hz],  g_wv_l[Lz*Hz*Hz];
__device__ __nv_bfloat16 g_wao_h[Lz*Hz*Hz], g_wao_l[Lz*Hz*Hz];
__device__ __nv_bfloat16 g_wi_h[Lz*Hz*FFz], g_wi_l[Lz*Hz*FFz];
__device__ __nv_bfloat16 g_wo_h[Lz*Hz*FFz], g_wo_l[Lz*Hz*FFz];

// ---------------- helpers ----------------
__device__ __forceinline__ void split1(float x, __nv_bfloat16& h, __nv_bfloat16& l) {
    h = __float2bfloat16(x);
    l = __float2bfloat16(x - __bfloat162float(h));
}
__device__ __forceinline__ void split2(float x, float y, uint32_t& hi, uint32_t& lo) {
    __nv_bfloat16 xh, xl, yh, yl;
    split1(x, xh, xl); split1(y, yh, yl);
    hi = (uint32_t)__bfloat16_as_ushort(xh) | ((uint32_t)__bfloat16_as_ushort(yh) << 16);
    lo = (uint32_t)__bfloat16_as_ushort(xl) | ((uint32_t)__bfloat16_as_ushort(yl) << 16);
}

// -------- merged prepass: split 7 tensors in ONE launch --------
struct SplitArgs {
    const float* in[7];
    __nv_bfloat16* h[7];
    __nv_bfloat16* l[7];
    int nblk[7];
};

__global__ __launch_bounds__(256) void split_all_kernel(SplitArgs A)
{
    int b = blockIdx.x;
    int seg = 0;
#pragma unroll
    for (int s = 0; s < 7; s++) {
        if (b < A.nblk[s]) { seg = s; break; }
        b -= A.nblk[s];
    }
    const int i = b * 256 + threadIdx.x;
    float4 v = ((const float4*)A.in[seg])[i];
    uint32_t h01, l01, h23, l23;
    split2(v.x, v.y, h01, l01);
    split2(v.z, v.w, h23, l23);
    ((uint2*)A.h[seg])[i] = make_uint2(h01, h23);
    ((uint2*)A.l[seg])[i] = make_uint2(l01, l23);
}

// ===== bf16x3 mma.sync GEMM: BK=32, 3 stages, XOR-swizzled smem, 2 CTAs/SM =====
// Supports per-z (blockIdx.z) A/B/C pointers, so z can be a fused-output index
// (QKV) or a split-K slice index (AO, FF2).
#define BM 128
#define BN 128
#define BK2 32

#define PLANE 4096
#define STG_ELEMS (4*PLANE)
#define GEMM_SMEM (3*STG_ELEMS*2)

#define ASOFFZ(s,pl,m,c)  ((s)*STG_ELEMS + (pl)*PLANE + (m)*32  + ((((c) ^ (((m)>>1)&3)))<<3))
#define BSOFFZ(s,pl,kk,c) ((s)*STG_ELEMS + 2*PLANE + (pl)*PLANE + (kk)*128 + ((((c) ^ ((kk)&7)))<<3))

struct GemmArgs {
    const __nv_bfloat16 *Ah[3], *Al[3];
    const __nv_bfloat16 *Bh[3], *Bl[3];
    const float* bias[3];
    float* C[3];
    __nv_bfloat16 *Ch, *Cl;
};

__device__ __forceinline__ void cpa16(void* dst, const void* src) {
    uint32_t d = (uint32_t)__cvta_generic_to_shared(dst);
    asm volatile("cp.async.cg.shared.global [%0], [%1], 16;" :: "r"(d), "l"(src));
}
__device__ __forceinline__ void ldsm4(uint32_t* r, const void* p) {
    uint32_t a = (uint32_t)__cvta_generic_to_shared(p);
    asm volatile("ldmatrix.sync.aligned.m8n8.x4.shared.b16 {%0,%1,%2,%3}, [%4];"
                 : "=r"(r[0]), "=r"(r[1]), "=r"(r[2]), "=r"(r[3]) : "r"(a));
}
__device__ __forceinline__ void ldsm4t(uint32_t* r, const void* p) {
    uint32_t a = (uint32_t)__cvta_generic_to_shared(p);
    asm volatile("ldmatrix.sync.aligned.m8n8.x4.trans.shared.b16 {%0,%1,%2,%3}, [%4];"
                 : "=r"(r[0]), "=r"(r[1]), "=r"(r[2]), "=r"(r[3]) : "r"(a));
}
__device__ __forceinline__ void mma16816(float* c, const uint32_t* a, const uint32_t* b) {
    asm volatile(
        "mma.sync.aligned.m16n8k16.row.col.f32.bf16.bf16.f32 "
        "{%0,%1,%2,%3}, {%4,%5,%6,%7}, {%8,%9}, {%0,%1,%2,%3};"
        : "+f"(c[0]), "+f"(c[1]), "+f"(c[2]), "+f"(c[3])
        : "r"(a[0]), "r"(a[1]), "r"(a[2]), "r"(a[3]), "r"(b[0]), "r"(b[1]));
}

// MODE 0: fp32 out + bias (QKV). MODE 1: bias + exact GELU, split bf16 out (FF1).
// MODE 2: fp32 partial out, NO bias (split-K slices; bias folded into LN).
template<int MODE>
__global__ __launch_bounds__(256, 2) void gemm_bf16x3(GemmArgs P, int K_ld, int K_len, int N)
{
    extern __shared__ __align__(16) __nv_bfloat16 sm[];

    const int z = blockIdx.z;
    const __nv_bfloat16* __restrict__ Ah = P.Ah[z];
    const __nv_bfloat16* __restrict__ Al = P.Al[z];
    const __nv_bfloat16* __restrict__ Bh = P.Bh[z];
    const __nv_bfloat16* __restrict__ Bl = P.Bl[z];

    const int n0 = blockIdx.x * BN;
    const int m0 = blockIdx.y * BM;
    const int tid  = threadIdx.x;
    const int lane = tid & 31;
    const int warp = tid >> 5;
    const int warpM = warp >> 2;
    const int warpN = warp & 3;

    const int nT = K_len / BK2;

    auto issue = [&](int t, int s) {
        const int k0 = t * BK2;
#pragma unroll
        for (int p = 0; p < 2; p++) {
            const int idx = tid + p * 256;
            const int ar = idx >> 2, acc_ = idx & 3;
            cpa16(sm + ASOFFZ(s, 0, ar, acc_), Ah + (size_t)(m0 + ar) * K_ld + k0 + acc_ * 8);
            cpa16(sm + ASOFFZ(s, 1, ar, acc_), Al + (size_t)(m0 + ar) * K_ld + k0 + acc_ * 8);
            const int br = idx >> 4, bcc = idx & 15;
            cpa16(sm + BSOFFZ(s, 0, br, bcc), Bh + (size_t)(k0 + br) * N + n0 + bcc * 8);
            cpa16(sm + BSOFFZ(s, 1, br, bcc), Bl + (size_t)(k0 + br) * N + n0 + bcc * 8);
        }
        asm volatile("cp.async.commit_group;" ::: "memory");
    };

    issue(0, 0);
    issue(1, 1);

    float acc[4][4][4] = {};
    int s = 0;

    for (int t = 0; t < nT; t++) {
        if (t + 1 < nT) asm volatile("cp.async.wait_group 1;" ::: "memory");
        else            asm volatile("cp.async.wait_group 0;" ::: "memory");
        __syncthreads();

        if (t + 2 < nT) {
            int s2 = s + 2; if (s2 >= 3) s2 -= 3;
            issue(t + 2, s2);
        }

#pragma unroll
        for (int sub = 0; sub < 2; sub++) {
            uint32_t ah[4][4], al[4][4], bh[4][2], bl[4][2];
            const int cA = sub * 2 + (lane >> 4);
#pragma unroll
            for (int mi = 0; mi < 4; mi++) {
                const int arow = warpM * 64 + mi * 16 + (lane & 15);
                ldsm4(ah[mi], sm + ASOFFZ(s, 0, arow, cA));
                ldsm4(al[mi], sm + ASOFFZ(s, 1, arow, cA));
            }
            const int brow = sub * 16 + (lane & 15);
#pragma unroll
            for (int pr = 0; pr < 2; pr++) {
                const int cB = warpN * 4 + pr * 2 + (lane >> 4);
                uint32_t tmp[4];
                ldsm4t(tmp, sm + BSOFFZ(s, 0, brow, cB));
                bh[pr * 2][0] = tmp[0]; bh[pr * 2][1] = tmp[1];
                bh[pr * 2 + 1][0] = tmp[2]; bh[pr * 2 + 1][1] = tmp[3];
                ldsm4t(tmp, sm + BSOFFZ(s, 1, brow, cB));
                bl[pr * 2][0] = tmp[0]; bl[pr * 2][1] = tmp[1];
                bl[pr * 2 + 1][0] = tmp[2]; bl[pr * 2 + 1][1] = tmp[3];
            }
#pragma unroll
            for (int mi = 0; mi < 4; mi++)
#pragma unroll
                for (int ni = 0; ni < 4; ni++)
                    mma16816(acc[mi][ni], ah[mi], bh[ni]);
#pragma unroll
            for (int mi = 0; mi < 4; mi++)
#pragma unroll
                for (int ni = 0; ni < 4; ni++)
                    mma16816(acc[mi][ni], ah[mi], bl[ni]);
#pragma unroll
            for (int mi = 0; mi < 4; mi++)
#pragma unroll
                for (int ni = 0; ni < 4; ni++)
                    mma16816(acc[mi][ni], al[mi], bh[ni]);
        }
        if (++s == 3) s = 0;
    }

    const float* __restrict__ bias = P.bias[z];
    const int g  = lane >> 2;
    const int tg = lane & 3;
#pragma unroll
    for (int mi = 0; mi < 4; mi++) {
#pragma unroll
        for (int ni = 0; ni < 4; ni++) {
            const int row = m0 + warpM * 64 + mi * 16 + g;
            const int col = n0 + warpN * 32 + ni * 8 + tg * 2;
            float v0 = acc[mi][ni][0];
            float v1 = acc[mi][ni][1];
            float v2 = acc[mi][ni][2];
            float v3 = acc[mi][ni][3];
            if (MODE != 2) {
                const float b0 = bias[col], b1 = bias[col + 1];
                v0 += b0; v1 += b1; v2 += b0; v3 += b1;
            }
            if (MODE == 1) {
                v0 = 0.5f * v0 * (1.0f + erff(v0 * 0.70710678118654752f));
                v1 = 0.5f * v1 * (1.0f + erff(v1 * 0.70710678118654752f));
                v2 = 0.5f * v2 * (1.0f + erff(v2 * 0.70710678118654752f));
                v3 = 0.5f * v3 * (1.0f + erff(v3 * 0.70710678118654752f));
                uint32_t hw, lw;
                split2(v0, v1, hw, lw);
                *(uint32_t*)(P.Ch + (size_t)row * N + col) = hw;
                *(uint32_t*)(P.Cl + (size_t)row * N + col) = lw;
                split2(v2, v3, hw, lw);
                *(uint32_t*)(P.Ch + (size_t)(row + 8) * N + col) = hw;
                *(uint32_t*)(P.Cl + (size_t)(row + 8) * N + col) = lw;
            } else {
                float* C = P.C[z];
                *(float2*)(C + (size_t)row * N + col)       = make_float2(v0, v1);
                *(float2*)(C + (size_t)(row + 8) * N + col) = make_float2(v2, v3);
            }
        }
    }
}

// ---------------- fused attention (flash-style, fp32, LDS.128 everywhere) ----------------
#define SMP 68
__global__ __launch_bounds__(256) void attention_kernel(
    const float* __restrict__ q, const float* __restrict__ k,
    const float* __restrict__ v, const float* __restrict__ mask,
    __nv_bfloat16* __restrict__ ctx_h, __nv_bfloat16* __restrict__ ctx_l)
{
    extern __shared__ float smf[];
    float* Qs  = smf;
    float* Ks  = Qs + 64 * SMP;
    float* VsT = Ks + 64 * SMP;
    float* Ps  = VsT + 64 * SMP;
    float* rm = Ps + 64 * SMP;
    float* rl = rm + 64;
    float* rs = rl + 64;
    float* am = rs + 64;

    const int tx = threadIdx.x, ty = threadIdx.y;
    const int tid = ty * 16 + tx;
    const int bh = blockIdx.y;
    const int b = bh / NHz, h = bh % NHz;
    const int i0 = blockIdx.x * 64;
    const float scale = 0.125f;

#pragma unroll
    for (int it = 0; it < 4; it++) {
        int idx = tid + it * 256;
        int row = idx >> 4;
        int d4 = (idx & 15) * 4;
        float4 t = *(const float4*)(q + (size_t)(b * Tz + i0 + row) * Hz + h * HDz + d4);
        *(float4*)&Qs[row * SMP + d4] = t;
    }
    if (tid < 64) { rm[tid] = -1e30f; rl[tid] = 0.0f; }

    float acc[4][4] = {};

    for (int jc = 0; jc < Tz / 64; jc++) {
        const int j0 = jc * 64;
#pragma unroll
        for (int it = 0; it < 4; it++) {
            int idx = tid + it * 256;
            int row = idx >> 4;
            int d4 = (idx & 15) * 4;
            float4 t = *(const float4*)(k + (size_t)(b * Tz + j0 + row) * Hz + h * HDz + d4);
            *(float4*)&Ks[row * SMP + d4] = t;
            float4 tv = *(const float4*)(v + (size_t)(b * Tz + j0 + row) * Hz + h * HDz + d4);
            VsT[(d4 + 0) * SMP + row] = tv.x;
            VsT[(d4 + 1) * SMP + row] = tv.y;
            VsT[(d4 + 2) * SMP + row] = tv.z;
            VsT[(d4 + 3) * SMP + row] = tv.w;
        }
        if (tid < 64) am[tid] = (1.0f - mask[b * Tz + j0 + tid]) * -10000.0f;
        __syncthreads();

        float s[4][4] = {};
#pragma unroll
        for (int d4 = 0; d4 < 64; d4 += 4) {
            float4 qv[4], kv[4];
#pragma unroll
            for (int i = 0; i < 4; i++) qv[i] = *(float4*)&Qs[(ty + 16 * i) * SMP + d4];
#pragma unroll
            for (int j = 0; j < 4; j++) kv[j] = *(float4*)&Ks[(tx + 16 * j) * SMP + d4];
#pragma unroll
            for (int i = 0; i < 4; i++)
#pragma unroll
                for (int j = 0; j < 4; j++) {
                    s[i][j] = fmaf(qv[i].x, kv[j].x, s[i][j]);
                    s[i][j] = fmaf(qv[i].y, kv[j].y, s[i][j]);
                    s[i][j] = fmaf(qv[i].z, kv[j].z, s[i][j]);
                    s[i][j] = fmaf(qv[i].w, kv[j].w, s[i][j]);
                }
        }
#pragma unroll
        for (int i = 0; i < 4; i++)
#pragma unroll
            for (int j = 0; j < 4; j++)
                Ps[(ty + 16 * i) * SMP + tx + 16 * j] = s[i][j] * scale + am[tx + 16 * j];
        __syncthreads();

        {
            const int srow = tid >> 2;
            const int ssub = tid & 3;
            float* prow = Ps + srow * SMP + ssub * 16;
            const float mo = rm[srow];
            float4 pv[4];
            float cm = -1e30f;
#pragma unroll
            for (int c = 0; c < 4; c++) {
                pv[c] = *(float4*)&prow[c * 4];
                cm = fmaxf(cm, fmaxf(fmaxf(pv[c].x, pv[c].y), fmaxf(pv[c].z, pv[c].w)));
            }
            cm = fmaxf(cm, __shfl_xor_sync(0xffffffffu, cm, 1));
            cm = fmaxf(cm, __shfl_xor_sync(0xffffffffu, cm, 2));
            const float nm = fmaxf(mo, cm);
            float sum = 0.0f;
#pragma unroll
            for (int c = 0; c < 4; c++) {
                pv[c].x = __expf(pv[c].x - nm);
                pv[c].y = __expf(pv[c].y - nm);
                pv[c].z = __expf(pv[c].z - nm);
                pv[c].w = __expf(pv[c].w - nm);
                sum += pv[c].x + pv[c].y + pv[c].z + pv[c].w;
                *(float4*)&prow[c * 4] = pv[c];
            }
            sum += __shfl_xor_sync(0xffffffffu, sum, 1);
            sum += __shfl_xor_sync(0xffffffffu, sum, 2);
            if (ssub == 0) {
                const float sc = __expf(mo - nm);
                rl[srow] = rl[srow] * sc + sum;
                rm[srow] = nm;
                rs[srow] = sc;
            }
        }
        __syncthreads();

#pragma unroll
        for (int i = 0; i < 4; i++) {
            const float sc = rs[ty + 16 * i];
#pragma unroll
            for (int j = 0; j < 4; j++) acc[i][j] *= sc;
        }
#pragma unroll
        for (int jj4 = 0; jj4 < 64; jj4 += 4) {
            float4 pv[4], vv[4];
#pragma unroll
            for (int i = 0; i < 4; i++) pv[i] = *(float4*)&Ps[(ty + 16 * i) * SMP + jj4];
#pragma unroll
            for (int j = 0; j < 4; j++) vv[j] = *(float4*)&VsT[(tx + 16 * j) * SMP + jj4];
#pragma unroll
            for (int i = 0; i < 4; i++)
#pragma unroll
                for (int j = 0; j < 4; j++) {
                    acc[i][j] = fmaf(pv[i].x, vv[j].x, acc[i][j]);
                    acc[i][j] = fmaf(pv[i].y, vv[j].y, acc[i][j]);
                    acc[i][j] = fmaf(pv[i].z, vv[j].z, acc[i][j]);
                    acc[i][j] = fmaf(pv[i].w, vv[j].w, acc[i][j]);
                }
        }
        __syncthreads();
    }

#pragma unroll
    for (int i = 0; i < 4; i++) {
        const float inv = 1.0f / rl[ty + 16 * i];
#pragma unroll
        for (int j = 0; j < 4; j++) {
            size_t off = (size_t)(b * Tz + i0 + ty + 16 * i) * Hz + h * HDz + tx + 16 * j;
            float val = acc[i][j] * inv;
            __nv_bfloat16 hv, lv;
            split1(val, hv, lv);
            ctx_h[off] = hv;
            ctx_l[off] = lv;
        }
    }
}

// ---------------- residual + LayerNorm over two split-K partials + gemm bias ----------------
__device__ __forceinline__ float block_reduce_sum(float val, float* red) {
    const int lane = threadIdx.x & 31, w = threadIdx.x >> 5;
#pragma unroll
    for (int o = 16; o > 0; o >>= 1) val += __shfl_down_sync(0xffffffffu, val, o);
    if (lane == 0) red[w] = val;
    __syncthreads();
    if (w == 0) {
        float t = (lane < 8) ? red[lane] : 0.0f;
#pragma unroll
        for (int o = 4; o > 0; o >>= 1) t += __shfl_down_sync(0xffffffffu, t, o);
        if (lane == 0) red[0] = t;
    }
    __syncthreads();
    float r = red[0];
    __syncthreads();
    return r;
}

__global__ __launch_bounds__(256) void ln_kernel(
    const float* __restrict__ a, const float* __restrict__ a2,
    const float* __restrict__ gb, const float* __restrict__ res,
    const float* __restrict__ g, const float* __restrict__ bb,
    float* __restrict__ out,
    __nv_bfloat16* __restrict__ oh, __nv_bfloat16* __restrict__ ol)
{
    __shared__ float buf[Hz];
    __shared__ float red[32];
    const int row = blockIdx.x;
    const float* ap  = a  + (size_t)row * Hz;
    const float* ap2 = a2 + (size_t)row * Hz;
    const float* rp  = res + (size_t)row * Hz;

    float ls = 0.0f;
    for (int i = threadIdx.x; i < Hz; i += 256) {
        float vv = ap[i] + ap2[i] + gb[i] + rp[i];
        buf[i] = vv;
        ls += vv;
    }
    const float mean = block_reduce_sum(ls, red) * (1.0f / Hz);

    float lq = 0.0f;
    for (int i = threadIdx.x; i < Hz; i += 256) {
        float d = buf[i] - mean;
        lq += d * d;
    }
    const float var = block_reduce_sum(lq, red) * (1.0f / Hz);
    const float rstd = rsqrtf(var + 1e-12f);

    for (int i = threadIdx.x; i < Hz; i += 256) {
        float y = (buf[i] - mean) * rstd * g[i] + bb[i];
        out[(size_t)row * Hz + i] = y;
        __nv_bfloat16 hv, lv;
        split1(y, hv, lv);
        oh[(size_t)row * Hz + i] = hv;
        ol[(size_t)row * Hz + i] = lv;
    }
}

// ---------------- launch ----------------
extern "C" void kernel_launch(void* const* d_in, const int* in_sizes, int n_in,
                              void* d_out, int out_size)
{
    const float* hidden = (const float*)d_in[0];
    const float* mask   = (const float*)d_in[1];
    const float* Wq  = (const float*)d_in[2];   const float* bq  = (const float*)d_in[3];
    const float* Wk  = (const float*)d_in[4];   const float* bk  = (const float*)d_in[5];
    const float* Wv  = (const float*)d_in[6];   const float* bv  = (const float*)d_in[7];
    const float* Wao = (const float*)d_in[8];   const float* bao = (const float*)d_in[9];
    const float* g1  = (const float*)d_in[10];  const float* b1  = (const float*)d_in[11];
    const float* Wi  = (const float*)d_in[12];  const float* bi  = (const float*)d_in[13];
    const float* Wo  = (const float*)d_in[14];  const float* bo  = (const float*)d_in[15];
    const float* g2  = (const float*)d_in[16];  const float* b2  = (const float*)d_in[17];
    float* out = (float*)d_out;

    float *q, *k, *v, *proj, *proj2, *attn, *xb;
    cudaGetSymbolAddress((void**)&q,     g_q);
    cudaGetSymbolAddress((void**)&k,     g_k);
    cudaGetSymbolAddress((void**)&v,     g_v);
    cudaGetSymbolAddress((void**)&proj,  g_proj);
    cudaGetSymbolAddress((void**)&proj2, g_proj2);
    cudaGetSymbolAddress((void**)&attn,  g_attn);
    cudaGetSymbolAddress((void**)&xb,    g_x);

    __nv_bfloat16 *xh, *xl, *ath, *atl, *cth, *ctl, *ffh, *ffl;
    cudaGetSymbolAddress((void**)&xh,  g_x_h);    cudaGetSymbolAddress((void**)&xl,  g_x_l);
    cudaGetSymbolAddress((void**)&ath, g_attn_h); cudaGetSymbolAddress((void**)&atl, g_attn_l);
    cudaGetSymbolAddress((void**)&cth, g_ctx_h);  cudaGetSymbolAddress((void**)&ctl, g_ctx_l);
    cudaGetSymbolAddress((void**)&ffh, g_ff_h);   cudaGetSymbolAddress((void**)&ffl, g_ff_l);

    __nv_bfloat16 *wqh, *wql, *wkh, *wkl, *wvh, *wvl, *waoh, *waol, *wih, *wil, *woh, *wol;
    cudaGetSymbolAddress((void**)&wqh,  g_wq_h);  cudaGetSymbolAddress((void**)&wql,  g_wq_l);
    cudaGetSymbolAddress((void**)&wkh,  g_wk_h);  cudaGetSymbolAddress((void**)&wkl,  g_wk_l);
    cudaGetSymbolAddress((void**)&wvh,  g_wv_h);  cudaGetSymbolAddress((void**)&wvl,  g_wv_l);
    cudaGetSymbolAddress((void**)&waoh, g_wao_h); cudaGetSymbolAddress((void**)&waol, g_wao_l);
    cudaGetSymbolAddress((void**)&wih,  g_wi_h);  cudaGetSymbolAddress((void**)&wil,  g_wi_l);
    cudaGetSymbolAddress((void**)&woh,  g_wo_h);  cudaGetSymbolAddress((void**)&wol,  g_wo_l);

    // merged prepass: ONE launch splits all weights + input
    {
        const int nHH = Lz * Hz * Hz, nHF = Lz * Hz * FFz, nX = Mz * Hz;
        SplitArgs A;
        A.in[0] = Wq;  A.h[0] = wqh;  A.l[0] = wql;  A.nblk[0] = nHH / 1024;
        A.in[1] = Wk;  A.h[1] = wkh;  A.l[1] = wkl;  A.nblk[1] = nHH / 1024;
        A.in[2] = Wv;  A.h[2] = wvh;  A.l[2] = wvl;  A.nblk[2] = nHH / 1024;
        A.in[3] = Wao; A.h[3] = waoh; A.l[3] = waol; A.nblk[3] = nHH / 1024;
        A.in[4] = Wi;  A.h[4] = wih;  A.l[4] = wil;  A.nblk[4] = nHF / 1024;
        A.in[5] = Wo;  A.h[5] = woh;  A.l[5] = wol;  A.nblk[5] = nHF / 1024;
        A.in[6] = hidden; A.h[6] = xh; A.l[6] = xl;  A.nblk[6] = nX / 1024;
        int total = 4 * (nHH / 1024) + 2 * (nHF / 1024) + nX / 1024;
        split_all_kernel<<<total, 256>>>(A);
    }

    const size_t att_smem = (size_t)(4 * 64 * SMP + 4 * 64) * sizeof(float);
    cudaFuncSetAttribute(attention_kernel,
                         cudaFuncAttributeMaxDynamicSharedMemorySize, (int)att_smem);
    cudaFuncSetAttribute(gemm_bf16x3<0>,
                         cudaFuncAttributeMaxDynamicSharedMemorySize, GEMM_SMEM);
    cudaFuncSetAttribute(gemm_bf16x3<1>,
                         cudaFuncAttributeMaxDynamicSharedMemorySize, GEMM_SMEM);
    cudaFuncSetAttribute(gemm_bf16x3<2>,
                         cudaFuncAttributeMaxDynamicSharedMemorySize, GEMM_SMEM);

    dim3 gAtt(Tz / 64, Bz * NHz);
    dim3 blkA(16, 16);

    for (int l = 0; l < Lz; l++) {
        const float* xres = (l == 0) ? hidden : xb;
        const size_t oHH = (size_t)l * Hz * Hz;
        const size_t oHF = (size_t)l * Hz * FFz;
        const size_t oH  = (size_t)l * Hz;
        const size_t oF  = (size_t)l * FFz;

        {   // fused QKV (z = output index)
            GemmArgs P = {};
            P.Ah[0] = P.Ah[1] = P.Ah[2] = xh;
            P.Al[0] = P.Al[1] = P.Al[2] = xl;
            P.Bh[0] = wqh + oHH; P.Bl[0] = wql + oHH;
            P.Bh[1] = wkh + oHH; P.Bl[1] = wkl + oHH;
            P.Bh[2] = wvh + oHH; P.Bl[2] = wvl + oHH;
            P.bias[0] = bq + oH; P.bias[1] = bk + oH; P.bias[2] = bv + oH;
            P.C[0] = q; P.C[1] = k; P.C[2] = v;
            gemm_bf16x3<0><<<dim3(Hz / BN, Mz / BM, 3), 256, GEMM_SMEM>>>(P, Hz, Hz, Hz);
        }

        attention_kernel<<<gAtt, blkA, att_smem>>>(q, k, v, mask, cth, ctl);

        {   // attention output projection: split-K x2 (z = slice index)
            GemmArgs P = {};
            P.Ah[0] = cth;       P.Al[0] = ctl;
            P.Ah[1] = cth + 384; P.Al[1] = ctl + 384;
            P.Bh[0] = waoh + oHH;            P.Bl[0] = waol + oHH;
            P.Bh[1] = waoh + oHH + 384 * Hz; P.Bl[1] = waol + oHH + 384 * Hz;
            P.C[0] = proj; P.C[1] = proj2;
            gemm_bf16x3<2><<<dim3(Hz / BN, Mz / BM, 2), 256, GEMM_SMEM>>>(P, Hz, 384, Hz);
        }
        ln_kernel<<<Mz, 256>>>(proj, proj2, bao + oH, xres, g1 + oH, b1 + oH, attn, ath, atl);

        {   // FF1 + GELU (split bf16 out)
            GemmArgs P = {};
            P.Ah[0] = ath; P.Al[0] = atl;
            P.Bh[0] = wih + oHF; P.Bl[0] = wil + oHF;
            P.bias[0] = bi + oF;
            P.Ch = ffh; P.Cl = ffl;
            gemm_bf16x3<1><<<dim3(FFz / BN, Mz / BM, 1), 256, GEMM_SMEM>>>(P, Hz, Hz, FFz);
        }
        {   // FF2: split-K x2 (z = slice index), K 3072 -> 2x1536
            GemmArgs P = {};
            P.Ah[0] = ffh;        P.Al[0] = ffl;
            P.Ah[1] = ffh + 1536; P.Al[1] = ffl + 1536;
            P.Bh[0] = woh + oHF;             P.Bl[0] = wol + oHF;
            P.Bh[1] = woh + oHF + 1536 * Hz; P.Bl[1] = wol + oHF + 1536 * Hz;
            P.C[0] = proj; P.C[1] = proj2;
            gemm_bf16x3<2><<<dim3(Hz / BN, Mz / BM, 2), 256, GEMM_SMEM>>>(P, FFz, 1536, Hz);
        }
        ln_kernel<<<Mz, 256>>>(proj, proj2, bo + oH, attn, g2 + oH, b2 + oH,
                               (l == Lz - 1) ? out : xb, xh, xl);
    }
}

// round 11
// speedup vs baseline: 1.1105x; 1.0035x over previous
#include <cuda_runtime.h>
#include <cuda_bf16.h>
#include <math.h>
#include <stdint.h>

#define Bz  8
#define Tz  512
#define Hz  768
#define NHz 12
#define HDz 64
#define FFz 3072
#define Lz  12
#define Mz  (Bz*Tz)   // 4096

// ---------------- fp32 scratch ----------------
__device__ float g_q[Mz*Hz];
__device__ float g_k[Mz*Hz];
__device__ float g_v[Mz*Hz];
__device__ float g_p0[Mz*Hz];
__device__ float g_p1[Mz*Hz];
__device__ float g_p2[Mz*Hz];
__device__ float g_p3[Mz*Hz];
__device__ float g_attn[Mz*Hz];
__device__ float g_x[Mz*Hz];

// ---------------- split (hi/lo bf16) activation scratch ----------------
__device__ __nv_bfloat16 g_x_h[Mz*Hz],    g_x_l[Mz*Hz];
__device__ __nv_bfloat16 g_attn_h[Mz*Hz], g_attn_l[Mz*Hz];
__device__ __nv_bfloat16 g_ctx_h[Mz*Hz],  g_ctx_l[Mz*Hz];
__device__ __nv_bfloat16 g_ff_h[Mz*FFz],  g_ff_l[Mz*FFz];

// ---------------- split weight storage ([L][K][N], hi/lo) ----------------
__device__ __nv_bfloat16 g_wq_h[Lz*Hz*Hz],  g_wq_l[Lz*Hz*Hz];
__device__ __nv_bfloat16 g_wk_h[Lz*Hz*Hz],  g_wk_l[Lz*Hz*Hz];
__device__ __nv_bfloat16 g_wv_h[Lz*Hz*Hz],  g_wv_l[Lz*Hz*Hz];
__device__ __nv_bfloat16 g_wao_h[Lz*Hz*Hz], g_wao_l[Lz*Hz*Hz];
__device__ __nv_bfloat16 g_wi_h[Lz*Hz*FFz], g_wi_l[Lz*Hz*FFz];
__device__ __nv_bfloat16 g_wo_h[Lz*Hz*FFz], g_wo_l[Lz*Hz*FFz];

// ---------------- helpers ----------------
__device__ __forceinline__ void split1(float x, __nv_bfloat16& h, __nv_bfloat16& l) {
    h = __float2bfloat16(x);
    l = __float2bfloat16(x - __bfloat162float(h));
}
__device__ __forceinline__ void split2(float x, float y, uint32_t& hi, uint32_t& lo) {
    __nv_bfloat16 xh, xl, yh, yl;
    split1(x, xh, xl); split1(y, yh, yl);
    hi = (uint32_t)__bfloat16_as_ushort(xh) | ((uint32_t)__bfloat16_as_ushort(yh) << 16);
    lo = (uint32_t)__bfloat16_as_ushort(xl) | ((uint32_t)__bfloat16_as_ushort(yl) << 16);
}

// -------- merged prepass: split 7 tensors in ONE launch --------
struct SplitArgs {
    const float* in[7];
    __nv_bfloat16* h[7];
    __nv_bfloat16* l[7];
    int nblk[7];
};

__global__ __launch_bounds__(256) void split_all_kernel(SplitArgs A)
{
    int b = blockIdx.x;
    int seg = 0;
#pragma unroll
    for (int s = 0; s < 7; s++) {
        if (b < A.nblk[s]) { seg = s; break; }
        b -= A.nblk[s];
    }
    const int i = b * 256 + threadIdx.x;
    float4 v = ((const float4*)A.in[seg])[i];
    uint32_t h01, l01, h23, l23;
    split2(v.x, v.y, h01, l01);
    split2(v.z, v.w, h23, l23);
    ((uint2*)A.h[seg])[i] = make_uint2(h01, h23);
    ((uint2*)A.l[seg])[i] = make_uint2(l01, l23);
}

// ===== bf16x3 mma.sync GEMM: BK=32, 3 stages, XOR-swizzled smem, 2 CTAs/SM =====
#define BM 128
#define BN 128
#define BK2 32

#define PLANE 4096
#define STG_ELEMS (4*PLANE)
#define GEMM_SMEM (3*STG_ELEMS*2)

#define ASOFFZ(s,pl,m,c)  ((s)*STG_ELEMS + (pl)*PLANE + (m)*32  + ((((c) ^ (((m)>>1)&3)))<<3))
#define BSOFFZ(s,pl,kk,c) ((s)*STG_ELEMS + 2*PLANE + (pl)*PLANE + (kk)*128 + ((((c) ^ ((kk)&7)))<<3))

struct GemmArgs {
    const __nv_bfloat16 *Ah[4], *Al[4];
    const __nv_bfloat16 *Bh[4], *Bl[4];
    const float* bias[4];
    float* C[4];
    __nv_bfloat16 *Ch, *Cl;
};

__device__ __forceinline__ void cpa16(void* dst, const void* src) {
    uint32_t d = (uint32_t)__cvta_generic_to_shared(dst);
    asm volatile("cp.async.cg.shared.global [%0], [%1], 16;" :: "r"(d), "l"(src));
}
__device__ __forceinline__ void ldsm4(uint32_t* r, const void* p) {
    uint32_t a = (uint32_t)__cvta_generic_to_shared(p);
    asm volatile("ldmatrix.sync.aligned.m8n8.x4.shared.b16 {%0,%1,%2,%3}, [%4];"
                 : "=r"(r[0]), "=r"(r[1]), "=r"(r[2]), "=r"(r[3]) : "r"(a));
}
__device__ __forceinline__ void ldsm4t(uint32_t* r, const void* p) {
    uint32_t a = (uint32_t)__cvta_generic_to_shared(p);
    asm volatile("ldmatrix.sync.aligned.m8n8.x4.trans.shared.b16 {%0,%1,%2,%3}, [%4];"
                 : "=r"(r[0]), "=r"(r[1]), "=r"(r[2]), "=r"(r[3]) : "r"(a));
}
__device__ __forceinline__ void mma16816(float* c, const uint32_t* a, const uint32_t* b) {
    asm volatile(
        "mma.sync.aligned.m16n8k16.row.col.f32.bf16.bf16.f32 "
        "{%0,%1,%2,%3}, {%4,%5,%6,%7}, {%8,%9}, {%0,%1,%2,%3};"
        : "+f"(c[0]), "+f"(c[1]), "+f"(c[2]), "+f"(c[3])
        : "r"(a[0]), "r"(a[1]), "r"(a[2]), "r"(a[3]), "r"(b[0]), "r"(b[1]));
}

// MODE 0: fp32 out + bias (QKV). MODE 1: bias + exact GELU, split bf16 out (FF1).
// MODE 2: fp32 partial out, NO bias (split-K slices; bias folded into LN).
template<int MODE>
__global__ __launch_bounds__(256, 2) void gemm_bf16x3(GemmArgs P, int K_ld, int K_len, int N)
{
    extern __shared__ __align__(16) __nv_bfloat16 sm[];

    const int z = blockIdx.z;
    const __nv_bfloat16* __restrict__ Ah = P.Ah[z];
    const __nv_bfloat16* __restrict__ Al = P.Al[z];
    const __nv_bfloat16* __restrict__ Bh = P.Bh[z];
    const __nv_bfloat16* __restrict__ Bl = P.Bl[z];

    const int n0 = blockIdx.x * BN;
    const int m0 = blockIdx.y * BM;
    const int tid  = threadIdx.x;
    const int lane = tid & 31;
    const int warp = tid >> 5;
    const int warpM = warp >> 2;
    const int warpN = warp & 3;

    const int nT = K_len / BK2;

    auto issue = [&](int t, int s) {
        const int k0 = t * BK2;
#pragma unroll
        for (int p = 0; p < 2; p++) {
            const int idx = tid + p * 256;
            const int ar = idx >> 2, acc_ = idx & 3;
            cpa16(sm + ASOFFZ(s, 0, ar, acc_), Ah + (size_t)(m0 + ar) * K_ld + k0 + acc_ * 8);
            cpa16(sm + ASOFFZ(s, 1, ar, acc_), Al + (size_t)(m0 + ar) * K_ld + k0 + acc_ * 8);
            const int br = idx >> 4, bcc = idx & 15;
            cpa16(sm + BSOFFZ(s, 0, br, bcc), Bh + (size_t)(k0 + br) * N + n0 + bcc * 8);
            cpa16(sm + BSOFFZ(s, 1, br, bcc), Bl + (size_t)(k0 + br) * N + n0 + bcc * 8);
        }
        asm volatile("cp.async.commit_group;" ::: "memory");
    };

    issue(0, 0);
    issue(1, 1);

    float acc[4][4][4] = {};
    int s = 0;

    for (int t = 0; t < nT; t++) {
        if (t + 1 < nT) asm volatile("cp.async.wait_group 1;" ::: "memory");
        else            asm volatile("cp.async.wait_group 0;" ::: "memory");
        __syncthreads();

        if (t + 2 < nT) {
            int s2 = s + 2; if (s2 >= 3) s2 -= 3;
            issue(t + 2, s2);
        }

#pragma unroll
        for (int sub = 0; sub < 2; sub++) {
            uint32_t ah[4][4], al[4][4], bh[4][2], bl[4][2];
            const int cA = sub * 2 + (lane >> 4);
#pragma unroll
            for (int mi = 0; mi < 4; mi++) {
                const int arow = warpM * 64 + mi * 16 + (lane & 15);
                ldsm4(ah[mi], sm + ASOFFZ(s, 0, arow, cA));
                ldsm4(al[mi], sm + ASOFFZ(s, 1, arow, cA));
            }
            const int brow = sub * 16 + (lane & 15);
#pragma unroll
            for (int pr = 0; pr < 2; pr++) {
                const int cB = warpN * 4 + pr * 2 + (lane >> 4);
                uint32_t tmp[4];
                ldsm4t(tmp, sm + BSOFFZ(s, 0, brow, cB));
                bh[pr * 2][0] = tmp[0]; bh[pr * 2][1] = tmp[1];
                bh[pr * 2 + 1][0] = tmp[2]; bh[pr * 2 + 1][1] = tmp[3];
                ldsm4t(tmp, sm + BSOFFZ(s, 1, brow, cB));
                bl[pr * 2][0] = tmp[0]; bl[pr * 2][1] = tmp[1];
                bl[pr * 2 + 1][0] = tmp[2]; bl[pr * 2 + 1][1] = tmp[3];
            }
#pragma unroll
            for (int mi = 0; mi < 4; mi++)
#pragma unroll
                for (int ni = 0; ni < 4; ni++)
                    mma16816(acc[mi][ni], ah[mi], bh[ni]);
#pragma unroll
            for (int mi = 0; mi < 4; mi++)
#pragma unroll
                for (int ni = 0; ni < 4; ni++)
                    mma16816(acc[mi][ni], ah[mi], bl[ni]);
#pragma unroll
            for (int mi = 0; mi < 4; mi++)
#pragma unroll
                for (int ni = 0; ni < 4; ni++)
                    mma16816(acc[mi][ni], al[mi], bh[ni]);
        }
        if (++s == 3) s = 0;
    }

    const float* __restrict__ bias = P.bias[z];
    const int g  = lane >> 2;
    const int tg = lane & 3;
#pragma unroll
    for (int mi = 0; mi < 4; mi++) {
#pragma unroll
        for (int ni = 0; ni < 4; ni++) {
            const int row = m0 + warpM * 64 + mi * 16 + g;
            const int col = n0 + warpN * 32 + ni * 8 + tg * 2;
            float v0 = acc[mi][ni][0];
            float v1 = acc[mi][ni][1];
            float v2 = acc[mi][ni][2];
            float v3 = acc[mi][ni][3];
            if (MODE != 2) {
                const float b0 = bias[col], b1 = bias[col + 1];
                v0 += b0; v1 += b1; v2 += b0; v3 += b1;
            }
            if (MODE == 1) {
                v0 = 0.5f * v0 * (1.0f + erff(v0 * 0.70710678118654752f));
                v1 = 0.5f * v1 * (1.0f + erff(v1 * 0.70710678118654752f));
                v2 = 0.5f * v2 * (1.0f + erff(v2 * 0.70710678118654752f));
                v3 = 0.5f * v3 * (1.0f + erff(v3 * 0.70710678118654752f));
                uint32_t hw, lw;
                split2(v0, v1, hw, lw);
                *(uint32_t*)(P.Ch + (size_t)row * N + col) = hw;
                *(uint32_t*)(P.Cl + (size_t)row * N + col) = lw;
                split2(v2, v3, hw, lw);
                *(uint32_t*)(P.Ch + (size_t)(row + 8) * N + col) = hw;
                *(uint32_t*)(P.Cl + (size_t)(row + 8) * N + col) = lw;
            } else {
                float* C = P.C[z];
                *(float2*)(C + (size_t)row * N + col)       = make_float2(v0, v1);
                *(float2*)(C + (size_t)(row + 8) * N + col) = make_float2(v2, v3);
            }
        }
    }
}

// ---------------- fused attention (flash-style, fp32, LDS.128 everywhere) ----------------
#define SMP 68
__global__ __launch_bounds__(256) void attention_kernel(
    const float* __restrict__ q, const float* __restrict__ k,
    const float* __restrict__ v, const float* __restrict__ mask,
    __nv_bfloat16* __restrict__ ctx_h, __nv_bfloat16* __restrict__ ctx_l)
{
    extern __shared__ float smf[];
    float* Qs  = smf;
    float* Ks  = Qs + 64 * SMP;
    float* VsT = Ks + 64 * SMP;
    float* Ps  = VsT + 64 * SMP;
    float* rm = Ps + 64 * SMP;
    float* rl = rm + 64;
    float* rs = rl + 64;
    float* am = rs + 64;

    const int tx = threadIdx.x, ty = threadIdx.y;
    const int tid = ty * 16 + tx;
    const int bh = blockIdx.y;
    const int b = bh / NHz, h = bh % NHz;
    const int i0 = blockIdx.x * 64;
    const float scale = 0.125f;

#pragma unroll
    for (int it = 0; it < 4; it++) {
        int idx = tid + it * 256;
        int row = idx >> 4;
        int d4 = (idx & 15) * 4;
        float4 t = *(const float4*)(q + (size_t)(b * Tz + i0 + row) * Hz + h * HDz + d4);
        *(float4*)&Qs[row * SMP + d4] = t;
    }
    if (tid < 64) { rm[tid] = -1e30f; rl[tid] = 0.0f; }

    float acc[4][4] = {};

    for (int jc = 0; jc < Tz / 64; jc++) {
        const int j0 = jc * 64;
#pragma unroll
        for (int it = 0; it < 4; it++) {
            int idx = tid + it * 256;
            int row = idx >> 4;
            int d4 = (idx & 15) * 4;
            float4 t = *(const float4*)(k + (size_t)(b * Tz + j0 + row) * Hz + h * HDz + d4);
            *(float4*)&Ks[row * SMP + d4] = t;
            float4 tv = *(const float4*)(v + (size_t)(b * Tz + j0 + row) * Hz + h * HDz + d4);
            VsT[(d4 + 0) * SMP + row] = tv.x;
            VsT[(d4 + 1) * SMP + row] = tv.y;
            VsT[(d4 + 2) * SMP + row] = tv.z;
            VsT[(d4 + 3) * SMP + row] = tv.w;
        }
        if (tid < 64) am[tid] = (1.0f - mask[b * Tz + j0 + tid]) * -10000.0f;
        __syncthreads();

        float s[4][4] = {};
#pragma unroll
        for (int d4 = 0; d4 < 64; d4 += 4) {
            float4 qv[4], kv[4];
#pragma unroll
            for (int i = 0; i < 4; i++) qv[i] = *(float4*)&Qs[(ty + 16 * i) * SMP + d4];
#pragma unroll
            for (int j = 0; j < 4; j++) kv[j] = *(float4*)&Ks[(tx + 16 * j) * SMP + d4];
#pragma unroll
            for (int i = 0; i < 4; i++)
#pragma unroll
                for (int j = 0; j < 4; j++) {
                    s[i][j] = fmaf(qv[i].x, kv[j].x, s[i][j]);
                    s[i][j] = fmaf(qv[i].y, kv[j].y, s[i][j]);
                    s[i][j] = fmaf(qv[i].z, kv[j].z, s[i][j]);
                    s[i][j] = fmaf(qv[i].w, kv[j].w, s[i][j]);
                }
        }
#pragma unroll
        for (int i = 0; i < 4; i++)
#pragma unroll
            for (int j = 0; j < 4; j++)
                Ps[(ty + 16 * i) * SMP + tx + 16 * j] = s[i][j] * scale + am[tx + 16 * j];
        __syncthreads();

        {
            const int srow = tid >> 2;
            const int ssub = tid & 3;
            float* prow = Ps + srow * SMP + ssub * 16;
            const float mo = rm[srow];
            float4 pv[4];
            float cm = -1e30f;
#pragma unroll
            for (int c = 0; c < 4; c++) {
                pv[c] = *(float4*)&prow[c * 4];
                cm = fmaxf(cm, fmaxf(fmaxf(pv[c].x, pv[c].y), fmaxf(pv[c].z, pv[c].w)));
            }
            cm = fmaxf(cm, __shfl_xor_sync(0xffffffffu, cm, 1));
            cm = fmaxf(cm, __shfl_xor_sync(0xffffffffu, cm, 2));
            const float nm = fmaxf(mo, cm);
            float sum = 0.0f;
#pragma unroll
            for (int c = 0; c < 4; c++) {
                pv[c].x = __expf(pv[c].x - nm);
                pv[c].y = __expf(pv[c].y - nm);
                pv[c].z = __expf(pv[c].z - nm);
                pv[c].w = __expf(pv[c].w - nm);
                sum += pv[c].x + pv[c].y + pv[c].z + pv[c].w;
                *(float4*)&prow[c * 4] = pv[c];
            }
            sum += __shfl_xor_sync(0xffffffffu, sum, 1);
            sum += __shfl_xor_sync(0xffffffffu, sum, 2);
            if (ssub == 0) {
                const float sc = __expf(mo - nm);
                rl[srow] = rl[srow] * sc + sum;
                rm[srow] = nm;
                rs[srow] = sc;
            }
        }
        __syncthreads();

#pragma unroll
        for (int i = 0; i < 4; i++) {
            const float sc = rs[ty + 16 * i];
#pragma unroll
            for (int j = 0; j < 4; j++) acc[i][j] *= sc;
        }
#pragma unroll
        for (int jj4 = 0; jj4 < 64; jj4 += 4) {
            float4 pv[4], vv[4];
#pragma unroll
            for (int i = 0; i < 4; i++) pv[i] = *(float4*)&Ps[(ty + 16 * i) * SMP + jj4];
#pragma unroll
            for (int j = 0; j < 4; j++) vv[j] = *(float4*)&VsT[(tx + 16 * j) * SMP + jj4];
#pragma unroll
            for (int i = 0; i < 4; i++)
#pragma unroll
                for (int j = 0; j < 4; j++) {
                    acc[i][j] = fmaf(pv[i].x, vv[j].x, acc[i][j]);
                    acc[i][j] = fmaf(pv[i].y, vv[j].y, acc[i][j]);
                    acc[i][j] = fmaf(pv[i].z, vv[j].z, acc[i][j]);
                    acc[i][j] = fmaf(pv[i].w, vv[j].w, acc[i][j]);
                }
        }
        __syncthreads();
    }

#pragma unroll
    for (int i = 0; i < 4; i++) {
        const float inv = 1.0f / rl[ty + 16 * i];
#pragma unroll
        for (int j = 0; j < 4; j++) {
            size_t off = (size_t)(b * Tz + i0 + ty + 16 * i) * Hz + h * HDz + tx + 16 * j;
            float val = acc[i][j] * inv;
            __nv_bfloat16 hv, lv;
            split1(val, hv, lv);
            ctx_h[off] = hv;
            ctx_l[off] = lv;
        }
    }
}

// ---------------- residual + LayerNorm over NP split-K partials + gemm bias ----------------
__device__ __forceinline__ float block_reduce_sum(float val, float* red) {
    const int lane = threadIdx.x & 31, w = threadIdx.x >> 5;
#pragma unroll
    for (int o = 16; o > 0; o >>= 1) val += __shfl_down_sync(0xffffffffu, val, o);
    if (lane == 0) red[w] = val;
    __syncthreads();
    if (w == 0) {
        float t = (lane < 8) ? red[lane] : 0.0f;
#pragma unroll
        for (int o = 4; o > 0; o >>= 1) t += __shfl_down_sync(0xffffffffu, t, o);
        if (lane == 0) red[0] = t;
    }
    __syncthreads();
    float r = red[0];
    __syncthreads();
    return r;
}

template<int NP>
__global__ __launch_bounds__(256) void ln_kernel(
    const float* __restrict__ p0, const float* __restrict__ p1,
    const float* __restrict__ p2, const float* __restrict__ p3,
    const float* __restrict__ gb, const float* __restrict__ res,
    const float* __restrict__ g, const float* __restrict__ bb,
    float* __restrict__ out,
    __nv_bfloat16* __restrict__ oh, __nv_bfloat16* __restrict__ ol)
{
    __shared__ float buf[Hz];
    __shared__ float red[32];
    const int row = blockIdx.x;
    const size_t ro = (size_t)row * Hz;

    float ls = 0.0f;
    for (int i = threadIdx.x; i < Hz; i += 256) {
        float vv = p0[ro + i] + p1[ro + i] + gb[i] + res[ro + i];
        if (NP >= 3) vv += p2[ro + i];
        if (NP >= 4) vv += p3[ro + i];
        buf[i] = vv;
        ls += vv;
    }
    const float mean = block_reduce_sum(ls, red) * (1.0f / Hz);

    float lq = 0.0f;
    for (int i = threadIdx.x; i < Hz; i += 256) {
        float d = buf[i] - mean;
        lq += d * d;
    }
    const float var = block_reduce_sum(lq, red) * (1.0f / Hz);
    const float rstd = rsqrtf(var + 1e-12f);

    for (int i = threadIdx.x; i < Hz; i += 256) {
        float y = (buf[i] - mean) * rstd * g[i] + bb[i];
        out[ro + i] = y;
        __nv_bfloat16 hv, lv;
        split1(y, hv, lv);
        oh[ro + i] = hv;
        ol[ro + i] = lv;
    }
}

// ---------------- launch ----------------
extern "C" void kernel_launch(void* const* d_in, const int* in_sizes, int n_in,
                              void* d_out, int out_size)
{
    const float* hidden = (const float*)d_in[0];
    const float* mask   = (const float*)d_in[1];
    const float* Wq  = (const float*)d_in[2];   const float* bq  = (const float*)d_in[3];
    const float* Wk  = (const float*)d_in[4];   const float* bk  = (const float*)d_in[5];
    const float* Wv  = (const float*)d_in[6];   const float* bv  = (const float*)d_in[7];
    const float* Wao = (const float*)d_in[8];   const float* bao = (const float*)d_in[9];
    const float* g1  = (const float*)d_in[10];  const float* b1  = (const float*)d_in[11];
    const float* Wi  = (const float*)d_in[12];  const float* bi  = (const float*)d_in[13];
    const float* Wo  = (const float*)d_in[14];  const float* bo  = (const float*)d_in[15];
    const float* g2  = (const float*)d_in[16];  const float* b2  = (const float*)d_in[17];
    float* out = (float*)d_out;

    float *q, *k, *v, *p0, *p1, *p2, *p3, *attn, *xb;
    cudaGetSymbolAddress((void**)&q,  g_q);
    cudaGetSymbolAddress((void**)&k,  g_k);
    cudaGetSymbolAddress((void**)&v,  g_v);
    cudaGetSymbolAddress((void**)&p0, g_p0);
    cudaGetSymbolAddress((void**)&p1, g_p1);
    cudaGetSymbolAddress((void**)&p2, g_p2);
    cudaGetSymbolAddress((void**)&p3, g_p3);
    cudaGetSymbolAddress((void**)&attn, g_attn);
    cudaGetSymbolAddress((void**)&xb, g_x);

    __nv_bfloat16 *xh, *xl, *ath, *atl, *cth, *ctl, *ffh, *ffl;
    cudaGetSymbolAddress((void**)&xh,  g_x_h);    cudaGetSymbolAddress((void**)&xl,  g_x_l);
    cudaGetSymbolAddress((void**)&ath, g_attn_h); cudaGetSymbolAddress((void**)&atl, g_attn_l);
    cudaGetSymbolAddress((void**)&cth, g_ctx_h);  cudaGetSymbolAddress((void**)&ctl, g_ctx_l);
    cudaGetSymbolAddress((void**)&ffh, g_ff_h);   cudaGetSymbolAddress((void**)&ffl, g_ff_l);

    __nv_bfloat16 *wqh, *wql, *wkh, *wkl, *wvh, *wvl, *waoh, *waol, *wih, *wil, *woh, *wol;
    cudaGetSymbolAddress((void**)&wqh,  g_wq_h);  cudaGetSymbolAddress((void**)&wql,  g_wq_l);
    cudaGetSymbolAddress((void**)&wkh,  g_wk_h);  cudaGetSymbolAddress((void**)&wkl,  g_wk_l);
    cudaGetSymbolAddress((void**)&wvh,  g_wv_h);  cudaGetSymbolAddress((void**)&wvl,  g_wv_l);
    cudaGetSymbolAddress((void**)&waoh, g_wao_h); cudaGetSymbolAddress((void**)&waol, g_wao_l);
    cudaGetSymbolAddress((void**)&wih,  g_wi_h);  cudaGetSymbolAddress((void**)&wil,  g_wi_l);
    cudaGetSymbolAddress((void**)&woh,  g_wo_h);  cudaGetSymbolAddress((void**)&wol,  g_wo_l);

    // merged prepass: ONE launch splits all weights + input
    {
        const int nHH = Lz * Hz * Hz, nHF = Lz * Hz * FFz, nX = Mz * Hz;
        SplitArgs A;
        A.in[0] = Wq;  A.h[0] = wqh;  A.l[0] = wql;  A.nblk[0] = nHH / 1024;
        A.in[1] = Wk;  A.h[1] = wkh;  A.l[1] = wkl;  A.nblk[1] = nHH / 1024;
        A.in[2] = Wv;  A.h[2] = wvh;  A.l[2] = wvl;  A.nblk[2] = nHH / 1024;
        A.in[3] = Wao; A.h[3] = waoh; A.l[3] = waol; A.nblk[3] = nHH / 1024;
        A.in[4] = Wi;  A.h[4] = wih;  A.l[4] = wil;  A.nblk[4] = nHF / 1024;
        A.in[5] = Wo;  A.h[5] = woh;  A.l[5] = wol;  A.nblk[5] = nHF / 1024;
        A.in[6] = hidden; A.h[6] = xh; A.l[6] = xl;  A.nblk[6] = nX / 1024;
        int total = 4 * (nHH / 1024) + 2 * (nHF / 1024) + nX / 1024;
        split_all_kernel<<<total, 256>>>(A);
    }

    const size_t att_smem = (size_t)(4 * 64 * SMP + 4 * 64) * sizeof(float);
    cudaFuncSetAttribute(attention_kernel,
                         cudaFuncAttributeMaxDynamicSharedMemorySize, (int)att_smem);
    cudaFuncSetAttribute(gemm_bf16x3<0>,
                         cudaFuncAttributeMaxDynamicSharedMemorySize, GEMM_SMEM);
    cudaFuncSetAttribute(gemm_bf16x3<1>,
                         cudaFuncAttributeMaxDynamicSharedMemorySize, GEMM_SMEM);
    cudaFuncSetAttribute(gemm_bf16x3<2>,
                         cudaFuncAttributeMaxDynamicSharedMemorySize, GEMM_SMEM);

    dim3 gAtt(Tz / 64, Bz * NHz);
    dim3 blkA(16, 16);

    for (int l = 0; l < Lz; l++) {
        const float* xres = (l == 0) ? hidden : xb;
        const size_t oHH = (size_t)l * Hz * Hz;
        const size_t oHF = (size_t)l * Hz * FFz;
        const size_t oH  = (size_t)l * Hz;
        const size_t oF  = (size_t)l * FFz;

        {   // fused QKV (z = output index); grid 576 -> 2 waves @97%
            GemmArgs P = {};
            P.Ah[0] = P.Ah[1] = P.Ah[2] = xh;
            P.Al[0] = P.Al[1] = P.Al[2] = xl;
            P.Bh[0] = wqh + oHH; P.Bl[0] = wql + oHH;
            P.Bh[1] = wkh + oHH; P.Bl[1] = wkl + oHH;
            P.Bh[2] = wvh + oHH; P.Bl[2] = wvl + oHH;
            P.bias[0] = bq + oH; P.bias[1] = bk + oH; P.bias[2] = bv + oH;
            P.C[0] = q; P.C[1] = k; P.C[2] = v;
            gemm_bf16x3<0><<<dim3(Hz / BN, Mz / BM, 3), 256, GEMM_SMEM>>>(P, Hz, Hz, Hz);
        }

        attention_kernel<<<gAtt, blkA, att_smem>>>(q, k, v, mask, cth, ctl);

        {   // AO projection: split-K x3 (K=768 -> 3x256); grid 576 -> 2 waves @97%
            GemmArgs P = {};
#pragma unroll
            for (int sK = 0; sK < 3; sK++) {
                P.Ah[sK] = cth + sK * 256;
                P.Al[sK] = ctl + sK * 256;
                P.Bh[sK] = waoh + oHH + (size_t)sK * 256 * Hz;
                P.Bl[sK] = waol + oHH + (size_t)sK * 256 * Hz;
            }
            P.C[0] = p0; P.C[1] = p1; P.C[2] = p2;
            gemm_bf16x3<2><<<dim3(Hz / BN, Mz / BM, 3), 256, GEMM_SMEM>>>(P, Hz, 256, Hz);
        }
        ln_kernel<3><<<Mz, 256>>>(p0, p1, p2, p3, bao + oH, xres, g1 + oH, b1 + oH,
                                  attn, ath, atl);

        {   // FF1 + GELU (split bf16 out); grid 768 -> 3 waves @86%
            GemmArgs P = {};
            P.Ah[0] = ath; P.Al[0] = atl;
            P.Bh[0] = wih + oHF; P.Bl[0] = wil + oHF;
            P.bias[0] = bi + oF;
            P.Ch = ffh; P.Cl = ffl;
            gemm_bf16x3<1><<<dim3(FFz / BN, Mz / BM, 1), 256, GEMM_SMEM>>>(P, Hz, Hz, FFz);
        }
        {   // FF2: split-K x4 (K=3072 -> 4x768); grid 768 -> 3 waves @86%
            GemmArgs P = {};
#pragma unroll
            for (int sK = 0; sK < 4; sK++) {
                P.Ah[sK] = ffh + sK * 768;
                P.Al[sK] = ffl + sK * 768;
                P.Bh[sK] = woh + oHF + (size_t)sK * 768 * Hz;
                P.Bl[sK] = wol + oHF + (size_t)sK * 768 * Hz;
            }
            P.C[0] = p0; P.C[1] = p1; P.C[2] = p2; P.C[3] = p3;
            gemm_bf16x3<2><<<dim3(Hz / BN, Mz / BM, 4), 256, GEMM_SMEM>>>(P, FFz, 768, Hz);
        }
        ln_kernel<4><<<Mz, 256>>>(p0, p1, p2, p3, bo + oH, attn, g2 + oH, b2 + oH,
                                  (l == Lz - 1) ? out : xb, xh, xl);
    }
}

// round 12
// speedup vs baseline: 1.3219x; 1.1904x over previous
#include <cuda_runtime.h>
#include <cuda_bf16.h>
#include <math.h>
#include <stdint.h>

#define Bz  8
#define Tz  512
#define Hz  768
#define NHz 12
#define HDz 64
#define FFz 3072
#define Lz  12
#define Mz  (Bz*Tz)   // 4096

// ---------------- fp32 scratch ----------------
__device__ float g_q[Mz*Hz];
__device__ float g_k[Mz*Hz];
__device__ float g_v[Mz*Hz];
__device__ float g_p0[Mz*Hz];
__device__ float g_p1[Mz*Hz];
__device__ float g_p2[Mz*Hz];
__device__ float g_p3[Mz*Hz];
__device__ float g_attn[Mz*Hz];
__device__ float g_x[Mz*Hz];

// ---------------- split (hi/lo bf16) activation scratch ----------------
__device__ __nv_bfloat16 g_x_h[Mz*Hz],    g_x_l[Mz*Hz];
__device__ __nv_bfloat16 g_attn_h[Mz*Hz], g_attn_l[Mz*Hz];
__device__ __nv_bfloat16 g_ctx_h[Mz*Hz],  g_ctx_l[Mz*Hz];
__device__ __nv_bfloat16 g_ff_h[Mz*FFz],  g_ff_l[Mz*FFz];

// ---------------- split weight storage ([L][K][N], hi/lo) ----------------
__device__ __nv_bfloat16 g_wq_h[Lz*Hz*Hz],  g_wq_l[Lz*Hz*Hz];
__device__ __nv_bfloat16 g_wk_h[Lz*Hz*Hz],  g_wk_l[Lz*Hz*Hz];
__device__ __nv_bfloat16 g_wv_h[Lz*Hz*Hz],  g_wv_l[Lz*Hz*Hz];
__device__ __nv_bfloat16 g_wao_h[Lz*Hz*Hz], g_wao_l[Lz*Hz*Hz];
__device__ __nv_bfloat16 g_wi_h[Lz*Hz*FFz], g_wi_l[Lz*Hz*FFz];
__device__ __nv_bfloat16 g_wo_h[Lz*Hz*FFz], g_wo_l[Lz*Hz*FFz];

// ---------------- helpers ----------------
__device__ __forceinline__ void split1(float x, __nv_bfloat16& h, __nv_bfloat16& l) {
    h = __float2bfloat16(x);
    l = __float2bfloat16(x - __bfloat162float(h));
}
__device__ __forceinline__ void split2(float x, float y, uint32_t& hi, uint32_t& lo) {
    __nv_bfloat16 xh, xl, yh, yl;
    split1(x, xh, xl); split1(y, yh, yl);
    hi = (uint32_t)__bfloat16_as_ushort(xh) | ((uint32_t)__bfloat16_as_ushort(yh) << 16);
    lo = (uint32_t)__bfloat16_as_ushort(xl) | ((uint32_t)__bfloat16_as_ushort(yl) << 16);
}

// -------- merged prepass: split 7 tensors in ONE launch --------
struct SplitArgs {
    const float* in[7];
    __nv_bfloat16* h[7];
    __nv_bfloat16* l[7];
    int nblk[7];
};

__global__ __launch_bounds__(256) void split_all_kernel(SplitArgs A)
{
    int b = blockIdx.x;
    int seg = 0;
#pragma unroll
    for (int s = 0; s < 7; s++) {
        if (b < A.nblk[s]) { seg = s; break; }
        b -= A.nblk[s];
    }
    const int i = b * 256 + threadIdx.x;
    float4 v = ((const float4*)A.in[seg])[i];
    uint32_t h01, l01, h23, l23;
    split2(v.x, v.y, h01, l01);
    split2(v.z, v.w, h23, l23);
    ((uint2*)A.h[seg])[i] = make_uint2(h01, h23);
    ((uint2*)A.l[seg])[i] = make_uint2(l01, l23);
}

// ===== bf16x3 mma.sync GEMM: BK=32, 3 stages, XOR-swizzled smem, 2 CTAs/SM =====
#define BM 128
#define BN 128
#define BK2 32

#define PLANE 4096
#define STG_ELEMS (4*PLANE)
#define GEMM_SMEM (3*STG_ELEMS*2)

#define ASOFFZ(s,pl,m,c)  ((s)*STG_ELEMS + (pl)*PLANE + (m)*32  + ((((c) ^ (((m)>>1)&3)))<<3))
#define BSOFFZ(s,pl,kk,c) ((s)*STG_ELEMS + 2*PLANE + (pl)*PLANE + (kk)*128 + ((((c) ^ ((kk)&7)))<<3))

struct GemmArgs {
    const __nv_bfloat16 *Ah[4], *Al[4];
    const __nv_bfloat16 *Bh[4], *Bl[4];
    const float* bias[4];
    float* C[4];
    __nv_bfloat16 *Ch, *Cl;
};

__device__ __forceinline__ void cpa16(void* dst, const void* src) {
    uint32_t d = (uint32_t)__cvta_generic_to_shared(dst);
    asm volatile("cp.async.cg.shared.global [%0], [%1], 16;" :: "r"(d), "l"(src));
}
__device__ __forceinline__ void ldsm4(uint32_t* r, const void* p) {
    uint32_t a = (uint32_t)__cvta_generic_to_shared(p);
    asm volatile("ldmatrix.sync.aligned.m8n8.x4.shared.b16 {%0,%1,%2,%3}, [%4];"
                 : "=r"(r[0]), "=r"(r[1]), "=r"(r[2]), "=r"(r[3]) : "r"(a));
}
__device__ __forceinline__ void ldsm4t(uint32_t* r, const void* p) {
    uint32_t a = (uint32_t)__cvta_generic_to_shared(p);
    asm volatile("ldmatrix.sync.aligned.m8n8.x4.trans.shared.b16 {%0,%1,%2,%3}, [%4];"
                 : "=r"(r[0]), "=r"(r[1]), "=r"(r[2]), "=r"(r[3]) : "r"(a));
}
__device__ __forceinline__ void mma16816(float* c, const uint32_t* a, const uint32_t* b) {
    asm volatile(
        "mma.sync.aligned.m16n8k16.row.col.f32.bf16.bf16.f32 "
        "{%0,%1,%2,%3}, {%4,%5,%6,%7}, {%8,%9}, {%0,%1,%2,%3};"
        : "+f"(c[0]), "+f"(c[1]), "+f"(c[2]), "+f"(c[3])
        : "r"(a[0]), "r"(a[1]), "r"(a[2]), "r"(a[3]), "r"(b[0]), "r"(b[1]));
}

// MODE 0: fp32 out + bias (QKV). MODE 1: bias + exact GELU, split bf16 out (FF1).
// MODE 2: fp32 partial out, NO bias (split-K slices; bias folded into LN).
template<int MODE>
__global__ __launch_bounds__(256, 2) void gemm_bf16x3(GemmArgs P, int K_ld, int K_len, int N)
{
    extern __shared__ __align__(16) __nv_bfloat16 sm[];

    const int z = blockIdx.z;
    const __nv_bfloat16* __restrict__ Ah = P.Ah[z];
    const __nv_bfloat16* __restrict__ Al = P.Al[z];
    const __nv_bfloat16* __restrict__ Bh = P.Bh[z];
    const __nv_bfloat16* __restrict__ Bl = P.Bl[z];

    const int n0 = blockIdx.x * BN;
    const int m0 = blockIdx.y * BM;
    const int tid  = threadIdx.x;
    const int lane = tid & 31;
    const int warp = tid >> 5;
    const int warpM = warp >> 2;
    const int warpN = warp & 3;

    const int nT = K_len / BK2;

    auto issue = [&](int t, int s) {
        const int k0 = t * BK2;
#pragma unroll
        for (int p = 0; p < 2; p++) {
            const int idx = tid + p * 256;
            const int ar = idx >> 2, acc_ = idx & 3;
            cpa16(sm + ASOFFZ(s, 0, ar, acc_), Ah + (size_t)(m0 + ar) * K_ld + k0 + acc_ * 8);
            cpa16(sm + ASOFFZ(s, 1, ar, acc_), Al + (size_t)(m0 + ar) * K_ld + k0 + acc_ * 8);
            const int br = idx >> 4, bcc = idx & 15;
            cpa16(sm + BSOFFZ(s, 0, br, bcc), Bh + (size_t)(k0 + br) * N + n0 + bcc * 8);
            cpa16(sm + BSOFFZ(s, 1, br, bcc), Bl + (size_t)(k0 + br) * N + n0 + bcc * 8);
        }
        asm volatile("cp.async.commit_group;" ::: "memory");
    };

    issue(0, 0);
    issue(1, 1);

    float acc[4][4][4] = {};
    int s = 0;

    for (int t = 0; t < nT; t++) {
        if (t + 1 < nT) asm volatile("cp.async.wait_group 1;" ::: "memory");
        else            asm volatile("cp.async.wait_group 0;" ::: "memory");
        __syncthreads();

        if (t + 2 < nT) {
            int s2 = s + 2; if (s2 >= 3) s2 -= 3;
            issue(t + 2, s2);
        }

#pragma unroll
        for (int sub = 0; sub < 2; sub++) {
            uint32_t ah[4][4], al[4][4], bh[4][2], bl[4][2];
            const int cA = sub * 2 + (lane >> 4);
#pragma unroll
            for (int mi = 0; mi < 4; mi++) {
                const int arow = warpM * 64 + mi * 16 + (lane & 15);
                ldsm4(ah[mi], sm + ASOFFZ(s, 0, arow, cA));
                ldsm4(al[mi], sm + ASOFFZ(s, 1, arow, cA));
            }
            const int brow = sub * 16 + (lane & 15);
#pragma unroll
            for (int pr = 0; pr < 2; pr++) {
                const int cB = warpN * 4 + pr * 2 + (lane >> 4);
                uint32_t tmp[4];
                ldsm4t(tmp, sm + BSOFFZ(s, 0, brow, cB));
                bh[pr * 2][0] = tmp[0]; bh[pr * 2][1] = tmp[1];
                bh[pr * 2 + 1][0] = tmp[2]; bh[pr * 2 + 1][1] = tmp[3];
                ldsm4t(tmp, sm + BSOFFZ(s, 1, brow, cB));
                bl[pr * 2][0] = tmp[0]; bl[pr * 2][1] = tmp[1];
                bl[pr * 2 + 1][0] = tmp[2]; bl[pr * 2 + 1][1] = tmp[3];
            }
#pragma unroll
            for (int mi = 0; mi < 4; mi++)
#pragma unroll
                for (int ni = 0; ni < 4; ni++)
                    mma16816(acc[mi][ni], ah[mi], bh[ni]);
#pragma unroll
            for (int mi = 0; mi < 4; mi++)
#pragma unroll
                for (int ni = 0; ni < 4; ni++)
                    mma16816(acc[mi][ni], ah[mi], bl[ni]);
#pragma unroll
            for (int mi = 0; mi < 4; mi++)
#pragma unroll
                for (int ni = 0; ni < 4; ni++)
                    mma16816(acc[mi][ni], al[mi], bh[ni]);
        }
        if (++s == 3) s = 0;
    }

    const float* __restrict__ bias = P.bias[z];
    const int g  = lane >> 2;
    const int tg = lane & 3;
#pragma unroll
    for (int mi = 0; mi < 4; mi++) {
#pragma unroll
        for (int ni = 0; ni < 4; ni++) {
            const int row = m0 + warpM * 64 + mi * 16 + g;
            const int col = n0 + warpN * 32 + ni * 8 + tg * 2;
            float v0 = acc[mi][ni][0];
            float v1 = acc[mi][ni][1];
            float v2 = acc[mi][ni][2];
            float v3 = acc[mi][ni][3];
            if (MODE != 2) {
                const float b0 = bias[col], b1 = bias[col + 1];
                v0 += b0; v1 += b1; v2 += b0; v3 += b1;
            }
            if (MODE == 1) {
                v0 = 0.5f * v0 * (1.0f + erff(v0 * 0.70710678118654752f));
                v1 = 0.5f * v1 * (1.0f + erff(v1 * 0.70710678118654752f));
                v2 = 0.5f * v2 * (1.0f + erff(v2 * 0.70710678118654752f));
                v3 = 0.5f * v3 * (1.0f + erff(v3 * 0.70710678118654752f));
                uint32_t hw, lw;
                split2(v0, v1, hw, lw);
                *(uint32_t*)(P.Ch + (size_t)row * N + col) = hw;
                *(uint32_t*)(P.Cl + (size_t)row * N + col) = lw;
                split2(v2, v3, hw, lw);
                *(uint32_t*)(P.Ch + (size_t)(row + 8) * N + col) = hw;
                *(uint32_t*)(P.Cl + (size_t)(row + 8) * N + col) = lw;
            } else {
                float* C = P.C[z];
                *(float2*)(C + (size_t)row * N + col)       = make_float2(v0, v1);
                *(float2*)(C + (size_t)(row + 8) * N + col) = make_float2(v2, v3);
            }
        }
    }
}

// ---------------- tensor-core flash attention (bf16x3 mma + fp32 softmax) ----------------
#define ALD 72   // bf16 tile leading dim (144B rows; conflict-free ldsm)
#define SLD 68   // fp32 S tile leading dim
#define ATT_SMEM (64*SLD*4 + 8*64*ALD*2 + 4*64*4)   // 92160 B

__global__ __launch_bounds__(256, 2) void attention_kernel(
    const float* __restrict__ q, const float* __restrict__ k,
    const float* __restrict__ v, const float* __restrict__ mask,
    __nv_bfloat16* __restrict__ ctx_h, __nv_bfloat16* __restrict__ ctx_l)
{
    extern __shared__ char smraw[];
    float* Sf = (float*)smraw;
    __nv_bfloat16* Qh = (__nv_bfloat16*)(smraw + 64 * SLD * 4);
    __nv_bfloat16* Ql = Qh + 64 * ALD;
    __nv_bfloat16* Kh = Ql + 64 * ALD;
    __nv_bfloat16* Kl = Kh + 64 * ALD;
    __nv_bfloat16* Vh = Kl + 64 * ALD;
    __nv_bfloat16* Vl = Vh + 64 * ALD;
    __nv_bfloat16* Ph = Vl + 64 * ALD;
    __nv_bfloat16* Pl = Ph + 64 * ALD;
    float* rm = (float*)(Pl + 64 * ALD);
    float* rl = rm + 64;
    float* rs = rl + 64;
    float* am = rs + 64;

    const int tid  = threadIdx.x;
    const int lane = tid & 31;
    const int warp = tid >> 5;
    const int warpM = warp >> 2;   // 0..1  (32 output rows each)
    const int warpN = warp & 3;    // 0..3  (16 output cols each)
    const int g  = lane >> 2;
    const int tg = lane & 3;
    const int bh = blockIdx.y;
    const int b = bh / NHz, h = bh % NHz;
    const int i0 = blockIdx.x * 64;
    const float scale = 0.125f;

    // load Q (fp32 -> hi/lo bf16)
#pragma unroll
    for (int it = 0; it < 4; it++) {
        const int idx = tid + it * 256;
        const int row = idx >> 4, d4 = (idx & 15) * 4;
        float4 t = *(const float4*)(q + (size_t)(b * Tz + i0 + row) * Hz + h * HDz + d4);
        uint32_t h01, l01, h23, l23;
        split2(t.x, t.y, h01, l01);
        split2(t.z, t.w, h23, l23);
        *(uint2*)&Qh[row * ALD + d4] = make_uint2(h01, h23);
        *(uint2*)&Ql[row * ALD + d4] = make_uint2(l01, l23);
    }
    if (tid < 64) { rm[tid] = -1e30f; rl[tid] = 0.0f; }

    float acco[2][2][4] = {};

    for (int jc = 0; jc < Tz / 64; jc++) {
        const int j0 = jc * 64;
        __syncthreads();   // prev chunk's mma done reading K/V/P smem

        // load K, V chunk (fp32 -> hi/lo bf16); K as [n][k], V as [k][n]=natural [j][d]
#pragma unroll
        for (int it = 0; it < 4; it++) {
            const int idx = tid + it * 256;
            const int row = idx >> 4, d4 = (idx & 15) * 4;
            float4 t = *(const float4*)(k + (size_t)(b * Tz + j0 + row) * Hz + h * HDz + d4);
            uint32_t h01, l01, h23, l23;
            split2(t.x, t.y, h01, l01);
            split2(t.z, t.w, h23, l23);
            *(uint2*)&Kh[row * ALD + d4] = make_uint2(h01, h23);
            *(uint2*)&Kl[row * ALD + d4] = make_uint2(l01, l23);
            float4 tv = *(const float4*)(v + (size_t)(b * Tz + j0 + row) * Hz + h * HDz + d4);
            split2(tv.x, tv.y, h01, l01);
            split2(tv.z, tv.w, h23, l23);
            *(uint2*)&Vh[row * ALD + d4] = make_uint2(h01, h23);
            *(uint2*)&Vl[row * ALD + d4] = make_uint2(l01, l23);
        }
        if (tid < 64) am[tid] = (1.0f - mask[b * Tz + j0 + tid]) * -10000.0f;
        __syncthreads();

        // S = Q @ K^T via mma (bf16x3). K stored [n][k] -> B frags via plain ldsm4.
        float accs[2][2][4] = {};
#pragma unroll
        for (int kk = 0; kk < 4; kk++) {
            const int colk = kk * 16 + (lane >> 4) * 8;
            uint32_t qh[2][4], ql[2][4];
#pragma unroll
            for (int mi = 0; mi < 2; mi++) {
                const int r = warpM * 32 + mi * 16 + (lane & 15);
                ldsm4(qh[mi], &Qh[r * ALD + colk]);
                ldsm4(ql[mi], &Ql[r * ALD + colk]);
            }
            uint32_t kh[2][2], kl[2][2];
            {
                const int r = warpN * 16 + (lane & 15);
                uint32_t t[4];
                ldsm4(t, &Kh[r * ALD + colk]);
                kh[0][0] = t[0]; kh[0][1] = t[2]; kh[1][0] = t[1]; kh[1][1] = t[3];
                ldsm4(t, &Kl[r * ALD + colk]);
                kl[0][0] = t[0]; kl[0][1] = t[2]; kl[1][0] = t[1]; kl[1][1] = t[3];
            }
#pragma unroll
            for (int mi = 0; mi < 2; mi++)
#pragma unroll
                for (int ni = 0; ni < 2; ni++) {
                    mma16816(accs[mi][ni], qh[mi], kh[ni]);
                    mma16816(accs[mi][ni], qh[mi], kl[ni]);
                    mma16816(accs[mi][ni], ql[mi], kh[ni]);
                }
        }
        // write S (scale + mask) to fp32 smem
#pragma unroll
        for (int mi = 0; mi < 2; mi++)
#pragma unroll
            for (int ni = 0; ni < 2; ni++) {
                const int row = warpM * 32 + mi * 16 + g;
                const int col = warpN * 16 + ni * 8 + tg * 2;
                Sf[row * SLD + col]           = accs[mi][ni][0] * scale + am[col];
                Sf[row * SLD + col + 1]       = accs[mi][ni][1] * scale + am[col + 1];
                Sf[(row + 8) * SLD + col]     = accs[mi][ni][2] * scale + am[col];
                Sf[(row + 8) * SLD + col + 1] = accs[mi][ni][3] * scale + am[col + 1];
            }
        __syncthreads();

        // parallel online softmax: 4 threads per row
        {
            const int srow = tid >> 2;
            const int ssub = tid & 3;
            float* prow = Sf + srow * SLD + ssub * 16;
            const float mo = rm[srow];
            float4 pv[4];
            float cm = -1e30f;
#pragma unroll
            for (int c = 0; c < 4; c++) {
                pv[c] = *(float4*)&prow[c * 4];
                cm = fmaxf(cm, fmaxf(fmaxf(pv[c].x, pv[c].y), fmaxf(pv[c].z, pv[c].w)));
            }
            cm = fmaxf(cm, __shfl_xor_sync(0xffffffffu, cm, 1));
            cm = fmaxf(cm, __shfl_xor_sync(0xffffffffu, cm, 2));
            const float nm = fmaxf(mo, cm);
            float sum = 0.0f;
#pragma unroll
            for (int c = 0; c < 4; c++) {
                pv[c].x = __expf(pv[c].x - nm);
                pv[c].y = __expf(pv[c].y - nm);
                pv[c].z = __expf(pv[c].z - nm);
                pv[c].w = __expf(pv[c].w - nm);
                sum += pv[c].x + pv[c].y + pv[c].z + pv[c].w;
                *(float4*)&prow[c * 4] = pv[c];
            }
            sum += __shfl_xor_sync(0xffffffffu, sum, 1);
            sum += __shfl_xor_sync(0xffffffffu, sum, 2);
            if (ssub == 0) {
                const float sc = __expf(mo - nm);
                rl[srow] = rl[srow] * sc + sum;
                rm[srow] = nm;
                rs[srow] = sc;
            }
        }
        __syncthreads();

        // convert P to hi/lo bf16 + rescale output accumulators
        {
            const int row = tid >> 2;
            const int q4  = tid & 3;
            const float* src = &Sf[row * SLD + q4 * 16];
            __nv_bfloat16* dh = &Ph[row * ALD + q4 * 16];
            __nv_bfloat16* dl = &Pl[row * ALD + q4 * 16];
#pragma unroll
            for (int c = 0; c < 4; c++) {
                float4 t = *(const float4*)&src[c * 4];
                uint32_t h01, l01, h23, l23;
                split2(t.x, t.y, h01, l01);
                split2(t.z, t.w, h23, l23);
                *(uint2*)&dh[c * 4] = make_uint2(h01, h23);
                *(uint2*)&dl[c * 4] = make_uint2(l01, l23);
            }
        }
#pragma unroll
        for (int mi = 0; mi < 2; mi++) {
            const int r1 = warpM * 32 + mi * 16 + g;
            const float s1 = rs[r1], s2 = rs[r1 + 8];
#pragma unroll
            for (int ni = 0; ni < 2; ni++) {
                acco[mi][ni][0] *= s1; acco[mi][ni][1] *= s1;
                acco[mi][ni][2] *= s2; acco[mi][ni][3] *= s2;
            }
        }
        __syncthreads();

        // O += P @ V via mma (bf16x3). V stored [k][n] -> B frags via ldsm4t.
#pragma unroll
        for (int kk = 0; kk < 4; kk++) {
            const int colk = kk * 16 + (lane >> 4) * 8;
            uint32_t ph[2][4], pl[2][4];
#pragma unroll
            for (int mi = 0; mi < 2; mi++) {
                const int r = warpM * 32 + mi * 16 + (lane & 15);
                ldsm4(ph[mi], &Ph[r * ALD + colk]);
                ldsm4(pl[mi], &Pl[r * ALD + colk]);
            }
            uint32_t vh[2][2], vl[2][2];
            {
                const int r = kk * 16 + (lane & 15);
                const int c = warpN * 16 + (lane >> 4) * 8;
                uint32_t t[4];
                ldsm4t(t, &Vh[r * ALD + c]);
                vh[0][0] = t[0]; vh[0][1] = t[1]; vh[1][0] = t[2]; vh[1][1] = t[3];
                ldsm4t(t, &Vl[r * ALD + c]);
                vl[0][0] = t[0]; vl[0][1] = t[1]; vl[1][0] = t[2]; vl[1][1] = t[3];
            }
#pragma unroll
            for (int mi = 0; mi < 2; mi++)
#pragma unroll
                for (int ni = 0; ni < 2; ni++) {
                    mma16816(acco[mi][ni], ph[mi], vh[ni]);
                    mma16816(acco[mi][ni], pl[mi], vh[ni]);
                    mma16816(acco[mi][ni], ph[mi], vl[ni]);
                }
        }
    }

    // epilogue: O / rl -> split bf16 ctx
#pragma unroll
    for (int mi = 0; mi < 2; mi++) {
        const int row = warpM * 32 + mi * 16 + g;
        const float inv1 = 1.0f / rl[row];
        const float inv2 = 1.0f / rl[row + 8];
#pragma unroll
        for (int ni = 0; ni < 2; ni++) {
            const int col = warpN * 16 + ni * 8 + tg * 2;
            size_t off = (size_t)(b * Tz + i0 + row) * Hz + h * HDz + col;
            uint32_t hw, lw;
            split2(acco[mi][ni][0] * inv1, acco[mi][ni][1] * inv1, hw, lw);
            *(uint32_t*)(ctx_h + off) = hw;
            *(uint32_t*)(ctx_l + off) = lw;
            off = (size_t)(b * Tz + i0 + row + 8) * Hz + h * HDz + col;
            split2(acco[mi][ni][2] * inv2, acco[mi][ni][3] * inv2, hw, lw);
            *(uint32_t*)(ctx_h + off) = hw;
            *(uint32_t*)(ctx_l + off) = lw;
        }
    }
}

// ---------------- residual + LayerNorm over NP split-K partials + gemm bias ----------------
__device__ __forceinline__ float block_reduce_sum(float val, float* red) {
    const int lane = threadIdx.x & 31, w = threadIdx.x >> 5;
#pragma unroll
    for (int o = 16; o > 0; o >>= 1) val += __shfl_down_sync(0xffffffffu, val, o);
    if (lane == 0) red[w] = val;
    __syncthreads();
    if (w == 0) {
        float t = (lane < 8) ? red[lane] : 0.0f;
#pragma unroll
        for (int o = 4; o > 0; o >>= 1) t += __shfl_down_sync(0xffffffffu, t, o);
        if (lane == 0) red[0] = t;
    }
    __syncthreads();
    float r = red[0];
    __syncthreads();
    return r;
}

template<int NP>
__global__ __launch_bounds__(256) void ln_kernel(
    const float* __restrict__ p0, const float* __restrict__ p1,
    const float* __restrict__ p2, const float* __restrict__ p3,
    const float* __restrict__ gb, const float* __restrict__ res,
    const float* __restrict__ g, const float* __restrict__ bb,
    float* __restrict__ out,
    __nv_bfloat16* __restrict__ oh, __nv_bfloat16* __restrict__ ol)
{
    __shared__ float buf[Hz];
    __shared__ float red[32];
    const int row = blockIdx.x;
    const size_t ro = (size_t)row * Hz;

    float ls = 0.0f;
    for (int i = threadIdx.x; i < Hz; i += 256) {
        float vv = p0[ro + i] + p1[ro + i] + gb[i] + res[ro + i];
        if (NP >= 3) vv += p2[ro + i];
        if (NP >= 4) vv += p3[ro + i];
        buf[i] = vv;
        ls += vv;
    }
    const float mean = block_reduce_sum(ls, red) * (1.0f / Hz);

    float lq = 0.0f;
    for (int i = threadIdx.x; i < Hz; i += 256) {
        float d = buf[i] - mean;
        lq += d * d;
    }
    const float var = block_reduce_sum(lq, red) * (1.0f / Hz);
    const float rstd = rsqrtf(var + 1e-12f);

    for (int i = threadIdx.x; i < Hz; i += 256) {
        float y = (buf[i] - mean) * rstd * g[i] + bb[i];
        out[ro + i] = y;
        __nv_bfloat16 hv, lv;
        split1(y, hv, lv);
        oh[ro + i] = hv;
        ol[ro + i] = lv;
    }
}

// ---------------- launch ----------------
extern "C" void kernel_launch(void* const* d_in, const int* in_sizes, int n_in,
                              void* d_out, int out_size)
{
    const float* hidden = (const float*)d_in[0];
    const float* mask   = (const float*)d_in[1];
    const float* Wq  = (const float*)d_in[2];   const float* bq  = (const float*)d_in[3];
    const float* Wk  = (const float*)d_in[4];   const float* bk  = (const float*)d_in[5];
    const float* Wv  = (const float*)d_in[6];   const float* bv  = (const float*)d_in[7];
    const float* Wao = (const float*)d_in[8];   const float* bao = (const float*)d_in[9];
    const float* g1  = (const float*)d_in[10];  const float* b1  = (const float*)d_in[11];
    const float* Wi  = (const float*)d_in[12];  const float* bi  = (const float*)d_in[13];
    const float* Wo  = (const float*)d_in[14];  const float* bo  = (const float*)d_in[15];
    const float* g2  = (const float*)d_in[16];  const float* b2  = (const float*)d_in[17];
    float* out = (float*)d_out;

    float *q, *k, *v, *p0, *p1, *p2, *p3, *attn, *xb;
    cudaGetSymbolAddress((void**)&q,  g_q);
    cudaGetSymbolAddress((void**)&k,  g_k);
    cudaGetSymbolAddress((void**)&v,  g_v);
    cudaGetSymbolAddress((void**)&p0, g_p0);
    cudaGetSymbolAddress((void**)&p1, g_p1);
    cudaGetSymbolAddress((void**)&p2, g_p2);
    cudaGetSymbolAddress((void**)&p3, g_p3);
    cudaGetSymbolAddress((void**)&attn, g_attn);
    cudaGetSymbolAddress((void**)&xb, g_x);

    __nv_bfloat16 *xh, *xl, *ath, *atl, *cth, *ctl, *ffh, *ffl;
    cudaGetSymbolAddress((void**)&xh,  g_x_h);    cudaGetSymbolAddress((void**)&xl,  g_x_l);
    cudaGetSymbolAddress((void**)&ath, g_attn_h); cudaGetSymbolAddress((void**)&atl, g_attn_l);
    cudaGetSymbolAddress((void**)&cth, g_ctx_h);  cudaGetSymbolAddress((void**)&ctl, g_ctx_l);
    cudaGetSymbolAddress((void**)&ffh, g_ff_h);   cudaGetSymbolAddress((void**)&ffl, g_ff_l);

    __nv_bfloat16 *wqh, *wql, *wkh, *wkl, *wvh, *wvl, *waoh, *waol, *wih, *wil, *woh, *wol;
    cudaGetSymbolAddress((void**)&wqh,  g_wq_h);  cudaGetSymbolAddress((void**)&wql,  g_wq_l);
    cudaGetSymbolAddress((void**)&wkh,  g_wk_h);  cudaGetSymbolAddress((void**)&wkl,  g_wk_l);
    cudaGetSymbolAddress((void**)&wvh,  g_wv_h);  cudaGetSymbolAddress((void**)&wvl,  g_wv_l);
    cudaGetSymbolAddress((void**)&waoh, g_wao_h); cudaGetSymbolAddress((void**)&waol, g_wao_l);
    cudaGetSymbolAddress((void**)&wih,  g_wi_h);  cudaGetSymbolAddress((void**)&wil,  g_wi_l);
    cudaGetSymbolAddress((void**)&woh,  g_wo_h);  cudaGetSymbolAddress((void**)&wol,  g_wo_l);

    // merged prepass: ONE launch splits all weights + input
    {
        const int nHH = Lz * Hz * Hz, nHF = Lz * Hz * FFz, nX = Mz * Hz;
        SplitArgs A;
        A.in[0] = Wq;  A.h[0] = wqh;  A.l[0] = wql;  A.nblk[0] = nHH / 1024;
        A.in[1] = Wk;  A.h[1] = wkh;  A.l[1] = wkl;  A.nblk[1] = nHH / 1024;
        A.in[2] = Wv;  A.h[2] = wvh;  A.l[2] = wvl;  A.nblk[2] = nHH / 1024;
        A.in[3] = Wao; A.h[3] = waoh; A.l[3] = waol; A.nblk[3] = nHH / 1024;
        A.in[4] = Wi;  A.h[4] = wih;  A.l[4] = wil;  A.nblk[4] = nHF / 1024;
        A.in[5] = Wo;  A.h[5] = woh;  A.l[5] = wol;  A.nblk[5] = nHF / 1024;
        A.in[6] = hidden; A.h[6] = xh; A.l[6] = xl;  A.nblk[6] = nX / 1024;
        int total = 4 * (nHH / 1024) + 2 * (nHF / 1024) + nX / 1024;
        split_all_kernel<<<total, 256>>>(A);
    }

    cudaFuncSetAttribute(attention_kernel,
                         cudaFuncAttributeMaxDynamicSharedMemorySize, ATT_SMEM);
    cudaFuncSetAttribute(gemm_bf16x3<0>,
                         cudaFuncAttributeMaxDynamicSharedMemorySize, GEMM_SMEM);
    cudaFuncSetAttribute(gemm_bf16x3<1>,
                         cudaFuncAttributeMaxDynamicSharedMemorySize, GEMM_SMEM);
    cudaFuncSetAttribute(gemm_bf16x3<2>,
                         cudaFuncAttributeMaxDynamicSharedMemorySize, GEMM_SMEM);

    dim3 gAtt(Tz / 64, Bz * NHz);

    for (int l = 0; l < Lz; l++) {
        const float* xres = (l == 0) ? hidden : xb;
        const size_t oHH = (size_t)l * Hz * Hz;
        const size_t oHF = (size_t)l * Hz * FFz;
        const size_t oH  = (size_t)l * Hz;
        const size_t oF  = (size_t)l * FFz;

        {   // fused QKV (z = output index)
            GemmArgs P = {};
            P.Ah[0] = P.Ah[1] = P.Ah[2] = xh;
            P.Al[0] = P.Al[1] = P.Al[2] = xl;
            P.Bh[0] = wqh + oHH; P.Bl[0] = wql + oHH;
            P.Bh[1] = wkh + oHH; P.Bl[1] = wkl + oHH;
            P.Bh[2] = wvh + oHH; P.Bl[2] = wvl + oHH;
            P.bias[0] = bq + oH; P.bias[1] = bk + oH; P.bias[2] = bv + oH;
            P.C[0] = q; P.C[1] = k; P.C[2] = v;
            gemm_bf16x3<0><<<dim3(Hz / BN, Mz / BM, 3), 256, GEMM_SMEM>>>(P, Hz, Hz, Hz);
        }

        attention_kernel<<<gAtt, 256, ATT_SMEM>>>(q, k, v, mask, cth, ctl);

        {   // AO projection: split-K x3 (K=768 -> 3x256)
            GemmArgs P = {};
#pragma unroll
            for (int sK = 0; sK < 3; sK++) {
                P.Ah[sK] = cth + sK * 256;
                P.Al[sK] = ctl + sK * 256;
                P.Bh[sK] = waoh + oHH + (size_t)sK * 256 * Hz;
                P.Bl[sK] = waol + oHH + (size_t)sK * 256 * Hz;
            }
            P.C[0] = p0; P.C[1] = p1; P.C[2] = p2;
            gemm_bf16x3<2><<<dim3(Hz / BN, Mz / BM, 3), 256, GEMM_SMEM>>>(P, Hz, 256, Hz);
        }
        ln_kernel<3><<<Mz, 256>>>(p0, p1, p2, p3, bao + oH, xres, g1 + oH, b1 + oH,
                                  attn, ath, atl);

        {   // FF1 + GELU (split bf16 out)
            GemmArgs P = {};
            P.Ah[0] = ath; P.Al[0] = atl;
            P.Bh[0] = wih + oHF; P.Bl[0] = wil + oHF;
            P.bias[0] = bi + oF;
            P.Ch = ffh; P.Cl = ffl;
            gemm_bf16x3<1><<<dim3(FFz / BN, Mz / BM, 1), 256, GEMM_SMEM>>>(P, Hz, Hz, FFz);
        }
        {   // FF2: split-K x4 (K=3072 -> 4x768)
            GemmArgs P = {};
#pragma unroll
            for (int sK = 0; sK < 4; sK++) {
                P.Ah[sK] = ffh + sK * 768;
                P.Al[sK] = ffl + sK * 768;
                P.Bh[sK] = woh + oHF + (size_t)sK * 768 * Hz;
                P.Bl[sK] = wol + oHF + (size_t)sK * 768 * Hz;
            }
            P.C[0] = p0; P.C[1] = p1; P.C[2] = p2; P.C[3] = p3;
            gemm_bf16x3<2><<<dim3(Hz / BN, Mz / BM, 4), 256, GEMM_SMEM>>>(P, FFz, 768, Hz);
        }
        ln_kernel<4><<<Mz, 256>>>(p0, p1, p2, p3, bo + oH, attn, g2 + oH, b2 + oH,
                                  (l == Lz - 1) ? out : xb, xh, xl);
    }
}

// round 13
// speedup vs baseline: 1.3518x; 1.0226x over previous
#include <cuda_runtime.h>
#include <cuda_bf16.h>
#include <math.h>
#include <stdint.h>

#define Bz  8
#define Tz  512
#define Hz  768
#define NHz 12
#define HDz 64
#define FFz 3072
#define Lz  12
#define Mz  (Bz*Tz)   // 4096

// ---------------- fp32 scratch ----------------
__device__ float g_q[Mz*Hz];
__device__ float g_k[Mz*Hz];
__device__ float g_v[Mz*Hz];
__device__ float g_p0[Mz*Hz];
__device__ float g_p1[Mz*Hz];
__device__ float g_p2[Mz*Hz];
__device__ float g_p3[Mz*Hz];
__device__ float g_attn[Mz*Hz];
__device__ float g_x[Mz*Hz];

// ---------------- split (hi/lo bf16) activation scratch ----------------
__device__ __nv_bfloat16 g_x_h[Mz*Hz],    g_x_l[Mz*Hz];
__device__ __nv_bfloat16 g_attn_h[Mz*Hz], g_attn_l[Mz*Hz];
__device__ __nv_bfloat16 g_ctx_h[Mz*Hz],  g_ctx_l[Mz*Hz];
__device__ __nv_bfloat16 g_ff_h[Mz*FFz],  g_ff_l[Mz*FFz];

// ---------------- split weight storage ([L][K][N], hi/lo) ----------------
__device__ __nv_bfloat16 g_wq_h[Lz*Hz*Hz],  g_wq_l[Lz*Hz*Hz];
__device__ __nv_bfloat16 g_wk_h[Lz*Hz*Hz],  g_wk_l[Lz*Hz*Hz];
__device__ __nv_bfloat16 g_wv_h[Lz*Hz*Hz],  g_wv_l[Lz*Hz*Hz];
__device__ __nv_bfloat16 g_wao_h[Lz*Hz*Hz], g_wao_l[Lz*Hz*Hz];
__device__ __nv_bfloat16 g_wi_h[Lz*Hz*FFz], g_wi_l[Lz*Hz*FFz];
__device__ __nv_bfloat16 g_wo_h[Lz*Hz*FFz], g_wo_l[Lz*Hz*FFz];

// ---------------- helpers ----------------
__device__ __forceinline__ void split1(float x, __nv_bfloat16& h, __nv_bfloat16& l) {
    h = __float2bfloat16(x);
    l = __float2bfloat16(x - __bfloat162float(h));
}
__device__ __forceinline__ void split2(float x, float y, uint32_t& hi, uint32_t& lo) {
    __nv_bfloat16 xh, xl, yh, yl;
    split1(x, xh, xl); split1(y, yh, yl);
    hi = (uint32_t)__bfloat16_as_ushort(xh) | ((uint32_t)__bfloat16_as_ushort(yh) << 16);
    lo = (uint32_t)__bfloat16_as_ushort(xl) | ((uint32_t)__bfloat16_as_ushort(yl) << 16);
}

// -------- merged prepass: split 7 tensors in ONE launch, 2 float4/thread --------
struct SplitArgs {
    const float* in[7];
    __nv_bfloat16* h[7];
    __nv_bfloat16* l[7];
    int nblk[7];   // blocks per segment (each block = 512 float4)
};

__global__ __launch_bounds__(256) void split_all_kernel(SplitArgs A)
{
    int b = blockIdx.x;
    int seg = 0;
#pragma unroll
    for (int s = 0; s < 7; s++) {
        if (b < A.nblk[s]) { seg = s; break; }
        b -= A.nblk[s];
    }
    const float4* in = (const float4*)A.in[seg];
    uint2* oh = (uint2*)A.h[seg];
    uint2* ol = (uint2*)A.l[seg];
    const int i0 = b * 512 + threadIdx.x;
    // two independent float4 per thread (MLP=2)
    float4 v0 = in[i0];
    float4 v1 = in[i0 + 256];
    uint32_t h01, l01, h23, l23;
    split2(v0.x, v0.y, h01, l01);
    split2(v0.z, v0.w, h23, l23);
    oh[i0] = make_uint2(h01, h23);
    ol[i0] = make_uint2(l01, l23);
    split2(v1.x, v1.y, h01, l01);
    split2(v1.z, v1.w, h23, l23);
    oh[i0 + 256] = make_uint2(h01, h23);
    ol[i0 + 256] = make_uint2(l01, l23);
}

// ===== bf16x3 mma.sync GEMM: BK=32, 3 stages, XOR-swizzled smem, 2 CTAs/SM =====
#define BM 128
#define BN 128
#define BK2 32

#define PLANE 4096
#define STG_ELEMS (4*PLANE)
#define GEMM_SMEM (3*STG_ELEMS*2)

#define ASOFFZ(s,pl,m,c)  ((s)*STG_ELEMS + (pl)*PLANE + (m)*32  + ((((c) ^ (((m)>>1)&3)))<<3))
#define BSOFFZ(s,pl,kk,c) ((s)*STG_ELEMS + 2*PLANE + (pl)*PLANE + (kk)*128 + ((((c) ^ ((kk)&7)))<<3))

struct GemmArgs {
    const __nv_bfloat16 *Ah[4], *Al[4];
    const __nv_bfloat16 *Bh[4], *Bl[4];
    const float* bias[4];
    float* C[4];
    __nv_bfloat16 *Ch, *Cl;
};

__device__ __forceinline__ void cpa16(void* dst, const void* src) {
    uint32_t d = (uint32_t)__cvta_generic_to_shared(dst);
    asm volatile("cp.async.cg.shared.global [%0], [%1], 16;" :: "r"(d), "l"(src));
}
__device__ __forceinline__ void ldsm4(uint32_t* r, const void* p) {
    uint32_t a = (uint32_t)__cvta_generic_to_shared(p);
    asm volatile("ldmatrix.sync.aligned.m8n8.x4.shared.b16 {%0,%1,%2,%3}, [%4];"
                 : "=r"(r[0]), "=r"(r[1]), "=r"(r[2]), "=r"(r[3]) : "r"(a));
}
__device__ __forceinline__ void ldsm4t(uint32_t* r, const void* p) {
    uint32_t a = (uint32_t)__cvta_generic_to_shared(p);
    asm volatile("ldmatrix.sync.aligned.m8n8.x4.trans.shared.b16 {%0,%1,%2,%3}, [%4];"
                 : "=r"(r[0]), "=r"(r[1]), "=r"(r[2]), "=r"(r[3]) : "r"(a));
}
__device__ __forceinline__ void mma16816(float* c, const uint32_t* a, const uint32_t* b) {
    asm volatile(
        "mma.sync.aligned.m16n8k16.row.col.f32.bf16.bf16.f32 "
        "{%0,%1,%2,%3}, {%4,%5,%6,%7}, {%8,%9}, {%0,%1,%2,%3};"
        : "+f"(c[0]), "+f"(c[1]), "+f"(c[2]), "+f"(c[3])
        : "r"(a[0]), "r"(a[1]), "r"(a[2]), "r"(a[3]), "r"(b[0]), "r"(b[1]));
}

// MODE 0: fp32 out + bias (QKV). MODE 1: bias + exact GELU, split bf16 out (FF1).
// MODE 2: fp32 partial out, NO bias (split-K slices; bias folded into LN).
template<int MODE>
__global__ __launch_bounds__(256, 2) void gemm_bf16x3(GemmArgs P, int K_ld, int K_len, int N)
{
    extern __shared__ __align__(16) __nv_bfloat16 sm[];

    const int z = blockIdx.z;
    const __nv_bfloat16* __restrict__ Ah = P.Ah[z];
    const __nv_bfloat16* __restrict__ Al = P.Al[z];
    const __nv_bfloat16* __restrict__ Bh = P.Bh[z];
    const __nv_bfloat16* __restrict__ Bl = P.Bl[z];

    const int n0 = blockIdx.x * BN;
    const int m0 = blockIdx.y * BM;
    const int tid  = threadIdx.x;
    const int lane = tid & 31;
    const int warp = tid >> 5;
    const int warpM = warp >> 2;
    const int warpN = warp & 3;

    const int nT = K_len / BK2;

    auto issue = [&](int t, int s) {
        const int k0 = t * BK2;
#pragma unroll
        for (int p = 0; p < 2; p++) {
            const int idx = tid + p * 256;
            const int ar = idx >> 2, acc_ = idx & 3;
            cpa16(sm + ASOFFZ(s, 0, ar, acc_), Ah + (size_t)(m0 + ar) * K_ld + k0 + acc_ * 8);
            cpa16(sm + ASOFFZ(s, 1, ar, acc_), Al + (size_t)(m0 + ar) * K_ld + k0 + acc_ * 8);
            const int br = idx >> 4, bcc = idx & 15;
            cpa16(sm + BSOFFZ(s, 0, br, bcc), Bh + (size_t)(k0 + br) * N + n0 + bcc * 8);
            cpa16(sm + BSOFFZ(s, 1, br, bcc), Bl + (size_t)(k0 + br) * N + n0 + bcc * 8);
        }
        asm volatile("cp.async.commit_group;" ::: "memory");
    };

    issue(0, 0);
    issue(1, 1);

    float acc[4][4][4] = {};
    int s = 0;

    for (int t = 0; t < nT; t++) {
        if (t + 1 < nT) asm volatile("cp.async.wait_group 1;" ::: "memory");
        else            asm volatile("cp.async.wait_group 0;" ::: "memory");
        __syncthreads();

        if (t + 2 < nT) {
            int s2 = s + 2; if (s2 >= 3) s2 -= 3;
            issue(t + 2, s2);
        }

#pragma unroll
        for (int sub = 0; sub < 2; sub++) {
            uint32_t ah[4][4], al[4][4], bh[4][2], bl[4][2];
            const int cA = sub * 2 + (lane >> 4);
#pragma unroll
            for (int mi = 0; mi < 4; mi++) {
                const int arow = warpM * 64 + mi * 16 + (lane & 15);
                ldsm4(ah[mi], sm + ASOFFZ(s, 0, arow, cA));
                ldsm4(al[mi], sm + ASOFFZ(s, 1, arow, cA));
            }
            const int brow = sub * 16 + (lane & 15);
#pragma unroll
            for (int pr = 0; pr < 2; pr++) {
                const int cB = warpN * 4 + pr * 2 + (lane >> 4);
                uint32_t tmp[4];
                ldsm4t(tmp, sm + BSOFFZ(s, 0, brow, cB));
                bh[pr * 2][0] = tmp[0]; bh[pr * 2][1] = tmp[1];
                bh[pr * 2 + 1][0] = tmp[2]; bh[pr * 2 + 1][1] = tmp[3];
                ldsm4t(tmp, sm + BSOFFZ(s, 1, brow, cB));
                bl[pr * 2][0] = tmp[0]; bl[pr * 2][1] = tmp[1];
                bl[pr * 2 + 1][0] = tmp[2]; bl[pr * 2 + 1][1] = tmp[3];
            }
#pragma unroll
            for (int mi = 0; mi < 4; mi++)
#pragma unroll
                for (int ni = 0; ni < 4; ni++)
                    mma16816(acc[mi][ni], ah[mi], bh[ni]);
#pragma unroll
            for (int mi = 0; mi < 4; mi++)
#pragma unroll
                for (int ni = 0; ni < 4; ni++)
                    mma16816(acc[mi][ni], ah[mi], bl[ni]);
#pragma unroll
            for (int mi = 0; mi < 4; mi++)
#pragma unroll
                for (int ni = 0; ni < 4; ni++)
                    mma16816(acc[mi][ni], al[mi], bh[ni]);
        }
        if (++s == 3) s = 0;
    }

    const float* __restrict__ bias = P.bias[z];
    const int g  = lane >> 2;
    const int tg = lane & 3;
#pragma unroll
    for (int mi = 0; mi < 4; mi++) {
#pragma unroll
        for (int ni = 0; ni < 4; ni++) {
            const int row = m0 + warpM * 64 + mi * 16 + g;
            const int col = n0 + warpN * 32 + ni * 8 + tg * 2;
            float v0 = acc[mi][ni][0];
            float v1 = acc[mi][ni][1];
            float v2 = acc[mi][ni][2];
            float v3 = acc[mi][ni][3];
            if (MODE != 2) {
                const float b0 = bias[col], b1 = bias[col + 1];
                v0 += b0; v1 += b1; v2 += b0; v3 += b1;
            }
            if (MODE == 1) {
                v0 = 0.5f * v0 * (1.0f + erff(v0 * 0.70710678118654752f));
                v1 = 0.5f * v1 * (1.0f + erff(v1 * 0.70710678118654752f));
                v2 = 0.5f * v2 * (1.0f + erff(v2 * 0.70710678118654752f));
                v3 = 0.5f * v3 * (1.0f + erff(v3 * 0.70710678118654752f));
                uint32_t hw, lw;
                split2(v0, v1, hw, lw);
                *(uint32_t*)(P.Ch + (size_t)row * N + col) = hw;
                *(uint32_t*)(P.Cl + (size_t)row * N + col) = lw;
                split2(v2, v3, hw, lw);
                *(uint32_t*)(P.Ch + (size_t)(row + 8) * N + col) = hw;
                *(uint32_t*)(P.Cl + (size_t)(row + 8) * N + col) = lw;
            } else {
                float* C = P.C[z];
                *(float2*)(C + (size_t)row * N + col)       = make_float2(v0, v1);
                *(float2*)(C + (size_t)(row + 8) * N + col) = make_float2(v2, v3);
            }
        }
    }
}

// ---------------- tensor-core flash attention (bf16x3 mma + fp32 softmax) ----------------
#define ALD 72   // bf16 tile leading dim (144B rows; conflict-free ldsm)
#define SLD 68   // fp32 S tile leading dim
#define ATT_SMEM (64*SLD*4 + 8*64*ALD*2 + 4*64*4)   // 92160 B

__global__ __launch_bounds__(256, 2) void attention_kernel(
    const float* __restrict__ q, const float* __restrict__ k,
    const float* __restrict__ v, const float* __restrict__ mask,
    __nv_bfloat16* __restrict__ ctx_h, __nv_bfloat16* __restrict__ ctx_l)
{
    extern __shared__ char smraw[];
    float* Sf = (float*)smraw;
    __nv_bfloat16* Qh = (__nv_bfloat16*)(smraw + 64 * SLD * 4);
    __nv_bfloat16* Ql = Qh + 64 * ALD;
    __nv_bfloat16* Kh = Ql + 64 * ALD;
    __nv_bfloat16* Kl = Kh + 64 * ALD;
    __nv_bfloat16* Vh = Kl + 64 * ALD;
    __nv_bfloat16* Vl = Vh + 64 * ALD;
    __nv_bfloat16* Ph = Vl + 64 * ALD;
    __nv_bfloat16* Pl = Ph + 64 * ALD;
    float* rm = (float*)(Pl + 64 * ALD);
    float* rl = rm + 64;
    float* rs = rl + 64;
    float* am = rs + 64;

    const int tid  = threadIdx.x;
    const int lane = tid & 31;
    const int warp = tid >> 5;
    const int warpM = warp >> 2;
    const int warpN = warp & 3;
    const int g  = lane >> 2;
    const int tg = lane & 3;
    const int bh = blockIdx.y;
    const int b = bh / NHz, h = bh % NHz;
    const int i0 = blockIdx.x * 64;
    const float scale = 0.125f;

#pragma unroll
    for (int it = 0; it < 4; it++) {
        const int idx = tid + it * 256;
        const int row = idx >> 4, d4 = (idx & 15) * 4;
        float4 t = *(const float4*)(q + (size_t)(b * Tz + i0 + row) * Hz + h * HDz + d4);
        uint32_t h01, l01, h23, l23;
        split2(t.x, t.y, h01, l01);
        split2(t.z, t.w, h23, l23);
        *(uint2*)&Qh[row * ALD + d4] = make_uint2(h01, h23);
        *(uint2*)&Ql[row * ALD + d4] = make_uint2(l01, l23);
    }
    if (tid < 64) { rm[tid] = -1e30f; rl[tid] = 0.0f; }

    float acco[2][2][4] = {};

    for (int jc = 0; jc < Tz / 64; jc++) {
        const int j0 = jc * 64;
        __syncthreads();

#pragma unroll
        for (int it = 0; it < 4; it++) {
            const int idx = tid + it * 256;
            const int row = idx >> 4, d4 = (idx & 15) * 4;
            float4 t = *(const float4*)(k + (size_t)(b * Tz + j0 + row) * Hz + h * HDz + d4);
            uint32_t h01, l01, h23, l23;
            split2(t.x, t.y, h01, l01);
            split2(t.z, t.w, h23, l23);
            *(uint2*)&Kh[row * ALD + d4] = make_uint2(h01, h23);
            *(uint2*)&Kl[row * ALD + d4] = make_uint2(l01, l23);
            float4 tv = *(const float4*)(v + (size_t)(b * Tz + j0 + row) * Hz + h * HDz + d4);
            split2(tv.x, tv.y, h01, l01);
            split2(tv.z, tv.w, h23, l23);
            *(uint2*)&Vh[row * ALD + d4] = make_uint2(h01, h23);
            *(uint2*)&Vl[row * ALD + d4] = make_uint2(l01, l23);
        }
        if (tid < 64) am[tid] = (1.0f - mask[b * Tz + j0 + tid]) * -10000.0f;
        __syncthreads();

        // S = Q @ K^T via mma (bf16x3)
        float accs[2][2][4] = {};
#pragma unroll
        for (int kk = 0; kk < 4; kk++) {
            const int colk = kk * 16 + (lane >> 4) * 8;
            uint32_t qh[2][4], ql[2][4];
#pragma unroll
            for (int mi = 0; mi < 2; mi++) {
                const int r = warpM * 32 + mi * 16 + (lane & 15);
                ldsm4(qh[mi], &Qh[r * ALD + colk]);
                ldsm4(ql[mi], &Ql[r * ALD + colk]);
            }
            uint32_t kh[2][2], kl[2][2];
            {
                const int r = warpN * 16 + (lane & 15);
                uint32_t t[4];
                ldsm4(t, &Kh[r * ALD + colk]);
                kh[0][0] = t[0]; kh[0][1] = t[2]; kh[1][0] = t[1]; kh[1][1] = t[3];
                ldsm4(t, &Kl[r * ALD + colk]);
                kl[0][0] = t[0]; kl[0][1] = t[2]; kl[1][0] = t[1]; kl[1][1] = t[3];
            }
#pragma unroll
            for (int mi = 0; mi < 2; mi++)
#pragma unroll
                for (int ni = 0; ni < 2; ni++) {
                    mma16816(accs[mi][ni], qh[mi], kh[ni]);
                    mma16816(accs[mi][ni], qh[mi], kl[ni]);
                    mma16816(accs[mi][ni], ql[mi], kh[ni]);
                }
        }
#pragma unroll
        for (int mi = 0; mi < 2; mi++)
#pragma unroll
            for (int ni = 0; ni < 2; ni++) {
                const int row = warpM * 32 + mi * 16 + g;
                const int col = warpN * 16 + ni * 8 + tg * 2;
                Sf[row * SLD + col]           = accs[mi][ni][0] * scale + am[col];
                Sf[row * SLD + col + 1]       = accs[mi][ni][1] * scale + am[col + 1];
                Sf[(row + 8) * SLD + col]     = accs[mi][ni][2] * scale + am[col];
                Sf[(row + 8) * SLD + col + 1] = accs[mi][ni][3] * scale + am[col + 1];
            }
        __syncthreads();

        // parallel online softmax
        {
            const int srow = tid >> 2;
            const int ssub = tid & 3;
            float* prow = Sf + srow * SLD + ssub * 16;
            const float mo = rm[srow];
            float4 pv[4];
            float cm = -1e30f;
#pragma unroll
            for (int c = 0; c < 4; c++) {
                pv[c] = *(float4*)&prow[c * 4];
                cm = fmaxf(cm, fmaxf(fmaxf(pv[c].x, pv[c].y), fmaxf(pv[c].z, pv[c].w)));
            }
            cm = fmaxf(cm, __shfl_xor_sync(0xffffffffu, cm, 1));
            cm = fmaxf(cm, __shfl_xor_sync(0xffffffffu, cm, 2));
            const float nm = fmaxf(mo, cm);
            float sum = 0.0f;
#pragma unroll
            for (int c = 0; c < 4; c++) {
                pv[c].x = __expf(pv[c].x - nm);
                pv[c].y = __expf(pv[c].y - nm);
                pv[c].z = __expf(pv[c].z - nm);
                pv[c].w = __expf(pv[c].w - nm);
                sum += pv[c].x + pv[c].y + pv[c].z + pv[c].w;
                *(float4*)&prow[c * 4] = pv[c];
            }
            sum += __shfl_xor_sync(0xffffffffu, sum, 1);
            sum += __shfl_xor_sync(0xffffffffu, sum, 2);
            if (ssub == 0) {
                const float sc = __expf(mo - nm);
                rl[srow] = rl[srow] * sc + sum;
                rm[srow] = nm;
                rs[srow] = sc;
            }
        }
        __syncthreads();

        // P -> hi/lo bf16; rescale output accumulators
        {
            const int row = tid >> 2;
            const int q4  = tid & 3;
            const float* src = &Sf[row * SLD + q4 * 16];
            __nv_bfloat16* dh = &Ph[row * ALD + q4 * 16];
            __nv_bfloat16* dl = &Pl[row * ALD + q4 * 16];
#pragma unroll
            for (int c = 0; c < 4; c++) {
                float4 t = *(const float4*)&src[c * 4];
                uint32_t h01, l01, h23, l23;
                split2(t.x, t.y, h01, l01);
                split2(t.z, t.w, h23, l23);
                *(uint2*)&dh[c * 4] = make_uint2(h01, h23);
                *(uint2*)&dl[c * 4] = make_uint2(l01, l23);
            }
        }
#pragma unroll
        for (int mi = 0; mi < 2; mi++) {
            const int r1 = warpM * 32 + mi * 16 + g;
            const float s1 = rs[r1], s2 = rs[r1 + 8];
#pragma unroll
            for (int ni = 0; ni < 2; ni++) {
                acco[mi][ni][0] *= s1; acco[mi][ni][1] *= s1;
                acco[mi][ni][2] *= s2; acco[mi][ni][3] *= s2;
            }
        }
        __syncthreads();

        // O += P @ V via mma (bf16x3)
#pragma unroll
        for (int kk = 0; kk < 4; kk++) {
            const int colk = kk * 16 + (lane >> 4) * 8;
            uint32_t ph[2][4], pl[2][4];
#pragma unroll
            for (int mi = 0; mi < 2; mi++) {
                const int r = warpM * 32 + mi * 16 + (lane & 15);
                ldsm4(ph[mi], &Ph[r * ALD + colk]);
                ldsm4(pl[mi], &Pl[r * ALD + colk]);
            }
            uint32_t vh[2][2], vl[2][2];
            {
                const int r = kk * 16 + (lane & 15);
                const int c = warpN * 16 + (lane >> 4) * 8;
                uint32_t t[4];
                ldsm4t(t, &Vh[r * ALD + c]);
                vh[0][0] = t[0]; vh[0][1] = t[1]; vh[1][0] = t[2]; vh[1][1] = t[3];
                ldsm4t(t, &Vl[r * ALD + c]);
                vl[0][0] = t[0]; vl[0][1] = t[1]; vl[1][0] = t[2]; vl[1][1] = t[3];
            }
#pragma unroll
            for (int mi = 0; mi < 2; mi++)
#pragma unroll
                for (int ni = 0; ni < 2; ni++) {
                    mma16816(acco[mi][ni], ph[mi], vh[ni]);
                    mma16816(acco[mi][ni], pl[mi], vh[ni]);
                    mma16816(acco[mi][ni], ph[mi], vl[ni]);
                }
        }
    }

#pragma unroll
    for (int mi = 0; mi < 2; mi++) {
        const int row = warpM * 32 + mi * 16 + g;
        const float inv1 = 1.0f / rl[row];
        const float inv2 = 1.0f / rl[row + 8];
#pragma unroll
        for (int ni = 0; ni < 2; ni++) {
            const int col = warpN * 16 + ni * 8 + tg * 2;
            size_t off = (size_t)(b * Tz + i0 + row) * Hz + h * HDz + col;
            uint32_t hw, lw;
            split2(acco[mi][ni][0] * inv1, acco[mi][ni][1] * inv1, hw, lw);
            *(uint32_t*)(ctx_h + off) = hw;
            *(uint32_t*)(ctx_l + off) = lw;
            off = (size_t)(b * Tz + i0 + row + 8) * Hz + h * HDz + col;
            split2(acco[mi][ni][2] * inv2, acco[mi][ni][3] * inv2, hw, lw);
            *(uint32_t*)(ctx_h + off) = hw;
            *(uint32_t*)(ctx_l + off) = lw;
        }
    }
}

// ---- register-resident LayerNorm: 1 float4/thread, fused sum/sumsq reduction ----
template<int NP>
__global__ __launch_bounds__(256) void ln_kernel(
    const float* __restrict__ p0, const float* __restrict__ p1,
    const float* __restrict__ p2, const float* __restrict__ p3,
    const float* __restrict__ gb, const float* __restrict__ res,
    const float* __restrict__ g, const float* __restrict__ bb,
    float* __restrict__ out,
    __nv_bfloat16* __restrict__ oh, __nv_bfloat16* __restrict__ ol)
{
    __shared__ float2 red2[8];
    const int row = blockIdx.x;
    const size_t ro = (size_t)row * Hz;
    const int i4 = threadIdx.x * 4;          // active if i4 < 768
    const int lane = threadIdx.x & 31, w = threadIdx.x >> 5;

    float4 xv = make_float4(0.f, 0.f, 0.f, 0.f);
    if (i4 < Hz) {
        float4 a0 = *(const float4*)(p0 + ro + i4);
        float4 a1 = *(const float4*)(p1 + ro + i4);
        float4 rr = *(const float4*)(res + ro + i4);
        float4 gg = *(const float4*)(gb + i4);
        xv.x = a0.x + a1.x + rr.x + gg.x;
        xv.y = a0.y + a1.y + rr.y + gg.y;
        xv.z = a0.z + a1.z + rr.z + gg.z;
        xv.w = a0.w + a1.w + rr.w + gg.w;
        if (NP >= 3) {
            float4 a2 = *(const float4*)(p2 + ro + i4);
            xv.x += a2.x; xv.y += a2.y; xv.z += a2.z; xv.w += a2.w;
        }
        if (NP >= 4) {
            float4 a3 = *(const float4*)(p3 + ro + i4);
            xv.x += a3.x; xv.y += a3.y; xv.z += a3.z; xv.w += a3.w;
        }
    }
    float s  = xv.x + xv.y + xv.z + xv.w;
    float sq = xv.x * xv.x + xv.y * xv.y + xv.z * xv.z + xv.w * xv.w;
#pragma unroll
    for (int o = 16; o > 0; o >>= 1) {
        s  += __shfl_down_sync(0xffffffffu, s, o);
        sq += __shfl_down_sync(0xffffffffu, sq, o);
    }
    if (lane == 0) red2[w] = make_float2(s, sq);
    __syncthreads();
    if (w == 0) {
        float2 t = (lane < 8) ? red2[lane] : make_float2(0.f, 0.f);
#pragma unroll
        for (int o = 4; o > 0; o >>= 1) {
            t.x += __shfl_down_sync(0xffffffffu, t.x, o);
            t.y += __shfl_down_sync(0xffffffffu, t.y, o);
        }
        if (lane == 0) red2[0] = t;
    }
    __syncthreads();
    const float mean = red2[0].x * (1.0f / Hz);
    const float var  = red2[0].y * (1.0f / Hz) - mean * mean;
    const float rstd = rsqrtf(var + 1e-12f);

    if (i4 < Hz) {
        float4 gv = *(const float4*)(g + i4);
        float4 bv = *(const float4*)(bb + i4);
        float4 y;
        y.x = (xv.x - mean) * rstd * gv.x + bv.x;
        y.y = (xv.y - mean) * rstd * gv.y + bv.y;
        y.z = (xv.z - mean) * rstd * gv.z + bv.z;
        y.w = (xv.w - mean) * rstd * gv.w + bv.w;
        *(float4*)(out + ro + i4) = y;
        uint32_t h01, l01, h23, l23;
        split2(y.x, y.y, h01, l01);
        split2(y.z, y.w, h23, l23);
        *(uint2*)(oh + ro + i4) = make_uint2(h01, h23);
        *(uint2*)(ol + ro + i4) = make_uint2(l01, l23);
    }
}

// ---------------- launch ----------------
extern "C" void kernel_launch(void* const* d_in, const int* in_sizes, int n_in,
                              void* d_out, int out_size)
{
    const float* hidden = (const float*)d_in[0];
    const float* mask   = (const float*)d_in[1];
    const float* Wq  = (const float*)d_in[2];   const float* bq  = (const float*)d_in[3];
    const float* Wk  = (const float*)d_in[4];   const float* bk  = (const float*)d_in[5];
    const float* Wv  = (const float*)d_in[6];   const float* bv  = (const float*)d_in[7];
    const float* Wao = (const float*)d_in[8];   const float* bao = (const float*)d_in[9];
    const float* g1  = (const float*)d_in[10];  const float* b1  = (const float*)d_in[11];
    const float* Wi  = (const float*)d_in[12];  const float* bi  = (const float*)d_in[13];
    const float* Wo  = (const float*)d_in[14];  const float* bo  = (const float*)d_in[15];
    const float* g2  = (const float*)d_in[16];  const float* b2  = (const float*)d_in[17];
    float* out = (float*)d_out;

    float *q, *k, *v, *p0, *p1, *p2, *p3, *attn, *xb;
    cudaGetSymbolAddress((void**)&q,  g_q);
    cudaGetSymbolAddress((void**)&k,  g_k);
    cudaGetSymbolAddress((void**)&v,  g_v);
    cudaGetSymbolAddress((void**)&p0, g_p0);
    cudaGetSymbolAddress((void**)&p1, g_p1);
    cudaGetSymbolAddress((void**)&p2, g_p2);
    cudaGetSymbolAddress((void**)&p3, g_p3);
    cudaGetSymbolAddress((void**)&attn, g_attn);
    cudaGetSymbolAddress((void**)&xb, g_x);

    __nv_bfloat16 *xh, *xl, *ath, *atl, *cth, *ctl, *ffh, *ffl;
    cudaGetSymbolAddress((void**)&xh,  g_x_h);    cudaGetSymbolAddress((void**)&xl,  g_x_l);
    cudaGetSymbolAddress((void**)&ath, g_attn_h); cudaGetSymbolAddress((void**)&atl, g_attn_l);
    cudaGetSymbolAddress((void**)&cth, g_ctx_h);  cudaGetSymbolAddress((void**)&ctl, g_ctx_l);
    cudaGetSymbolAddress((void**)&ffh, g_ff_h);   cudaGetSymbolAddress((void**)&ffl, g_ff_l);

    __nv_bfloat16 *wqh, *wql, *wkh, *wkl, *wvh, *wvl, *waoh, *waol, *wih, *wil, *woh, *wol;
    cudaGetSymbolAddress((void**)&wqh,  g_wq_h);  cudaGetSymbolAddress((void**)&wql,  g_wq_l);
    cudaGetSymbolAddress((void**)&wkh,  g_wk_h);  cudaGetSymbolAddress((void**)&wkl,  g_wk_l);
    cudaGetSymbolAddress((void**)&wvh,  g_wv_h);  cudaGetSymbolAddress((void**)&wvl,  g_wv_l);
    cudaGetSymbolAddress((void**)&waoh, g_wao_h); cudaGetSymbolAddress((void**)&waol, g_wao_l);
    cudaGetSymbolAddress((void**)&wih,  g_wi_h);  cudaGetSymbolAddress((void**)&wil,  g_wi_l);
    cudaGetSymbolAddress((void**)&woh,  g_wo_h);  cudaGetSymbolAddress((void**)&wol,  g_wo_l);

    // merged prepass: ONE launch splits all weights + input (512 float4/block)
    {
        const int nHH = Lz * Hz * Hz, nHF = Lz * Hz * FFz, nX = Mz * Hz;
        SplitArgs A;
        A.in[0] = Wq;  A.h[0] = wqh;  A.l[0] = wql;  A.nblk[0] = nHH / 2048;
        A.in[1] = Wk;  A.h[1] = wkh;  A.l[1] = wkl;  A.nblk[1] = nHH / 2048;
        A.in[2] = Wv;  A.h[2] = wvh;  A.l[2] = wvl;  A.nblk[2] = nHH / 2048;
        A.in[3] = Wao; A.h[3] = waoh; A.l[3] = waol; A.nblk[3] = nHH / 2048;
        A.in[4] = Wi;  A.h[4] = wih;  A.l[4] = wil;  A.nblk[4] = nHF / 2048;
        A.in[5] = Wo;  A.h[5] = woh;  A.l[5] = wol;  A.nblk[5] = nHF / 2048;
        A.in[6] = hidden; A.h[6] = xh; A.l[6] = xl;  A.nblk[6] = nX / 2048;
        int total = 4 * (nHH / 2048) + 2 * (nHF / 2048) + nX / 2048;
        split_all_kernel<<<total, 256>>>(A);
    }

    cudaFuncSetAttribute(attention_kernel,
                         cudaFuncAttributeMaxDynamicSharedMemorySize, ATT_SMEM);
    cudaFuncSetAttribute(gemm_bf16x3<0>,
                         cudaFuncAttributeMaxDynamicSharedMemorySize, GEMM_SMEM);
    cudaFuncSetAttribute(gemm_bf16x3<1>,
                         cudaFuncAttributeMaxDynamicSharedMemorySize, GEMM_SMEM);
    cudaFuncSetAttribute(gemm_bf16x3<2>,
                         cudaFuncAttributeMaxDynamicSharedMemorySize, GEMM_SMEM);

    dim3 gAtt(Tz / 64, Bz * NHz);

    for (int l = 0; l < Lz; l++) {
        const float* xres = (l == 0) ? hidden : xb;
        const size_t oHH = (size_t)l * Hz * Hz;
        const size_t oHF = (size_t)l * Hz * FFz;
        const size_t oH  = (size_t)l * Hz;
        const size_t oF  = (size_t)l * FFz;

        {   // fused QKV
            GemmArgs P = {};
            P.Ah[0] = P.Ah[1] = P.Ah[2] = xh;
            P.Al[0] = P.Al[1] = P.Al[2] = xl;
            P.Bh[0] = wqh + oHH; P.Bl[0] = wql + oHH;
            P.Bh[1] = wkh + oHH; P.Bl[1] = wkl + oHH;
            P.Bh[2] = wvh + oHH; P.Bl[2] = wvl + oHH;
            P.bias[0] = bq + oH; P.bias[1] = bk + oH; P.bias[2] = bv + oH;
            P.C[0] = q; P.C[1] = k; P.C[2] = v;
            gemm_bf16x3<0><<<dim3(Hz / BN, Mz / BM, 3), 256, GEMM_SMEM>>>(P, Hz, Hz, Hz);
        }

        attention_kernel<<<gAtt, 256, ATT_SMEM>>>(q, k, v, mask, cth, ctl);

        {   // AO projection: split-K x3
            GemmArgs P = {};
#pragma unroll
            for (int sK = 0; sK < 3; sK++) {
                P.Ah[sK] = cth + sK * 256;
                P.Al[sK] = ctl + sK * 256;
                P.Bh[sK] = waoh + oHH + (size_t)sK * 256 * Hz;
                P.Bl[sK] = waol + oHH + (size_t)sK * 256 * Hz;
            }
            P.C[0] = p0; P.C[1] = p1; P.C[2] = p2;
            gemm_bf16x3<2><<<dim3(Hz / BN, Mz / BM, 3), 256, GEMM_SMEM>>>(P, Hz, 256, Hz);
        }
        ln_kernel<3><<<Mz, 256>>>(p0, p1, p2, p3, bao + oH, xres, g1 + oH, b1 + oH,
                                  attn, ath, atl);

        {   // FF1 + GELU
            GemmArgs P = {};
            P.Ah[0] = ath; P.Al[0] = atl;
            P.Bh[0] = wih + oHF; P.Bl[0] = wil + oHF;
            P.bias[0] = bi + oF;
            P.Ch = ffh; P.Cl = ffl;
            gemm_bf16x3<1><<<dim3(FFz / BN, Mz / BM, 1), 256, GEMM_SMEM>>>(P, Hz, Hz, FFz);
        }
        {   // FF2: split-K x4
            GemmArgs P = {};
#pragma unroll
            for (int sK = 0; sK < 4; sK++) {
                P.Ah[sK] = ffh + sK * 768;
                P.Al[sK] = ffl + sK * 768;
                P.Bh[sK] = woh + oHF + (size_t)sK * 768 * Hz;
                P.Bl[sK] = wol + oHF + (size_t)sK * 768 * Hz;
            }
            P.C[0] = p0; P.C[1] = p1; P.C[2] = p2; P.C[3] = p3;
            gemm_bf16x3<2><<<dim3(Hz / BN, Mz / BM, 4), 256, GEMM_SMEM>>>(P, FFz, 768, Hz);
        }
        ln_kernel<4><<<Mz, 256>>>(p0, p1, p2, p3, bo + oH, attn, g2 + oH, b2 + oH,
                                  (l == Lz - 1) ? out : xb, xh, xl);
    }
}

// round 14
// speedup vs baseline: 1.3846x; 1.0243x over previous
#include <cuda_runtime.h>
#include <cuda_bf16.h>
#include <math.h>
#include <stdint.h>

#define Bz  8
#define Tz  512
#define Hz  768
#define NHz 12
#define HDz 64
#define FFz 3072
#define Lz  12
#define Mz  (Bz*Tz)   // 4096

// ---------------- fp32 scratch ----------------
__device__ float g_p0[Mz*Hz];
__device__ float g_p1[Mz*Hz];
__device__ float g_p2[Mz*Hz];
__device__ float g_p3[Mz*Hz];
__device__ float g_attn[Mz*Hz];
__device__ float g_x[Mz*Hz];

// ---------------- split (hi/lo bf16) activation scratch ----------------
__device__ __nv_bfloat16 g_qh[Mz*Hz], g_ql[Mz*Hz];
__device__ __nv_bfloat16 g_kh[Mz*Hz], g_kl[Mz*Hz];
__device__ __nv_bfloat16 g_vh[Mz*Hz], g_vl[Mz*Hz];
__device__ __nv_bfloat16 g_x_h[Mz*Hz],    g_x_l[Mz*Hz];
__device__ __nv_bfloat16 g_attn_h[Mz*Hz], g_attn_l[Mz*Hz];
__device__ __nv_bfloat16 g_ctx_h[Mz*Hz],  g_ctx_l[Mz*Hz];
__device__ __nv_bfloat16 g_ff_h[Mz*FFz],  g_ff_l[Mz*FFz];

// ---------------- split weight storage ([L][K][N], hi/lo) ----------------
__device__ __nv_bfloat16 g_wq_h[Lz*Hz*Hz],  g_wq_l[Lz*Hz*Hz];
__device__ __nv_bfloat16 g_wk_h[Lz*Hz*Hz],  g_wk_l[Lz*Hz*Hz];
__device__ __nv_bfloat16 g_wv_h[Lz*Hz*Hz],  g_wv_l[Lz*Hz*Hz];
__device__ __nv_bfloat16 g_wao_h[Lz*Hz*Hz], g_wao_l[Lz*Hz*Hz];
__device__ __nv_bfloat16 g_wi_h[Lz*Hz*FFz], g_wi_l[Lz*Hz*FFz];
__device__ __nv_bfloat16 g_wo_h[Lz*Hz*FFz], g_wo_l[Lz*Hz*FFz];

// ---------------- helpers ----------------
__device__ __forceinline__ void split1(float x, __nv_bfloat16& h, __nv_bfloat16& l) {
    h = __float2bfloat16(x);
    l = __float2bfloat16(x - __bfloat162float(h));
}
__device__ __forceinline__ void split2(float x, float y, uint32_t& hi, uint32_t& lo) {
    __nv_bfloat16 xh, xl, yh, yl;
    split1(x, xh, xl); split1(y, yh, yl);
    hi = (uint32_t)__bfloat16_as_ushort(xh) | ((uint32_t)__bfloat16_as_ushort(yh) << 16);
    lo = (uint32_t)__bfloat16_as_ushort(xl) | ((uint32_t)__bfloat16_as_ushort(yl) << 16);
}

// -------- merged prepass: split 7 tensors in ONE launch, 2 float4/thread --------
struct SplitArgs {
    const float* in[7];
    __nv_bfloat16* h[7];
    __nv_bfloat16* l[7];
    int nblk[7];
};

__global__ __launch_bounds__(256) void split_all_kernel(SplitArgs A)
{
    int b = blockIdx.x;
    int seg = 0;
#pragma unroll
    for (int s = 0; s < 7; s++) {
        if (b < A.nblk[s]) { seg = s; break; }
        b -= A.nblk[s];
    }
    const float4* in = (const float4*)A.in[seg];
    uint2* oh = (uint2*)A.h[seg];
    uint2* ol = (uint2*)A.l[seg];
    const int i0 = b * 512 + threadIdx.x;
    float4 v0 = in[i0];
    float4 v1 = in[i0 + 256];
    uint32_t h01, l01, h23, l23;
    split2(v0.x, v0.y, h01, l01);
    split2(v0.z, v0.w, h23, l23);
    oh[i0] = make_uint2(h01, h23);
    ol[i0] = make_uint2(l01, l23);
    split2(v1.x, v1.y, h01, l01);
    split2(v1.z, v1.w, h23, l23);
    oh[i0 + 256] = make_uint2(h01, h23);
    ol[i0 + 256] = make_uint2(l01, l23);
}

// ===== bf16x3 mma.sync GEMM: BK=32, 3 stages, XOR-swizzled smem, 2 CTAs/SM =====
#define BM 128
#define BN 128
#define BK2 32

#define PLANE 4096
#define STG_ELEMS (4*PLANE)
#define GEMM_SMEM (3*STG_ELEMS*2)

#define ASOFFZ(s,pl,m,c)  ((s)*STG_ELEMS + (pl)*PLANE + (m)*32  + ((((c) ^ (((m)>>1)&3)))<<3))
#define BSOFFZ(s,pl,kk,c) ((s)*STG_ELEMS + 2*PLANE + (pl)*PLANE + (kk)*128 + ((((c) ^ ((kk)&7)))<<3))

struct GemmArgs {
    const __nv_bfloat16 *Ah[4], *Al[4];
    const __nv_bfloat16 *Bh[4], *Bl[4];
    const float* bias[4];
    float* C[4];
    __nv_bfloat16 *Ch[4], *Cl[4];
};

__device__ __forceinline__ void cpa16(void* dst, const void* src) {
    uint32_t d = (uint32_t)__cvta_generic_to_shared(dst);
    asm volatile("cp.async.cg.shared.global [%0], [%1], 16;" :: "r"(d), "l"(src));
}
__device__ __forceinline__ void ldsm4(uint32_t* r, const void* p) {
    uint32_t a = (uint32_t)__cvta_generic_to_shared(p);
    asm volatile("ldmatrix.sync.aligned.m8n8.x4.shared.b16 {%0,%1,%2,%3}, [%4];"
                 : "=r"(r[0]), "=r"(r[1]), "=r"(r[2]), "=r"(r[3]) : "r"(a));
}
__device__ __forceinline__ void ldsm4t(uint32_t* r, const void* p) {
    uint32_t a = (uint32_t)__cvta_generic_to_shared(p);
    asm volatile("ldmatrix.sync.aligned.m8n8.x4.trans.shared.b16 {%0,%1,%2,%3}, [%4];"
                 : "=r"(r[0]), "=r"(r[1]), "=r"(r[2]), "=r"(r[3]) : "r"(a));
}
__device__ __forceinline__ void mma16816(float* c, const uint32_t* a, const uint32_t* b) {
    asm volatile(
        "mma.sync.aligned.m16n8k16.row.col.f32.bf16.bf16.f32 "
        "{%0,%1,%2,%3}, {%4,%5,%6,%7}, {%8,%9}, {%0,%1,%2,%3};"
        : "+f"(c[0]), "+f"(c[1]), "+f"(c[2]), "+f"(c[3])
        : "r"(a[0]), "r"(a[1]), "r"(a[2]), "r"(a[3]), "r"(b[0]), "r"(b[1]));
}

// MODE 0: bias + split bf16 out (QKV). MODE 1: bias + GELU + split bf16 out (FF1).
// MODE 2: fp32 partial out, NO bias (split-K slices; bias folded into LN).
template<int MODE>
__global__ __launch_bounds__(256, 2) void gemm_bf16x3(GemmArgs P, int K_ld, int K_len, int N)
{
    extern __shared__ __align__(16) __nv_bfloat16 sm[];

    const int z = blockIdx.z;
    const __nv_bfloat16* __restrict__ Ah = P.Ah[z];
    const __nv_bfloat16* __restrict__ Al = P.Al[z];
    const __nv_bfloat16* __restrict__ Bh = P.Bh[z];
    const __nv_bfloat16* __restrict__ Bl = P.Bl[z];

    const int n0 = blockIdx.x * BN;
    const int m0 = blockIdx.y * BM;
    const int tid  = threadIdx.x;
    const int lane = tid & 31;
    const int warp = tid >> 5;
    const int warpM = warp >> 2;
    const int warpN = warp & 3;

    const int nT = K_len / BK2;

    auto issue = [&](int t, int s) {
        const int k0 = t * BK2;
#pragma unroll
        for (int p = 0; p < 2; p++) {
            const int idx = tid + p * 256;
            const int ar = idx >> 2, acc_ = idx & 3;
            cpa16(sm + ASOFFZ(s, 0, ar, acc_), Ah + (size_t)(m0 + ar) * K_ld + k0 + acc_ * 8);
            cpa16(sm + ASOFFZ(s, 1, ar, acc_), Al + (size_t)(m0 + ar) * K_ld + k0 + acc_ * 8);
            const int br = idx >> 4, bcc = idx & 15;
            cpa16(sm + BSOFFZ(s, 0, br, bcc), Bh + (size_t)(k0 + br) * N + n0 + bcc * 8);
            cpa16(sm + BSOFFZ(s, 1, br, bcc), Bl + (size_t)(k0 + br) * N + n0 + bcc * 8);
        }
        asm volatile("cp.async.commit_group;" ::: "memory");
    };

    issue(0, 0);
    issue(1, 1);

    float acc[4][4][4] = {};
    int s = 0;

    for (int t = 0; t < nT; t++) {
        if (t + 1 < nT) asm volatile("cp.async.wait_group 1;" ::: "memory");
        else            asm volatile("cp.async.wait_group 0;" ::: "memory");
        __syncthreads();

        if (t + 2 < nT) {
            int s2 = s + 2; if (s2 >= 3) s2 -= 3;
            issue(t + 2, s2);
        }

#pragma unroll
        for (int sub = 0; sub < 2; sub++) {
            uint32_t ah[4][4], al[4][4], bh[4][2], bl[4][2];
            const int cA = sub * 2 + (lane >> 4);
#pragma unroll
            for (int mi = 0; mi < 4; mi++) {
                const int arow = warpM * 64 + mi * 16 + (lane & 15);
                ldsm4(ah[mi], sm + ASOFFZ(s, 0, arow, cA));
                ldsm4(al[mi], sm + ASOFFZ(s, 1, arow, cA));
            }
            const int brow = sub * 16 + (lane & 15);
#pragma unroll
            for (int pr = 0; pr < 2; pr++) {
                const int cB = warpN * 4 + pr * 2 + (lane >> 4);
                uint32_t tmp[4];
                ldsm4t(tmp, sm + BSOFFZ(s, 0, brow, cB));
                bh[pr * 2][0] = tmp[0]; bh[pr * 2][1] = tmp[1];
                bh[pr * 2 + 1][0] = tmp[2]; bh[pr * 2 + 1][1] = tmp[3];
                ldsm4t(tmp, sm + BSOFFZ(s, 1, brow, cB));
                bl[pr * 2][0] = tmp[0]; bl[pr * 2][1] = tmp[1];
                bl[pr * 2 + 1][0] = tmp[2]; bl[pr * 2 + 1][1] = tmp[3];
            }
#pragma unroll
            for (int mi = 0; mi < 4; mi++)
#pragma unroll
                for (int ni = 0; ni < 4; ni++)
                    mma16816(acc[mi][ni], ah[mi], bh[ni]);
#pragma unroll
            for (int mi = 0; mi < 4; mi++)
#pragma unroll
                for (int ni = 0; ni < 4; ni++)
                    mma16816(acc[mi][ni], ah[mi], bl[ni]);
#pragma unroll
            for (int mi = 0; mi < 4; mi++)
#pragma unroll
                for (int ni = 0; ni < 4; ni++)
                    mma16816(acc[mi][ni], al[mi], bh[ni]);
        }
        if (++s == 3) s = 0;
    }

    const float* __restrict__ bias = P.bias[z];
    const int g  = lane >> 2;
    const int tg = lane & 3;
#pragma unroll
    for (int mi = 0; mi < 4; mi++) {
#pragma unroll
        for (int ni = 0; ni < 4; ni++) {
            const int row = m0 + warpM * 64 + mi * 16 + g;
            const int col = n0 + warpN * 32 + ni * 8 + tg * 2;
            float v0 = acc[mi][ni][0];
            float v1 = acc[mi][ni][1];
            float v2 = acc[mi][ni][2];
            float v3 = acc[mi][ni][3];
            if (MODE != 2) {
                const float b0 = bias[col], b1 = bias[col + 1];
                v0 += b0; v1 += b1; v2 += b0; v3 += b1;
            }
            if (MODE == 1) {
                v0 = 0.5f * v0 * (1.0f + erff(v0 * 0.70710678118654752f));
                v1 = 0.5f * v1 * (1.0f + erff(v1 * 0.70710678118654752f));
                v2 = 0.5f * v2 * (1.0f + erff(v2 * 0.70710678118654752f));
                v3 = 0.5f * v3 * (1.0f + erff(v3 * 0.70710678118654752f));
            }
            if (MODE == 2) {
                float* C = P.C[z];
                *(float2*)(C + (size_t)row * N + col)       = make_float2(v0, v1);
                *(float2*)(C + (size_t)(row + 8) * N + col) = make_float2(v2, v3);
            } else {
                __nv_bfloat16* Ch = P.Ch[z];
                __nv_bfloat16* Cl = P.Cl[z];
                uint32_t hw, lw;
                split2(v0, v1, hw, lw);
                *(uint32_t*)(Ch + (size_t)row * N + col) = hw;
                *(uint32_t*)(Cl + (size_t)row * N + col) = lw;
                split2(v2, v3, hw, lw);
                *(uint32_t*)(Ch + (size_t)(row + 8) * N + col) = hw;
                *(uint32_t*)(Cl + (size_t)(row + 8) * N + col) = lw;
            }
        }
    }
}

// ------- tensor-core flash attention (pre-split bf16 operands, fused softmax/P) -------
#define ALD 72   // bf16 tile leading dim (144B rows; conflict-free ldsm)
#define SLD 68   // fp32 S tile leading dim
#define ATT_SMEM (64*SLD*4 + 8*64*ALD*2 + 4*64*4)   // 92160 B

__global__ __launch_bounds__(256, 2) void attention_kernel(
    const __nv_bfloat16* __restrict__ qh_g, const __nv_bfloat16* __restrict__ ql_g,
    const __nv_bfloat16* __restrict__ kh_g, const __nv_bfloat16* __restrict__ kl_g,
    const __nv_bfloat16* __restrict__ vh_g, const __nv_bfloat16* __restrict__ vl_g,
    const float* __restrict__ mask,
    __nv_bfloat16* __restrict__ ctx_h, __nv_bfloat16* __restrict__ ctx_l)
{
    extern __shared__ char smraw[];
    float* Sf = (float*)smraw;
    __nv_bfloat16* Qh = (__nv_bfloat16*)(smraw + 64 * SLD * 4);
    __nv_bfloat16* Ql = Qh + 64 * ALD;
    __nv_bfloat16* Kh = Ql + 64 * ALD;
    __nv_bfloat16* Kl = Kh + 64 * ALD;
    __nv_bfloat16* Vh = Kl + 64 * ALD;
    __nv_bfloat16* Vl = Vh + 64 * ALD;
    __nv_bfloat16* Ph = Vl + 64 * ALD;
    __nv_bfloat16* Pl = Ph + 64 * ALD;
    float* rm = (float*)(Pl + 64 * ALD);
    float* rl = rm + 64;
    float* rs = rl + 64;
    float* am = rs + 64;

    const int tid  = threadIdx.x;
    const int lane = tid & 31;
    const int warp = tid >> 5;
    const int warpM = warp >> 2;
    const int warpN = warp & 3;
    const int g  = lane >> 2;
    const int tg = lane & 3;
    const int bh = blockIdx.y;
    const int b = bh / NHz, h = bh % NHz;
    const int i0 = blockIdx.x * 64;
    const float scale = 0.125f;

    // load Q planes (bf16, 16B vectors)
#pragma unroll
    for (int p = 0; p < 2; p++) {
        const int u = tid + p * 256;
        const int row = u >> 3, c16 = (u & 7) * 8;
        const size_t go = (size_t)(b * Tz + i0 + row) * Hz + h * HDz + c16;
        *(uint4*)&Qh[row * ALD + c16] = *(const uint4*)(qh_g + go);
        *(uint4*)&Ql[row * ALD + c16] = *(const uint4*)(ql_g + go);
    }
    if (tid < 64) { rm[tid] = -1e30f; rl[tid] = 0.0f; }

    float acco[2][2][4] = {};

    for (int jc = 0; jc < Tz / 64; jc++) {
        const int j0 = jc * 64;
        __syncthreads();   // prev chunk's mma done reading K/V/P smem

        // load K, V planes (bf16, 16B vectors)
#pragma unroll
        for (int p = 0; p < 2; p++) {
            const int u = tid + p * 256;
            const int row = u >> 3, c16 = (u & 7) * 8;
            const size_t go = (size_t)(b * Tz + j0 + row) * Hz + h * HDz + c16;
            *(uint4*)&Kh[row * ALD + c16] = *(const uint4*)(kh_g + go);
            *(uint4*)&Kl[row * ALD + c16] = *(const uint4*)(kl_g + go);
            *(uint4*)&Vh[row * ALD + c16] = *(const uint4*)(vh_g + go);
            *(uint4*)&Vl[row * ALD + c16] = *(const uint4*)(vl_g + go);
        }
        if (tid < 64) am[tid] = (1.0f - mask[b * Tz + j0 + tid]) * -10000.0f;
        __syncthreads();

        // S = Q @ K^T via mma (bf16x3)
        float accs[2][2][4] = {};
#pragma unroll
        for (int kk = 0; kk < 4; kk++) {
            const int colk = kk * 16 + (lane >> 4) * 8;
            uint32_t qh[2][4], ql[2][4];
#pragma unroll
            for (int mi = 0; mi < 2; mi++) {
                const int r = warpM * 32 + mi * 16 + (lane & 15);
                ldsm4(qh[mi], &Qh[r * ALD + colk]);
                ldsm4(ql[mi], &Ql[r * ALD + colk]);
            }
            uint32_t kh[2][2], kl[2][2];
            {
                const int r = warpN * 16 + (lane & 15);
                uint32_t t[4];
                ldsm4(t, &Kh[r * ALD + colk]);
                kh[0][0] = t[0]; kh[0][1] = t[2]; kh[1][0] = t[1]; kh[1][1] = t[3];
                ldsm4(t, &Kl[r * ALD + colk]);
                kl[0][0] = t[0]; kl[0][1] = t[2]; kl[1][0] = t[1]; kl[1][1] = t[3];
            }
#pragma unroll
            for (int mi = 0; mi < 2; mi++)
#pragma unroll
                for (int ni = 0; ni < 2; ni++) {
                    mma16816(accs[mi][ni], qh[mi], kh[ni]);
                    mma16816(accs[mi][ni], qh[mi], kl[ni]);
                    mma16816(accs[mi][ni], ql[mi], kh[ni]);
                }
        }
#pragma unroll
        for (int mi = 0; mi < 2; mi++)
#pragma unroll
            for (int ni = 0; ni < 2; ni++) {
                const int row = warpM * 32 + mi * 16 + g;
                const int col = warpN * 16 + ni * 8 + tg * 2;
                Sf[row * SLD + col]           = accs[mi][ni][0] * scale + am[col];
                Sf[row * SLD + col + 1]       = accs[mi][ni][1] * scale + am[col + 1];
                Sf[(row + 8) * SLD + col]     = accs[mi][ni][2] * scale + am[col];
                Sf[(row + 8) * SLD + col + 1] = accs[mi][ni][3] * scale + am[col + 1];
            }
        __syncthreads();

        // fused online softmax + P bf16 conversion (writes Ph/Pl directly)
        {
            const int srow = tid >> 2;
            const int ssub = tid & 3;
            const float* prow = Sf + srow * SLD + ssub * 16;
            const float mo = rm[srow];
            float4 pv[4];
            float cm = -1e30f;
#pragma unroll
            for (int c = 0; c < 4; c++) {
                pv[c] = *(const float4*)&prow[c * 4];
                cm = fmaxf(cm, fmaxf(fmaxf(pv[c].x, pv[c].y), fmaxf(pv[c].z, pv[c].w)));
            }
            cm = fmaxf(cm, __shfl_xor_sync(0xffffffffu, cm, 1));
            cm = fmaxf(cm, __shfl_xor_sync(0xffffffffu, cm, 2));
            const float nm = fmaxf(mo, cm);
            float sum = 0.0f;
            __nv_bfloat16* dh = &Ph[srow * ALD + ssub * 16];
            __nv_bfloat16* dl = &Pl[srow * ALD + ssub * 16];
#pragma unroll
            for (int c = 0; c < 4; c++) {
                pv[c].x = __expf(pv[c].x - nm);
                pv[c].y = __expf(pv[c].y - nm);
                pv[c].z = __expf(pv[c].z - nm);
                pv[c].w = __expf(pv[c].w - nm);
                sum += pv[c].x + pv[c].y + pv[c].z + pv[c].w;
                uint32_t h01, l01, h23, l23;
                split2(pv[c].x, pv[c].y, h01, l01);
                split2(pv[c].z, pv[c].w, h23, l23);
                *(uint2*)&dh[c * 4] = make_uint2(h01, h23);
                *(uint2*)&dl[c * 4] = make_uint2(l01, l23);
            }
            sum += __shfl_xor_sync(0xffffffffu, sum, 1);
            sum += __shfl_xor_sync(0xffffffffu, sum, 2);
            if (ssub == 0) {
                const float sc = __expf(mo - nm);
                rl[srow] = rl[srow] * sc + sum;
                rm[srow] = nm;
                rs[srow] = sc;
            }
        }
        __syncthreads();

        // rescale output accumulators
#pragma unroll
        for (int mi = 0; mi < 2; mi++) {
            const int r1 = warpM * 32 + mi * 16 + g;
            const float s1 = rs[r1], s2 = rs[r1 + 8];
#pragma unroll
            for (int ni = 0; ni < 2; ni++) {
                acco[mi][ni][0] *= s1; acco[mi][ni][1] *= s1;
                acco[mi][ni][2] *= s2; acco[mi][ni][3] *= s2;
            }
        }

        // O += P @ V via mma (bf16x3)
#pragma unroll
        for (int kk = 0; kk < 4; kk++) {
            const int colk = kk * 16 + (lane >> 4) * 8;
            uint32_t ph[2][4], pl[2][4];
#pragma unroll
            for (int mi = 0; mi < 2; mi++) {
                const int r = warpM * 32 + mi * 16 + (lane & 15);
                ldsm4(ph[mi], &Ph[r * ALD + colk]);
                ldsm4(pl[mi], &Pl[r * ALD + colk]);
            }
            uint32_t vh[2][2], vl[2][2];
            {
                const int r = kk * 16 + (lane & 15);
                const int c = warpN * 16 + (lane >> 4) * 8;
                uint32_t t[4];
                ldsm4t(t, &Vh[r * ALD + c]);
                vh[0][0] = t[0]; vh[0][1] = t[1]; vh[1][0] = t[2]; vh[1][1] = t[3];
                ldsm4t(t, &Vl[r * ALD + c]);
                vl[0][0] = t[0]; vl[0][1] = t[1]; vl[1][0] = t[2]; vl[1][1] = t[3];
            }
#pragma unroll
            for (int mi = 0; mi < 2; mi++)
#pragma unroll
                for (int ni = 0; ni < 2; ni++) {
                    mma16816(acco[mi][ni], ph[mi], vh[ni]);
                    mma16816(acco[mi][ni], pl[mi], vh[ni]);
                    mma16816(acco[mi][ni], ph[mi], vl[ni]);
                }
        }
    }

#pragma unroll
    for (int mi = 0; mi < 2; mi++) {
        const int row = warpM * 32 + mi * 16 + g;
        const float inv1 = 1.0f / rl[row];
        const float inv2 = 1.0f / rl[row + 8];
#pragma unroll
        for (int ni = 0; ni < 2; ni++) {
            const int col = warpN * 16 + ni * 8 + tg * 2;
            size_t off = (size_t)(b * Tz + i0 + row) * Hz + h * HDz + col;
            uint32_t hw, lw;
            split2(acco[mi][ni][0] * inv1, acco[mi][ni][1] * inv1, hw, lw);
            *(uint32_t*)(ctx_h + off) = hw;
            *(uint32_t*)(ctx_l + off) = lw;
            off = (size_t)(b * Tz + i0 + row + 8) * Hz + h * HDz + col;
            split2(acco[mi][ni][2] * inv2, acco[mi][ni][3] * inv2, hw, lw);
            *(uint32_t*)(ctx_h + off) = hw;
            *(uint32_t*)(ctx_l + off) = lw;
        }
    }
}

// ---- register-resident LayerNorm: 1 float4/thread, fused sum/sumsq reduction ----
template<int NP>
__global__ __launch_bounds__(256) void ln_kernel(
    const float* __restrict__ p0, const float* __restrict__ p1,
    const float* __restrict__ p2, const float* __restrict__ p3,
    const float* __restrict__ gb, const float* __restrict__ res,
    const float* __restrict__ g, const float* __restrict__ bb,
    float* __restrict__ out,
    __nv_bfloat16* __restrict__ oh, __nv_bfloat16* __restrict__ ol)
{
    __shared__ float2 red2[8];
    const int row = blockIdx.x;
    const size_t ro = (size_t)row * Hz;
    const int i4 = threadIdx.x * 4;
    const int lane = threadIdx.x & 31, w = threadIdx.x >> 5;

    float4 xv = make_float4(0.f, 0.f, 0.f, 0.f);
    if (i4 < Hz) {
        float4 a0 = *(const float4*)(p0 + ro + i4);
        float4 a1 = *(const float4*)(p1 + ro + i4);
        float4 rr = *(const float4*)(res + ro + i4);
        float4 gg = *(const float4*)(gb + i4);
        xv.x = a0.x + a1.x + rr.x + gg.x;
        xv.y = a0.y + a1.y + rr.y + gg.y;
        xv.z = a0.z + a1.z + rr.z + gg.z;
        xv.w = a0.w + a1.w + rr.w + gg.w;
        if (NP >= 3) {
            float4 a2 = *(const float4*)(p2 + ro + i4);
            xv.x += a2.x; xv.y += a2.y; xv.z += a2.z; xv.w += a2.w;
        }
        if (NP >= 4) {
            float4 a3 = *(const float4*)(p3 + ro + i4);
            xv.x += a3.x; xv.y += a3.y; xv.z += a3.z; xv.w += a3.w;
        }
    }
    float s  = xv.x + xv.y + xv.z + xv.w;
    float sq = xv.x * xv.x + xv.y * xv.y + xv.z * xv.z + xv.w * xv.w;
#pragma unroll
    for (int o = 16; o > 0; o >>= 1) {
        s  += __shfl_down_sync(0xffffffffu, s, o);
        sq += __shfl_down_sync(0xffffffffu, sq, o);
    }
    if (lane == 0) red2[w] = make_float2(s, sq);
    __syncthreads();
    if (w == 0) {
        float2 t = (lane < 8) ? red2[lane] : make_float2(0.f, 0.f);
#pragma unroll
        for (int o = 4; o > 0; o >>= 1) {
            t.x += __shfl_down_sync(0xffffffffu, t.x, o);
            t.y += __shfl_down_sync(0xffffffffu, t.y, o);
        }
        if (lane == 0) red2[0] = t;
    }
    __syncthreads();
    const float mean = red2[0].x * (1.0f / Hz);
    const float var  = red2[0].y * (1.0f / Hz) - mean * mean;
    const float rstd = rsqrtf(var + 1e-12f);

    if (i4 < Hz) {
        float4 gv = *(const float4*)(g + i4);
        float4 bv = *(const float4*)(bb + i4);
        float4 y;
        y.x = (xv.x - mean) * rstd * gv.x + bv.x;
        y.y = (xv.y - mean) * rstd * gv.y + bv.y;
        y.z = (xv.z - mean) * rstd * gv.z + bv.z;
        y.w = (xv.w - mean) * rstd * gv.w + bv.w;
        *(float4*)(out + ro + i4) = y;
        uint32_t h01, l01, h23, l23;
        split2(y.x, y.y, h01, l01);
        split2(y.z, y.w, h23, l23);
        *(uint2*)(oh + ro + i4) = make_uint2(h01, h23);
        *(uint2*)(ol + ro + i4) = make_uint2(l01, l23);
    }
}

// ---------------- launch ----------------
extern "C" void kernel_launch(void* const* d_in, const int* in_sizes, int n_in,
                              void* d_out, int out_size)
{
    const float* hidden = (const float*)d_in[0];
    const float* mask   = (const float*)d_in[1];
    const float* Wq  = (const float*)d_in[2];   const float* bq  = (const float*)d_in[3];
    const float* Wk  = (const float*)d_in[4];   const float* bk  = (const float*)d_in[5];
    const float* Wv  = (const float*)d_in[6];   const float* bv  = (const float*)d_in[7];
    const float* Wao = (const float*)d_in[8];   const float* bao = (const float*)d_in[9];
    const float* g1  = (const float*)d_in[10];  const float* b1  = (const float*)d_in[11];
    const float* Wi  = (const float*)d_in[12];  const float* bi  = (const float*)d_in[13];
    const float* Wo  = (const float*)d_in[14];  const float* bo  = (const float*)d_in[15];
    const float* g2  = (const float*)d_in[16];  const float* b2  = (const float*)d_in[17];
    float* out = (float*)d_out;

    float *p0, *p1, *p2, *p3, *attn, *xb;
    cudaGetSymbolAddress((void**)&p0, g_p0);
    cudaGetSymbolAddress((void**)&p1, g_p1);
    cudaGetSymbolAddress((void**)&p2, g_p2);
    cudaGetSymbolAddress((void**)&p3, g_p3);
    cudaGetSymbolAddress((void**)&attn, g_attn);
    cudaGetSymbolAddress((void**)&xb, g_x);

    __nv_bfloat16 *qh, *ql, *kh, *kl, *vh, *vl;
    cudaGetSymbolAddress((void**)&qh, g_qh); cudaGetSymbolAddress((void**)&ql, g_ql);
    cudaGetSymbolAddress((void**)&kh, g_kh); cudaGetSymbolAddress((void**)&kl, g_kl);
    cudaGetSymbolAddress((void**)&vh, g_vh); cudaGetSymbolAddress((void**)&vl, g_vl);

    __nv_bfloat16 *xh, *xl, *ath, *atl, *cth, *ctl, *ffh, *ffl;
    cudaGetSymbolAddress((void**)&xh,  g_x_h);    cudaGetSymbolAddress((void**)&xl,  g_x_l);
    cudaGetSymbolAddress((void**)&ath, g_attn_h); cudaGetSymbolAddress((void**)&atl, g_attn_l);
    cudaGetSymbolAddress((void**)&cth, g_ctx_h);  cudaGetSymbolAddress((void**)&ctl, g_ctx_l);
    cudaGetSymbolAddress((void**)&ffh, g_ff_h);   cudaGetSymbolAddress((void**)&ffl, g_ff_l);

    __nv_bfloat16 *wqh, *wql, *wkh, *wkl, *wvh, *wvl, *waoh, *waol, *wih, *wil, *woh, *wol;
    cudaGetSymbolAddress((void**)&wqh,  g_wq_h);  cudaGetSymbolAddress((void**)&wql,  g_wq_l);
    cudaGetSymbolAddress((void**)&wkh,  g_wk_h);  cudaGetSymbolAddress((void**)&wkl,  g_wk_l);
    cudaGetSymbolAddress((void**)&wvh,  g_wv_h);  cudaGetSymbolAddress((void**)&wvl,  g_wv_l);
    cudaGetSymbolAddress((void**)&waoh, g_wao_h); cudaGetSymbolAddress((void**)&waol, g_wao_l);
    cudaGetSymbolAddress((void**)&wih,  g_wi_h);  cudaGetSymbolAddress((void**)&wil,  g_wi_l);
    cudaGetSymbolAddress((void**)&woh,  g_wo_h);  cudaGetSymbolAddress((void**)&wol,  g_wo_l);

    // merged prepass: ONE launch splits all weights + input (512 float4/block)
    {
        const int nHH = Lz * Hz * Hz, nHF = Lz * Hz * FFz, nX = Mz * Hz;
        SplitArgs A;
        A.in[0] = Wq;  A.h[0] = wqh;  A.l[0] = wql;  A.nblk[0] = nHH / 2048;
        A.in[1] = Wk;  A.h[1] = wkh;  A.l[1] = wkl;  A.nblk[1] = nHH / 2048;
        A.in[2] = Wv;  A.h[2] = wvh;  A.l[2] = wvl;  A.nblk[2] = nHH / 2048;
        A.in[3] = Wao; A.h[3] = waoh; A.l[3] = waol; A.nblk[3] = nHH / 2048;
        A.in[4] = Wi;  A.h[4] = wih;  A.l[4] = wil;  A.nblk[4] = nHF / 2048;
        A.in[5] = Wo;  A.h[5] = woh;  A.l[5] = wol;  A.nblk[5] = nHF / 2048;
        A.in[6] = hidden; A.h[6] = xh; A.l[6] = xl;  A.nblk[6] = nX / 2048;
        int total = 4 * (nHH / 2048) + 2 * (nHF / 2048) + nX / 2048;
        split_all_kernel<<<total, 256>>>(A);
    }

    cudaFuncSetAttribute(attention_kernel,
                         cudaFuncAttributeMaxDynamicSharedMemorySize, ATT_SMEM);
    cudaFuncSetAttribute(gemm_bf16x3<0>,
                         cudaFuncAttributeMaxDynamicSharedMemorySize, GEMM_SMEM);
    cudaFuncSetAttribute(gemm_bf16x3<1>,
                         cudaFuncAttributeMaxDynamicSharedMemorySize, GEMM_SMEM);
    cudaFuncSetAttribute(gemm_bf16x3<2>,
                         cudaFuncAttributeMaxDynamicSharedMemorySize, GEMM_SMEM);

    dim3 gAtt(Tz / 64, Bz * NHz);

    for (int l = 0; l < Lz; l++) {
        const float* xres = (l == 0) ? hidden : xb;
        const size_t oHH = (size_t)l * Hz * Hz;
        const size_t oHF = (size_t)l * Hz * FFz;
        const size_t oH  = (size_t)l * Hz;
        const size_t oF  = (size_t)l * FFz;

        {   // fused QKV -> split bf16 q/k/v directly
            GemmArgs P = {};
            P.Ah[0] = P.Ah[1] = P.Ah[2] = xh;
            P.Al[0] = P.Al[1] = P.Al[2] = xl;
            P.Bh[0] = wqh + oHH; P.Bl[0] = wql + oHH;
            P.Bh[1] = wkh + oHH; P.Bl[1] = wkl + oHH;
            P.Bh[2] = wvh + oHH; P.Bl[2] = wvl + oHH;
            P.bias[0] = bq + oH; P.bias[1] = bk + oH; P.bias[2] = bv + oH;
            P.Ch[0] = qh; P.Cl[0] = ql;
            P.Ch[1] = kh; P.Cl[1] = kl;
            P.Ch[2] = vh; P.Cl[2] = vl;
            gemm_bf16x3<0><<<dim3(Hz / BN, Mz / BM, 3), 256, GEMM_SMEM>>>(P, Hz, Hz, Hz);
        }

        attention_kernel<<<gAtt, 256, ATT_SMEM>>>(qh, ql, kh, kl, vh, vl, mask, cth, ctl);

        {   // AO projection: split-K x3
            GemmArgs P = {};
#pragma unroll
            for (int sK = 0; sK < 3; sK++) {
                P.Ah[sK] = cth + sK * 256;
                P.Al[sK] = ctl + sK * 256;
                P.Bh[sK] = waoh + oHH + (size_t)sK * 256 * Hz;
                P.Bl[sK] = waol + oHH + (size_t)sK * 256 * Hz;
            }
            P.C[0] = p0; P.C[1] = p1; P.C[2] = p2;
            gemm_bf16x3<2><<<dim3(Hz / BN, Mz / BM, 3), 256, GEMM_SMEM>>>(P, Hz, 256, Hz);
        }
        ln_kernel<3><<<Mz, 256>>>(p0, p1, p2, p3, bao + oH, xres, g1 + oH, b1 + oH,
                                  attn, ath, atl);

        {   // FF1 + GELU
            GemmArgs P = {};
            P.Ah[0] = ath; P.Al[0] = atl;
            P.Bh[0] = wih + oHF; P.Bl[0] = wil + oHF;
            P.bias[0] = bi + oF;
            P.Ch[0] = ffh; P.Cl[0] = ffl;
            gemm_bf16x3<1><<<dim3(FFz / BN, Mz / BM, 1), 256, GEMM_SMEM>>>(P, Hz, Hz, FFz);
        }
        {   // FF2: split-K x4
            GemmArgs P = {};
#pragma unroll
            for (int sK = 0; sK < 4; sK++) {
                P.Ah[sK] = ffh + sK * 768;
                P.Al[sK] = ffl + sK * 768;
                P.Bh[sK] = woh + oHF + (size_t)sK * 768 * Hz;
                P.Bl[sK] = wol + oHF + (size_t)sK * 768 * Hz;
            }
            P.C[0] = p0; P.C[1] = p1; P.C[2] = p2; P.C[3] = p3;
            gemm_bf16x3<2><<<dim3(Hz / BN, Mz / BM, 4), 256, GEMM_SMEM>>>(P, FFz, 768, Hz);
        }
        ln_kernel<4><<<Mz, 256>>>(p0, p1, p2, p3, bo + oH, attn, g2 + oH, b2 + oH,
                                  (l == Lz - 1) ? out : xb, xh, xl);
    }
}

// round 15
// speedup vs baseline: 1.3974x; 1.0093x over previous
#include <cuda_runtime.h>
#include <cuda_bf16.h>
#include <math.h>
#include <stdint.h>

#define Bz  8
#define Tz  512
#define Hz  768
#define NHz 12
#define HDz 64
#define FFz 3072
#define Lz  12
#define Mz  (Bz*Tz)   // 4096

// ---------------- fp32 scratch ----------------
__device__ float g_p0[Mz*Hz];
__device__ float g_p1[Mz*Hz];
__device__ float g_p2[Mz*Hz];
__device__ float g_p3[Mz*Hz];
__device__ float g_attn[Mz*Hz];
__device__ float g_x[Mz*Hz];

// ---------------- split (hi/lo bf16) activation scratch ----------------
__device__ __nv_bfloat16 g_qh[Mz*Hz], g_ql[Mz*Hz];
__device__ __nv_bfloat16 g_kh[Mz*Hz], g_kl[Mz*Hz];
__device__ __nv_bfloat16 g_vh[Mz*Hz], g_vl[Mz*Hz];
__device__ __nv_bfloat16 g_x_h[Mz*Hz],    g_x_l[Mz*Hz];
__device__ __nv_bfloat16 g_attn_h[Mz*Hz], g_attn_l[Mz*Hz];
__device__ __nv_bfloat16 g_ctx_h[Mz*Hz],  g_ctx_l[Mz*Hz];
__device__ __nv_bfloat16 g_ff_h[Mz*FFz],  g_ff_l[Mz*FFz];

// ---------------- split weight storage ([L][K][N], hi/lo) ----------------
__device__ __nv_bfloat16 g_wq_h[Lz*Hz*Hz],  g_wq_l[Lz*Hz*Hz];
__device__ __nv_bfloat16 g_wk_h[Lz*Hz*Hz],  g_wk_l[Lz*Hz*Hz];
__device__ __nv_bfloat16 g_wv_h[Lz*Hz*Hz],  g_wv_l[Lz*Hz*Hz];
__device__ __nv_bfloat16 g_wao_h[Lz*Hz*Hz], g_wao_l[Lz*Hz*Hz];
__device__ __nv_bfloat16 g_wi_h[Lz*Hz*FFz], g_wi_l[Lz*Hz*FFz];
__device__ __nv_bfloat16 g_wo_h[Lz*Hz*FFz], g_wo_l[Lz*Hz*FFz];

// ---------------- helpers ----------------
__device__ __forceinline__ void split1(float x, __nv_bfloat16& h, __nv_bfloat16& l) {
    h = __float2bfloat16(x);
    l = __float2bfloat16(x - __bfloat162float(h));
}
__device__ __forceinline__ void split2(float x, float y, uint32_t& hi, uint32_t& lo) {
    __nv_bfloat16 xh, xl, yh, yl;
    split1(x, xh, xl); split1(y, yh, yl);
    hi = (uint32_t)__bfloat16_as_ushort(xh) | ((uint32_t)__bfloat16_as_ushort(yh) << 16);
    lo = (uint32_t)__bfloat16_as_ushort(xl) | ((uint32_t)__bfloat16_as_ushort(yl) << 16);
}

// -------- merged prepass: split 7 tensors in ONE launch, 2 float4/thread --------
struct SplitArgs {
    const float* in[7];
    __nv_bfloat16* h[7];
    __nv_bfloat16* l[7];
    int nblk[7];
};

__global__ __launch_bounds__(256) void split_all_kernel(SplitArgs A)
{
    int b = blockIdx.x;
    int seg = 0;
#pragma unroll
    for (int s = 0; s < 7; s++) {
        if (b < A.nblk[s]) { seg = s; break; }
        b -= A.nblk[s];
    }
    const float4* in = (const float4*)A.in[seg];
    uint2* oh = (uint2*)A.h[seg];
    uint2* ol = (uint2*)A.l[seg];
    const int i0 = b * 512 + threadIdx.x;
    float4 v0 = in[i0];
    float4 v1 = in[i0 + 256];
    uint32_t h01, l01, h23, l23;
    split2(v0.x, v0.y, h01, l01);
    split2(v0.z, v0.w, h23, l23);
    oh[i0] = make_uint2(h01, h23);
    ol[i0] = make_uint2(l01, l23);
    split2(v1.x, v1.y, h01, l01);
    split2(v1.z, v1.w, h23, l23);
    oh[i0 + 256] = make_uint2(h01, h23);
    ol[i0 + 256] = make_uint2(l01, l23);
}

// ===== bf16x3 mma.sync GEMM: BK=32, 3 stages, XOR-swizzled smem, 2 CTAs/SM =====
#define BM 128
#define BN 128
#define BK2 32

#define PLANE 4096
#define STG_ELEMS (4*PLANE)
#define GEMM_SMEM (3*STG_ELEMS*2)

#define ASOFFZ(s,pl,m,c)  ((s)*STG_ELEMS + (pl)*PLANE + (m)*32  + ((((c) ^ (((m)>>1)&3)))<<3))
#define BSOFFZ(s,pl,kk,c) ((s)*STG_ELEMS + 2*PLANE + (pl)*PLANE + (kk)*128 + ((((c) ^ ((kk)&7)))<<3))

struct GemmArgs {
    const __nv_bfloat16 *Ah[4], *Al[4];
    const __nv_bfloat16 *Bh[4], *Bl[4];
    const float* bias[4];
    float* C[4];
    __nv_bfloat16 *Ch[4], *Cl[4];
};

__device__ __forceinline__ void cpa16(void* dst, const void* src) {
    uint32_t d = (uint32_t)__cvta_generic_to_shared(dst);
    asm volatile("cp.async.cg.shared.global [%0], [%1], 16;" :: "r"(d), "l"(src));
}
__device__ __forceinline__ void ldsm4(uint32_t* r, const void* p) {
    uint32_t a = (uint32_t)__cvta_generic_to_shared(p);
    asm volatile("ldmatrix.sync.aligned.m8n8.x4.shared.b16 {%0,%1,%2,%3}, [%4];"
                 : "=r"(r[0]), "=r"(r[1]), "=r"(r[2]), "=r"(r[3]) : "r"(a));
}
__device__ __forceinline__ void ldsm4t(uint32_t* r, const void* p) {
    uint32_t a = (uint32_t)__cvta_generic_to_shared(p);
    asm volatile("ldmatrix.sync.aligned.m8n8.x4.trans.shared.b16 {%0,%1,%2,%3}, [%4];"
                 : "=r"(r[0]), "=r"(r[1]), "=r"(r[2]), "=r"(r[3]) : "r"(a));
}
__device__ __forceinline__ void mma16816(float* c, const uint32_t* a, const uint32_t* b) {
    asm volatile(
        "mma.sync.aligned.m16n8k16.row.col.f32.bf16.bf16.f32 "
        "{%0,%1,%2,%3}, {%4,%5,%6,%7}, {%8,%9}, {%0,%1,%2,%3};"
        : "+f"(c[0]), "+f"(c[1]), "+f"(c[2]), "+f"(c[3])
        : "r"(a[0]), "r"(a[1]), "r"(a[2]), "r"(a[3]), "r"(b[0]), "r"(b[1]));
}

// MODE 0: bias + split bf16 out (QKV). MODE 1: bias + GELU + split bf16 out (FF1).
// MODE 2: fp32 partial out, NO bias (split-K slices; bias folded into LN).
template<int MODE>
__global__ __launch_bounds__(256, 2) void gemm_bf16x3(GemmArgs P, int K_ld, int K_len, int N)
{
    extern __shared__ __align__(16) __nv_bfloat16 sm[];

    const int z = blockIdx.z;
    const __nv_bfloat16* __restrict__ Ah = P.Ah[z];
    const __nv_bfloat16* __restrict__ Al = P.Al[z];
    const __nv_bfloat16* __restrict__ Bh = P.Bh[z];
    const __nv_bfloat16* __restrict__ Bl = P.Bl[z];

    const int n0 = blockIdx.x * BN;
    const int m0 = blockIdx.y * BM;
    const int tid  = threadIdx.x;
    const int lane = tid & 31;
    const int warp = tid >> 5;
    const int warpM = warp >> 2;
    const int warpN = warp & 3;

    const int nT = K_len / BK2;

    auto issue = [&](int t, int s) {
        const int k0 = t * BK2;
#pragma unroll
        for (int p = 0; p < 2; p++) {
            const int idx = tid + p * 256;
            const int ar = idx >> 2, acc_ = idx & 3;
            cpa16(sm + ASOFFZ(s, 0, ar, acc_), Ah + (size_t)(m0 + ar) * K_ld + k0 + acc_ * 8);
            cpa16(sm + ASOFFZ(s, 1, ar, acc_), Al + (size_t)(m0 + ar) * K_ld + k0 + acc_ * 8);
            const int br = idx >> 4, bcc = idx & 15;
            cpa16(sm + BSOFFZ(s, 0, br, bcc), Bh + (size_t)(k0 + br) * N + n0 + bcc * 8);
            cpa16(sm + BSOFFZ(s, 1, br, bcc), Bl + (size_t)(k0 + br) * N + n0 + bcc * 8);
        }
        asm volatile("cp.async.commit_group;" ::: "memory");
    };

    issue(0, 0);
    issue(1, 1);

    float acc[4][4][4] = {};
    int s = 0;

    for (int t = 0; t < nT; t++) {
        if (t + 1 < nT) asm volatile("cp.async.wait_group 1;" ::: "memory");
        else            asm volatile("cp.async.wait_group 0;" ::: "memory");
        __syncthreads();

        if (t + 2 < nT) {
            int s2 = s + 2; if (s2 >= 3) s2 -= 3;
            issue(t + 2, s2);
        }

#pragma unroll
        for (int sub = 0; sub < 2; sub++) {
            uint32_t ah[4][4], al[4][4], bh[4][2], bl[4][2];
            const int cA = sub * 2 + (lane >> 4);
#pragma unroll
            for (int mi = 0; mi < 4; mi++) {
                const int arow = warpM * 64 + mi * 16 + (lane & 15);
                ldsm4(ah[mi], sm + ASOFFZ(s, 0, arow, cA));
                ldsm4(al[mi], sm + ASOFFZ(s, 1, arow, cA));
            }
            const int brow = sub * 16 + (lane & 15);
#pragma unroll
            for (int pr = 0; pr < 2; pr++) {
                const int cB = warpN * 4 + pr * 2 + (lane >> 4);
                uint32_t tmp[4];
                ldsm4t(tmp, sm + BSOFFZ(s, 0, brow, cB));
                bh[pr * 2][0] = tmp[0]; bh[pr * 2][1] = tmp[1];
                bh[pr * 2 + 1][0] = tmp[2]; bh[pr * 2 + 1][1] = tmp[3];
                ldsm4t(tmp, sm + BSOFFZ(s, 1, brow, cB));
                bl[pr * 2][0] = tmp[0]; bl[pr * 2][1] = tmp[1];
                bl[pr * 2 + 1][0] = tmp[2]; bl[pr * 2 + 1][1] = tmp[3];
            }
#pragma unroll
            for (int mi = 0; mi < 4; mi++)
#pragma unroll
                for (int ni = 0; ni < 4; ni++)
                    mma16816(acc[mi][ni], ah[mi], bh[ni]);
#pragma unroll
            for (int mi = 0; mi < 4; mi++)
#pragma unroll
                for (int ni = 0; ni < 4; ni++)
                    mma16816(acc[mi][ni], ah[mi], bl[ni]);
#pragma unroll
            for (int mi = 0; mi < 4; mi++)
#pragma unroll
                for (int ni = 0; ni < 4; ni++)
                    mma16816(acc[mi][ni], al[mi], bh[ni]);
        }
        if (++s == 3) s = 0;
    }

    const float* __restrict__ bias = P.bias[z];
    const int g  = lane >> 2;
    const int tg = lane & 3;
#pragma unroll
    for (int mi = 0; mi < 4; mi++) {
#pragma unroll
        for (int ni = 0; ni < 4; ni++) {
            const int row = m0 + warpM * 64 + mi * 16 + g;
            const int col = n0 + warpN * 32 + ni * 8 + tg * 2;
            float v0 = acc[mi][ni][0];
            float v1 = acc[mi][ni][1];
            float v2 = acc[mi][ni][2];
            float v3 = acc[mi][ni][3];
            if (MODE != 2) {
                const float b0 = bias[col], b1 = bias[col + 1];
                v0 += b0; v1 += b1; v2 += b0; v3 += b1;
            }
            if (MODE == 1) {
                v0 = 0.5f * v0 * (1.0f + erff(v0 * 0.70710678118654752f));
                v1 = 0.5f * v1 * (1.0f + erff(v1 * 0.70710678118654752f));
                v2 = 0.5f * v2 * (1.0f + erff(v2 * 0.70710678118654752f));
                v3 = 0.5f * v3 * (1.0f + erff(v3 * 0.70710678118654752f));
            }
            if (MODE == 2) {
                float* C = P.C[z];
                *(float2*)(C + (size_t)row * N + col)       = make_float2(v0, v1);
                *(float2*)(C + (size_t)(row + 8) * N + col) = make_float2(v2, v3);
            } else {
                __nv_bfloat16* Ch = P.Ch[z];
                __nv_bfloat16* Cl = P.Cl[z];
                uint32_t hw, lw;
                split2(v0, v1, hw, lw);
                *(uint32_t*)(Ch + (size_t)row * N + col) = hw;
                *(uint32_t*)(Cl + (size_t)row * N + col) = lw;
                split2(v2, v3, hw, lw);
                *(uint32_t*)(Ch + (size_t)(row + 8) * N + col) = hw;
                *(uint32_t*)(Cl + (size_t)(row + 8) * N + col) = lw;
            }
        }
    }
}

// ------- tensor-core flash attention: fragment-resident softmax, 3 CTAs/SM -------
#define ALD 72   // bf16 tile leading dim (144B rows; conflict-free ldsm)
#define ATT_SMEM (8*64*ALD*2 + (64 + 256 + 256)*4)   // 76032 B

__global__ __launch_bounds__(256, 3) void attention_kernel(
    const __nv_bfloat16* __restrict__ qh_g, const __nv_bfloat16* __restrict__ ql_g,
    const __nv_bfloat16* __restrict__ kh_g, const __nv_bfloat16* __restrict__ kl_g,
    const __nv_bfloat16* __restrict__ vh_g, const __nv_bfloat16* __restrict__ vl_g,
    const float* __restrict__ mask,
    __nv_bfloat16* __restrict__ ctx_h, __nv_bfloat16* __restrict__ ctx_l)
{
    extern __shared__ char smraw[];
    __nv_bfloat16* Qh = (__nv_bfloat16*)smraw;
    __nv_bfloat16* Ql = Qh + 64 * ALD;
    __nv_bfloat16* Kh = Ql + 64 * ALD;
    __nv_bfloat16* Kl = Kh + 64 * ALD;
    __nv_bfloat16* Vh = Kl + 64 * ALD;
    __nv_bfloat16* Vl = Vh + 64 * ALD;
    __nv_bfloat16* Ph = Vl + 64 * ALD;
    __nv_bfloat16* Pl = Ph + 64 * ALD;
    float* am   = (float*)(Pl + 64 * ALD);
    float* wmax = am + 64;     // [64][4]
    float* wsum = wmax + 256;  // [64][4]

    const int tid  = threadIdx.x;
    const int lane = tid & 31;
    const int warp = tid >> 5;
    const int warpM = warp >> 2;
    const int warpN = warp & 3;
    const int g  = lane >> 2;
    const int tg = lane & 3;
    const int bh = blockIdx.y;
    const int b = bh / NHz, h = bh % NHz;
    const int i0 = blockIdx.x * 64;
    const float scale = 0.125f;

    // load Q planes (bf16, 16B vectors)
#pragma unroll
    for (int p = 0; p < 2; p++) {
        const int u = tid + p * 256;
        const int row = u >> 3, c16 = (u & 7) * 8;
        const size_t go = (size_t)(b * Tz + i0 + row) * Hz + h * HDz + c16;
        *(uint4*)&Qh[row * ALD + c16] = *(const uint4*)(qh_g + go);
        *(uint4*)&Ql[row * ALD + c16] = *(const uint4*)(ql_g + go);
    }

    // thread-local online softmax state: rows warpM*32 + g + 8*i  (i = mi*2 + half)
    float rm_loc[4], rl_loc[4];
#pragma unroll
    for (int i = 0; i < 4; i++) { rm_loc[i] = -1e30f; rl_loc[i] = 0.0f; }

    float acco[2][2][4] = {};

    for (int jc = 0; jc < Tz / 64; jc++) {
        const int j0 = jc * 64;
        __syncthreads();   // prev chunk's mma done reading K/V/P smem

        // load K, V planes
#pragma unroll
        for (int p = 0; p < 2; p++) {
            const int u = tid + p * 256;
            const int row = u >> 3, c16 = (u & 7) * 8;
            const size_t go = (size_t)(b * Tz + j0 + row) * Hz + h * HDz + c16;
            *(uint4*)&Kh[row * ALD + c16] = *(const uint4*)(kh_g + go);
            *(uint4*)&Kl[row * ALD + c16] = *(const uint4*)(kl_g + go);
            *(uint4*)&Vh[row * ALD + c16] = *(const uint4*)(vh_g + go);
            *(uint4*)&Vl[row * ALD + c16] = *(const uint4*)(vl_g + go);
        }
        if (tid < 64) am[tid] = (1.0f - mask[b * Tz + j0 + tid]) * -10000.0f;
        __syncthreads();

        // S = Q @ K^T via mma (bf16x3)
        float accs[2][2][4] = {};
#pragma unroll
        for (int kk = 0; kk < 4; kk++) {
            const int colk = kk * 16 + (lane >> 4) * 8;
            uint32_t qh[2][4], ql[2][4];
#pragma unroll
            for (int mi = 0; mi < 2; mi++) {
                const int r = warpM * 32 + mi * 16 + (lane & 15);
                ldsm4(qh[mi], &Qh[r * ALD + colk]);
                ldsm4(ql[mi], &Ql[r * ALD + colk]);
            }
            uint32_t kh[2][2], kl[2][2];
            {
                const int r = warpN * 16 + (lane & 15);
                uint32_t t[4];
                ldsm4(t, &Kh[r * ALD + colk]);
                kh[0][0] = t[0]; kh[0][1] = t[2]; kh[1][0] = t[1]; kh[1][1] = t[3];
                ldsm4(t, &Kl[r * ALD + colk]);
                kl[0][0] = t[0]; kl[0][1] = t[2]; kl[1][0] = t[1]; kl[1][1] = t[3];
            }
#pragma unroll
            for (int mi = 0; mi < 2; mi++)
#pragma unroll
                for (int ni = 0; ni < 2; ni++) {
                    mma16816(accs[mi][ni], qh[mi], kh[ni]);
                    mma16816(accs[mi][ni], qh[mi], kl[ni]);
                    mma16816(accs[mi][ni], ql[mi], kh[ni]);
                }
        }

        // scale + mask in fragments; per-row chunk max (4 tg lanes per row)
        float cmax[4];
#pragma unroll
        for (int i = 0; i < 4; i++) cmax[i] = -1e30f;
#pragma unroll
        for (int mi = 0; mi < 2; mi++)
#pragma unroll
            for (int ni = 0; ni < 2; ni++) {
                const int col = warpN * 16 + ni * 8 + tg * 2;
                const float m0v = am[col], m1v = am[col + 1];
                accs[mi][ni][0] = accs[mi][ni][0] * scale + m0v;
                accs[mi][ni][1] = accs[mi][ni][1] * scale + m1v;
                accs[mi][ni][2] = accs[mi][ni][2] * scale + m0v;
                accs[mi][ni][3] = accs[mi][ni][3] * scale + m1v;
                cmax[mi * 2]     = fmaxf(cmax[mi * 2],     fmaxf(accs[mi][ni][0], accs[mi][ni][1]));
                cmax[mi * 2 + 1] = fmaxf(cmax[mi * 2 + 1], fmaxf(accs[mi][ni][2], accs[mi][ni][3]));
            }
#pragma unroll
        for (int i = 0; i < 4; i++) {
            cmax[i] = fmaxf(cmax[i], __shfl_xor_sync(0xffffffffu, cmax[i], 1));
            cmax[i] = fmaxf(cmax[i], __shfl_xor_sync(0xffffffffu, cmax[i], 2));
        }
        if (tg == 0) {
#pragma unroll
            for (int i = 0; i < 4; i++)
                wmax[(warpM * 32 + g + 8 * i) * 4 + warpN] = cmax[i];
        }
        __syncthreads();

        // combine across warpN warps; exp; write P; row sums
        float nm[4], sc[4], rsum[4];
#pragma unroll
        for (int i = 0; i < 4; i++) {
            const int row = warpM * 32 + g + 8 * i;
            float m = fmaxf(fmaxf(wmax[row * 4 + 0], wmax[row * 4 + 1]),
                            fmaxf(wmax[row * 4 + 2], wmax[row * 4 + 3]));
            nm[i] = fmaxf(rm_loc[i], m);
            sc[i] = __expf(rm_loc[i] - nm[i]);
            rsum[i] = 0.0f;
        }
#pragma unroll
        for (int mi = 0; mi < 2; mi++)
#pragma unroll
            for (int ni = 0; ni < 2; ni++) {
#pragma unroll
                for (int hf = 0; hf < 2; hf++) {
                    const int i = mi * 2 + hf;
                    float p0 = __expf(accs[mi][ni][hf * 2]     - nm[i]);
                    float p1 = __expf(accs[mi][ni][hf * 2 + 1] - nm[i]);
                    rsum[i] += p0 + p1;
                    uint32_t hw, lw;
                    split2(p0, p1, hw, lw);
                    const int row = warpM * 32 + mi * 16 + hf * 8 + g;
                    const int col = warpN * 16 + ni * 8 + tg * 2;
                    *(uint32_t*)&Ph[row * ALD + col] = hw;
                    *(uint32_t*)&Pl[row * ALD + col] = lw;
                }
            }
#pragma unroll
        for (int i = 0; i < 4; i++) {
            rsum[i] += __shfl_xor_sync(0xffffffffu, rsum[i], 1);
            rsum[i] += __shfl_xor_sync(0xffffffffu, rsum[i], 2);
        }
        if (tg == 0) {
#pragma unroll
            for (int i = 0; i < 4; i++)
                wsum[(warpM * 32 + g + 8 * i) * 4 + warpN] = rsum[i];
        }
        __syncthreads();

#pragma unroll
        for (int i = 0; i < 4; i++) {
            const int row = warpM * 32 + g + 8 * i;
            const float tot = wsum[row * 4 + 0] + wsum[row * 4 + 1]
                            + wsum[row * 4 + 2] + wsum[row * 4 + 3];
            rl_loc[i] = rl_loc[i] * sc[i] + tot;
            rm_loc[i] = nm[i];
        }
        // rescale output accumulators
#pragma unroll
        for (int mi = 0; mi < 2; mi++)
#pragma unroll
            for (int ni = 0; ni < 2; ni++) {
                acco[mi][ni][0] *= sc[mi * 2];     acco[mi][ni][1] *= sc[mi * 2];
                acco[mi][ni][2] *= sc[mi * 2 + 1]; acco[mi][ni][3] *= sc[mi * 2 + 1];
            }

        // O += P @ V via mma (bf16x3)
#pragma unroll
        for (int kk = 0; kk < 4; kk++) {
            const int colk = kk * 16 + (lane >> 4) * 8;
            uint32_t ph[2][4], pl[2][4];
#pragma unroll
            for (int mi = 0; mi < 2; mi++) {
                const int r = warpM * 32 + mi * 16 + (lane & 15);
                ldsm4(ph[mi], &Ph[r * ALD + colk]);
                ldsm4(pl[mi], &Pl[r * ALD + colk]);
            }
            uint32_t vh[2][2], vl[2][2];
            {
                const int r = kk * 16 + (lane & 15);
                const int c = warpN * 16 + (lane >> 4) * 8;
                uint32_t t[4];
                ldsm4t(t, &Vh[r * ALD + c]);
                vh[0][0] = t[0]; vh[0][1] = t[1]; vh[1][0] = t[2]; vh[1][1] = t[3];
                ldsm4t(t, &Vl[r * ALD + c]);
                vl[0][0] = t[0]; vl[0][1] = t[1]; vl[1][0] = t[2]; vl[1][1] = t[3];
            }
#pragma unroll
            for (int mi = 0; mi < 2; mi++)
#pragma unroll
                for (int ni = 0; ni < 2; ni++) {
                    mma16816(acco[mi][ni], ph[mi], vh[ni]);
                    mma16816(acco[mi][ni], pl[mi], vh[ni]);
                    mma16816(acco[mi][ni], ph[mi], vl[ni]);
                }
        }
    }

    // epilogue: O / rl -> split bf16 ctx
#pragma unroll
    for (int mi = 0; mi < 2; mi++) {
        const int row = warpM * 32 + mi * 16 + g;
        const float inv1 = 1.0f / rl_loc[mi * 2];
        const float inv2 = 1.0f / rl_loc[mi * 2 + 1];
#pragma unroll
        for (int ni = 0; ni < 2; ni++) {
            const int col = warpN * 16 + ni * 8 + tg * 2;
            size_t off = (size_t)(b * Tz + i0 + row) * Hz + h * HDz + col;
            uint32_t hw, lw;
            split2(acco[mi][ni][0] * inv1, acco[mi][ni][1] * inv1, hw, lw);
            *(uint32_t*)(ctx_h + off) = hw;
            *(uint32_t*)(ctx_l + off) = lw;
            off = (size_t)(b * Tz + i0 + row + 8) * Hz + h * HDz + col;
            split2(acco[mi][ni][2] * inv2, acco[mi][ni][3] * inv2, hw, lw);
            *(uint32_t*)(ctx_h + off) = hw;
            *(uint32_t*)(ctx_l + off) = lw;
        }
    }
}

// ---- register-resident LayerNorm: 1 float4/thread, fused sum/sumsq reduction ----
template<int NP>
__global__ __launch_bounds__(256) void ln_kernel(
    const float* __restrict__ p0, const float* __restrict__ p1,
    const float* __restrict__ p2, const float* __restrict__ p3,
    const float* __restrict__ gb, const float* __restrict__ res,
    const float* __restrict__ g, const float* __restrict__ bb,
    float* __restrict__ out,
    __nv_bfloat16* __restrict__ oh, __nv_bfloat16* __restrict__ ol)
{
    __shared__ float2 red2[8];
    const int row = blockIdx.x;
    const size_t ro = (size_t)row * Hz;
    const int i4 = threadIdx.x * 4;
    const int lane = threadIdx.x & 31, w = threadIdx.x >> 5;

    float4 xv = make_float4(0.f, 0.f, 0.f, 0.f);
    if (i4 < Hz) {
        float4 a0 = *(const float4*)(p0 + ro + i4);
        float4 a1 = *(const float4*)(p1 + ro + i4);
        float4 rr = *(const float4*)(res + ro + i4);
        float4 gg = *(const float4*)(gb + i4);
        xv.x = a0.x + a1.x + rr.x + gg.x;
        xv.y = a0.y + a1.y + rr.y + gg.y;
        xv.z = a0.z + a1.z + rr.z + gg.z;
        xv.w = a0.w + a1.w + rr.w + gg.w;
        if (NP >= 3) {
            float4 a2 = *(const float4*)(p2 + ro + i4);
            xv.x += a2.x; xv.y += a2.y; xv.z += a2.z; xv.w += a2.w;
        }
        if (NP >= 4) {
            float4 a3 = *(const float4*)(p3 + ro + i4);
            xv.x += a3.x; xv.y += a3.y; xv.z += a3.z; xv.w += a3.w;
        }
    }
    float s  = xv.x + xv.y + xv.z + xv.w;
    float sq = xv.x * xv.x + xv.y * xv.y + xv.z * xv.z + xv.w * xv.w;
#pragma unroll
    for (int o = 16; o > 0; o >>= 1) {
        s  += __shfl_down_sync(0xffffffffu, s, o);
        sq += __shfl_down_sync(0xffffffffu, sq, o);
    }
    if (lane == 0) red2[w] = make_float2(s, sq);
    __syncthreads();
    if (w == 0) {
        float2 t = (lane < 8) ? red2[lane] : make_float2(0.f, 0.f);
#pragma unroll
        for (int o = 4; o > 0; o >>= 1) {
            t.x += __shfl_down_sync(0xffffffffu, t.x, o);
            t.y += __shfl_down_sync(0xffffffffu, t.y, o);
        }
        if (lane == 0) red2[0] = t;
    }
    __syncthreads();
    const float mean = red2[0].x * (1.0f / Hz);
    const float var  = red2[0].y * (1.0f / Hz) - mean * mean;
    const float rstd = rsqrtf(var + 1e-12f);

    if (i4 < Hz) {
        float4 gv = *(const float4*)(g + i4);
        float4 bv = *(const float4*)(bb + i4);
        float4 y;
        y.x = (xv.x - mean) * rstd * gv.x + bv.x;
        y.y = (xv.y - mean) * rstd * gv.y + bv.y;
        y.z = (xv.z - mean) * rstd * gv.z + bv.z;
        y.w = (xv.w - mean) * rstd * gv.w + bv.w;
        *(float4*)(out + ro + i4) = y;
        uint32_t h01, l01, h23, l23;
        split2(y.x, y.y, h01, l01);
        split2(y.z, y.w, h23, l23);
        *(uint2*)(oh + ro + i4) = make_uint2(h01, h23);
        *(uint2*)(ol + ro + i4) = make_uint2(l01, l23);
    }
}

// ---------------- launch ----------------
extern "C" void kernel_launch(void* const* d_in, const int* in_sizes, int n_in,
                              void* d_out, int out_size)
{
    const float* hidden = (const float*)d_in[0];
    const float* mask   = (const float*)d_in[1];
    const float* Wq  = (const float*)d_in[2];   const float* bq  = (const float*)d_in[3];
    const float* Wk  = (const float*)d_in[4];   const float* bk  = (const float*)d_in[5];
    const float* Wv  = (const float*)d_in[6];   const float* bv  = (const float*)d_in[7];
    const float* Wao = (const float*)d_in[8];   const float* bao = (const float*)d_in[9];
    const float* g1  = (const float*)d_in[10];  const float* b1  = (const float*)d_in[11];
    const float* Wi  = (const float*)d_in[12];  const float* bi  = (const float*)d_in[13];
    const float* Wo  = (const float*)d_in[14];  const float* bo  = (const float*)d_in[15];
    const float* g2  = (const float*)d_in[16];  const float* b2  = (const float*)d_in[17];
    float* out = (float*)d_out;

    float *p0, *p1, *p2, *p3, *attn, *xb;
    cudaGetSymbolAddress((void**)&p0, g_p0);
    cudaGetSymbolAddress((void**)&p1, g_p1);
    cudaGetSymbolAddress((void**)&p2, g_p2);
    cudaGetSymbolAddress((void**)&p3, g_p3);
    cudaGetSymbolAddress((void**)&attn, g_attn);
    cudaGetSymbolAddress((void**)&xb, g_x);

    __nv_bfloat16 *qh, *ql, *kh, *kl, *vh, *vl;
    cudaGetSymbolAddress((void**)&qh, g_qh); cudaGetSymbolAddress((void**)&ql, g_ql);
    cudaGetSymbolAddress((void**)&kh, g_kh); cudaGetSymbolAddress((void**)&kl, g_kl);
    cudaGetSymbolAddress((void**)&vh, g_vh); cudaGetSymbolAddress((void**)&vl, g_vl);

    __nv_bfloat16 *xh, *xl, *ath, *atl, *cth, *ctl, *ffh, *ffl;
    cudaGetSymbolAddress((void**)&xh,  g_x_h);    cudaGetSymbolAddress((void**)&xl,  g_x_l);
    cudaGetSymbolAddress((void**)&ath, g_attn_h); cudaGetSymbolAddress((void**)&atl, g_attn_l);
    cudaGetSymbolAddress((void**)&cth, g_ctx_h);  cudaGetSymbolAddress((void**)&ctl, g_ctx_l);
    cudaGetSymbolAddress((void**)&ffh, g_ff_h);   cudaGetSymbolAddress((void**)&ffl, g_ff_l);

    __nv_bfloat16 *wqh, *wql, *wkh, *wkl, *wvh, *wvl, *waoh, *waol, *wih, *wil, *woh, *wol;
    cudaGetSymbolAddress((void**)&wqh,  g_wq_h);  cudaGetSymbolAddress((void**)&wql,  g_wq_l);
    cudaGetSymbolAddress((void**)&wkh,  g_wk_h);  cudaGetSymbolAddress((void**)&wkl,  g_wk_l);
    cudaGetSymbolAddress((void**)&wvh,  g_wv_h);  cudaGetSymbolAddress((void**)&wvl,  g_wv_l);
    cudaGetSymbolAddress((void**)&waoh, g_wao_h); cudaGetSymbolAddress((void**)&waol, g_wao_l);
    cudaGetSymbolAddress((void**)&wih,  g_wi_h);  cudaGetSymbolAddress((void**)&wil,  g_wi_l);
    cudaGetSymbolAddress((void**)&woh,  g_wo_h);  cudaGetSymbolAddress((void**)&wol,  g_wo_l);

    // merged prepass: ONE launch splits all weights + input (512 float4/block)
    {
        const int nHH = Lz * Hz * Hz, nHF = Lz * Hz * FFz, nX = Mz * Hz;
        SplitArgs A;
        A.in[0] = Wq;  A.h[0] = wqh;  A.l[0] = wql;  A.nblk[0] = nHH / 2048;
        A.in[1] = Wk;  A.h[1] = wkh;  A.l[1] = wkl;  A.nblk[1] = nHH / 2048;
        A.in[2] = Wv;  A.h[2] = wvh;  A.l[2] = wvl;  A.nblk[2] = nHH / 2048;
        A.in[3] = Wao; A.h[3] = waoh; A.l[3] = waol; A.nblk[3] = nHH / 2048;
        A.in[4] = Wi;  A.h[4] = wih;  A.l[4] = wil;  A.nblk[4] = nHF / 2048;
        A.in[5] = Wo;  A.h[5] = woh;  A.l[5] = wol;  A.nblk[5] = nHF / 2048;
        A.in[6] = hidden; A.h[6] = xh; A.l[6] = xl;  A.nblk[6] = nX / 2048;
        int total = 4 * (nHH / 2048) + 2 * (nHF / 2048) + nX / 2048;
        split_all_kernel<<<total, 256>>>(A);
    }

    cudaFuncSetAttribute(attention_kernel,
                         cudaFuncAttributeMaxDynamicSharedMemorySize, ATT_SMEM);
    cudaFuncSetAttribute(gemm_bf16x3<0>,
                         cudaFuncAttributeMaxDynamicSharedMemorySize, GEMM_SMEM);
    cudaFuncSetAttribute(gemm_bf16x3<1>,
                         cudaFuncAttributeMaxDynamicSharedMemorySize, GEMM_SMEM);
    cudaFuncSetAttribute(gemm_bf16x3<2>,
                         cudaFuncAttributeMaxDynamicSharedMemorySize, GEMM_SMEM);

    dim3 gAtt(Tz / 64, Bz * NHz);

    for (int l = 0; l < Lz; l++) {
        const float* xres = (l == 0) ? hidden : xb;
        const size_t oHH = (size_t)l * Hz * Hz;
        const size_t oHF = (size_t)l * Hz * FFz;
        const size_t oH  = (size_t)l * Hz;
        const size_t oF  = (size_t)l * FFz;

        {   // fused QKV -> split bf16 q/k/v directly
            GemmArgs P = {};
            P.Ah[0] = P.Ah[1] = P.Ah[2] = xh;
            P.Al[0] = P.Al[1] = P.Al[2] = xl;
            P.Bh[0] = wqh + oHH; P.Bl[0] = wql + oHH;
            P.Bh[1] = wkh + oHH; P.Bl[1] = wkl + oHH;
            P.Bh[2] = wvh + oHH; P.Bl[2] = wvl + oHH;
            P.bias[0] = bq + oH; P.bias[1] = bk + oH; P.bias[2] = bv + oH;
            P.Ch[0] = qh; P.Cl[0] = ql;
            P.Ch[1] = kh; P.Cl[1] = kl;
            P.Ch[2] = vh; P.Cl[2] = vl;
            gemm_bf16x3<0><<<dim3(Hz / BN, Mz / BM, 3), 256, GEMM_SMEM>>>(P, Hz, Hz, Hz);
        }

        attention_kernel<<<gAtt, 256, ATT_SMEM>>>(qh, ql, kh, kl, vh, vl, mask, cth, ctl);

        {   // AO projection: split-K x3
            GemmArgs P = {};
#pragma unroll
            for (int sK = 0; sK < 3; sK++) {
                P.Ah[sK] = cth + sK * 256;
                P.Al[sK] = ctl + sK * 256;
                P.Bh[sK] = waoh + oHH + (size_t)sK * 256 * Hz;
                P.Bl[sK] = waol + oHH + (size_t)sK * 256 * Hz;
            }
            P.C[0] = p0; P.C[1] = p1; P.C[2] = p2;
            gemm_bf16x3<2><<<dim3(Hz / BN, Mz / BM, 3), 256, GEMM_SMEM>>>(P, Hz, 256, Hz);
        }
        ln_kernel<3><<<Mz, 256>>>(p0, p1, p2, p3, bao + oH, xres, g1 + oH, b1 + oH,
                                  attn, ath, atl);

        {   // FF1 + GELU
            GemmArgs P = {};
            P.Ah[0] = ath; P.Al[0] = atl;
            P.Bh[0] = wih + oHF; P.Bl[0] = wil + oHF;
            P.bias[0] = bi + oF;
            P.Ch[0] = ffh; P.Cl[0] = ffl;
            gemm_bf16x3<1><<<dim3(FFz / BN, Mz / BM, 1), 256, GEMM_SMEM>>>(P, Hz, Hz, FFz);
        }
        {   // FF2: split-K x4
            GemmArgs P = {};
#pragma unroll
            for (int sK = 0; sK < 4; sK++) {
                P.Ah[sK] = ffh + sK * 768;
                P.Al[sK] = ffl + sK * 768;
                P.Bh[sK] = woh + oHF + (size_t)sK * 768 * Hz;
                P.Bl[sK] = wol + oHF + (size_t)sK * 768 * Hz;
            }
            P.C[0] = p0; P.C[1] = p1; P.C[2] = p2; P.C[3] = p3;
            gemm_bf16x3<2><<<dim3(Hz / BN, Mz / BM, 4), 256, GEMM_SMEM>>>(P, FFz, 768, Hz);
        }
        ln_kernel<4><<<Mz, 256>>>(p0, p1, p2, p3, bo + oH, attn, g2 + oH, b2 + oH,
                                  (l == Lz - 1) ? out : xb, xh, xl);
    }
}

// round 16
// speedup vs baseline: 1.4074x; 1.0071x over previous
#include <cuda_runtime.h>
#include <cuda_bf16.h>
#include <math.h>
#include <stdint.h>

#define Bz  8
#define Tz  512
#define Hz  768
#define NHz 12
#define HDz 64
#define FFz 3072
#define Lz  12
#define Mz  (Bz*Tz)   // 4096

// ---------------- fp32 scratch ----------------
__device__ float g_p0[Mz*Hz];
__device__ float g_p1[Mz*Hz];
__device__ float g_p2[Mz*Hz];
__device__ float g_p3[Mz*Hz];
__device__ float g_attn[Mz*Hz];
__device__ float g_x[Mz*Hz];

// ---------------- split (hi/lo bf16) activation scratch ----------------
__device__ __nv_bfloat16 g_qh[Mz*Hz], g_ql[Mz*Hz];
__device__ __nv_bfloat16 g_kh[Mz*Hz], g_kl[Mz*Hz];
__device__ __nv_bfloat16 g_vh[Mz*Hz], g_vl[Mz*Hz];
__device__ __nv_bfloat16 g_x_h[Mz*Hz],    g_x_l[Mz*Hz];
__device__ __nv_bfloat16 g_attn_h[Mz*Hz], g_attn_l[Mz*Hz];
__device__ __nv_bfloat16 g_ctx_h[Mz*Hz],  g_ctx_l[Mz*Hz];
__device__ __nv_bfloat16 g_ff_h[Mz*FFz],  g_ff_l[Mz*FFz];

// ---------------- split weight storage ([L][K][N], hi/lo) ----------------
__device__ __nv_bfloat16 g_wq_h[Lz*Hz*Hz],  g_wq_l[Lz*Hz*Hz];
__device__ __nv_bfloat16 g_wk_h[Lz*Hz*Hz],  g_wk_l[Lz*Hz*Hz];
__device__ __nv_bfloat16 g_wv_h[Lz*Hz*Hz],  g_wv_l[Lz*Hz*Hz];
__device__ __nv_bfloat16 g_wao_h[Lz*Hz*Hz], g_wao_l[Lz*Hz*Hz];
__device__ __nv_bfloat16 g_wi_h[Lz*Hz*FFz], g_wi_l[Lz*Hz*FFz];
__device__ __nv_bfloat16 g_wo_h[Lz*Hz*FFz], g_wo_l[Lz*Hz*FFz];

// ---------------- helpers ----------------
__device__ __forceinline__ void split1(float x, __nv_bfloat16& h, __nv_bfloat16& l) {
    h = __float2bfloat16(x);
    l = __float2bfloat16(x - __bfloat162float(h));
}
__device__ __forceinline__ void split2(float x, float y, uint32_t& hi, uint32_t& lo) {
    __nv_bfloat16 xh, xl, yh, yl;
    split1(x, xh, xl); split1(y, yh, yl);
    hi = (uint32_t)__bfloat16_as_ushort(xh) | ((uint32_t)__bfloat16_as_ushort(yh) << 16);
    lo = (uint32_t)__bfloat16_as_ushort(xl) | ((uint32_t)__bfloat16_as_ushort(yl) << 16);
}

// -------- merged prepass: split 7 tensors in ONE launch, 2 float4/thread --------
struct SplitArgs {
    const float* in[7];
    __nv_bfloat16* h[7];
    __nv_bfloat16* l[7];
    int nblk[7];
};

__global__ __launch_bounds__(256) void split_all_kernel(SplitArgs A)
{
    int b = blockIdx.x;
    int seg = 0;
#pragma unroll
    for (int s = 0; s < 7; s++) {
        if (b < A.nblk[s]) { seg = s; break; }
        b -= A.nblk[s];
    }
    const float4* in = (const float4*)A.in[seg];
    uint2* oh = (uint2*)A.h[seg];
    uint2* ol = (uint2*)A.l[seg];
    const int i0 = b * 512 + threadIdx.x;
    float4 v0 = in[i0];
    float4 v1 = in[i0 + 256];
    uint32_t h01, l01, h23, l23;
    split2(v0.x, v0.y, h01, l01);
    split2(v0.z, v0.w, h23, l23);
    oh[i0] = make_uint2(h01, h23);
    ol[i0] = make_uint2(l01, l23);
    split2(v1.x, v1.y, h01, l01);
    split2(v1.z, v1.w, h23, l23);
    oh[i0 + 256] = make_uint2(h01, h23);
    ol[i0 + 256] = make_uint2(l01, l23);
}

// ===== bf16x3 mma.sync GEMM: BK=32, 3 stages, XOR-swizzled smem, 2 CTAs/SM =====
#define BM 128
#define BN 128
#define BK2 32

#define PLANE 4096
#define STG_ELEMS (4*PLANE)
#define GEMM_SMEM (3*STG_ELEMS*2)

#define ASOFFZ(s,pl,m,c)  ((s)*STG_ELEMS + (pl)*PLANE + (m)*32  + ((((c) ^ (((m)>>1)&3)))<<3))
#define BSOFFZ(s,pl,kk,c) ((s)*STG_ELEMS + 2*PLANE + (pl)*PLANE + (kk)*128 + ((((c) ^ ((kk)&7)))<<3))

struct GemmArgs {
    const __nv_bfloat16 *Ah[4], *Al[4];
    const __nv_bfloat16 *Bh[4], *Bl[4];
    const float* bias[4];
    float* C[4];
    __nv_bfloat16 *Ch[4], *Cl[4];
};

__device__ __forceinline__ void cpa16(void* dst, const void* src) {
    uint32_t d = (uint32_t)__cvta_generic_to_shared(dst);
    asm volatile("cp.async.cg.shared.global [%0], [%1], 16;" :: "r"(d), "l"(src));
}
__device__ __forceinline__ void ldsm4(uint32_t* r, const void* p) {
    uint32_t a = (uint32_t)__cvta_generic_to_shared(p);
    asm volatile("ldmatrix.sync.aligned.m8n8.x4.shared.b16 {%0,%1,%2,%3}, [%4];"
                 : "=r"(r[0]), "=r"(r[1]), "=r"(r[2]), "=r"(r[3]) : "r"(a));
}
__device__ __forceinline__ void ldsm4t(uint32_t* r, const void* p) {
    uint32_t a = (uint32_t)__cvta_generic_to_shared(p);
    asm volatile("ldmatrix.sync.aligned.m8n8.x4.trans.shared.b16 {%0,%1,%2,%3}, [%4];"
                 : "=r"(r[0]), "=r"(r[1]), "=r"(r[2]), "=r"(r[3]) : "r"(a));
}
__device__ __forceinline__ void mma16816(float* c, const uint32_t* a, const uint32_t* b) {
    asm volatile(
        "mma.sync.aligned.m16n8k16.row.col.f32.bf16.bf16.f32 "
        "{%0,%1,%2,%3}, {%4,%5,%6,%7}, {%8,%9}, {%0,%1,%2,%3};"
        : "+f"(c[0]), "+f"(c[1]), "+f"(c[2]), "+f"(c[3])
        : "r"(a[0]), "r"(a[1]), "r"(a[2]), "r"(a[3]), "r"(b[0]), "r"(b[1]));
}

// MODE 0: bias + split bf16 out (QKV). MODE 1: bias + GELU + split bf16 out (FF1).
// MODE 2: fp32 partial out, NO bias (split-K slices; bias folded into LN).
template<int MODE>
__global__ __launch_bounds__(256, 2) void gemm_bf16x3(GemmArgs P, int K_ld, int K_len, int N)
{
    extern __shared__ __align__(16) __nv_bfloat16 sm[];

    const int z = blockIdx.z;
    const __nv_bfloat16* __restrict__ Ah = P.Ah[z];
    const __nv_bfloat16* __restrict__ Al = P.Al[z];
    const __nv_bfloat16* __restrict__ Bh = P.Bh[z];
    const __nv_bfloat16* __restrict__ Bl = P.Bl[z];

    const int n0 = blockIdx.x * BN;
    const int m0 = blockIdx.y * BM;
    const int tid  = threadIdx.x;
    const int lane = tid & 31;
    const int warp = tid >> 5;
    const int warpM = warp >> 2;
    const int warpN = warp & 3;

    const int nT = K_len / BK2;

    auto issue = [&](int t, int s) {
        const int k0 = t * BK2;
#pragma unroll
        for (int p = 0; p < 2; p++) {
            const int idx = tid + p * 256;
            const int ar = idx >> 2, acc_ = idx & 3;
            cpa16(sm + ASOFFZ(s, 0, ar, acc_), Ah + (size_t)(m0 + ar) * K_ld + k0 + acc_ * 8);
            cpa16(sm + ASOFFZ(s, 1, ar, acc_), Al + (size_t)(m0 + ar) * K_ld + k0 + acc_ * 8);
            const int br = idx >> 4, bcc = idx & 15;
            cpa16(sm + BSOFFZ(s, 0, br, bcc), Bh + (size_t)(k0 + br) * N + n0 + bcc * 8);
            cpa16(sm + BSOFFZ(s, 1, br, bcc), Bl + (size_t)(k0 + br) * N + n0 + bcc * 8);
        }
        asm volatile("cp.async.commit_group;" ::: "memory");
    };

    issue(0, 0);
    issue(1, 1);

    float acc[4][4][4] = {};
    int s = 0;

    for (int t = 0; t < nT; t++) {
        if (t + 1 < nT) asm volatile("cp.async.wait_group 1;" ::: "memory");
        else            asm volatile("cp.async.wait_group 0;" ::: "memory");
        __syncthreads();

        if (t + 2 < nT) {
            int s2 = s + 2; if (s2 >= 3) s2 -= 3;
            issue(t + 2, s2);
        }

#pragma unroll
        for (int sub = 0; sub < 2; sub++) {
            uint32_t ah[4][4], al[4][4], bh[4][2], bl[4][2];
            const int cA = sub * 2 + (lane >> 4);
#pragma unroll
            for (int mi = 0; mi < 4; mi++) {
                const int arow = warpM * 64 + mi * 16 + (lane & 15);
                ldsm4(ah[mi], sm + ASOFFZ(s, 0, arow, cA));
                ldsm4(al[mi], sm + ASOFFZ(s, 1, arow, cA));
            }
            const int brow = sub * 16 + (lane & 15);
            // load hi B plane first, run hh sweep under it, then lo B plane
#pragma unroll
            for (int pr = 0; pr < 2; pr++) {
                const int cB = warpN * 4 + pr * 2 + (lane >> 4);
                uint32_t tmp[4];
                ldsm4t(tmp, sm + BSOFFZ(s, 0, brow, cB));
                bh[pr * 2][0] = tmp[0]; bh[pr * 2][1] = tmp[1];
                bh[pr * 2 + 1][0] = tmp[2]; bh[pr * 2 + 1][1] = tmp[3];
            }
#pragma unroll
            for (int mi = 0; mi < 4; mi++)
#pragma unroll
                for (int ni = 0; ni < 4; ni++)
                    mma16816(acc[mi][ni], ah[mi], bh[ni]);
#pragma unroll
            for (int pr = 0; pr < 2; pr++) {
                const int cB = warpN * 4 + pr * 2 + (lane >> 4);
                uint32_t tmp[4];
                ldsm4t(tmp, sm + BSOFFZ(s, 1, brow, cB));
                bl[pr * 2][0] = tmp[0]; bl[pr * 2][1] = tmp[1];
                bl[pr * 2 + 1][0] = tmp[2]; bl[pr * 2 + 1][1] = tmp[3];
            }
#pragma unroll
            for (int mi = 0; mi < 4; mi++)
#pragma unroll
                for (int ni = 0; ni < 4; ni++)
                    mma16816(acc[mi][ni], ah[mi], bl[ni]);
#pragma unroll
            for (int mi = 0; mi < 4; mi++)
#pragma unroll
                for (int ni = 0; ni < 4; ni++)
                    mma16816(acc[mi][ni], al[mi], bh[ni]);
        }
        if (++s == 3) s = 0;
    }

    const float* __restrict__ bias = P.bias[z];
    const int g  = lane >> 2;
    const int tg = lane & 3;
#pragma unroll
    for (int mi = 0; mi < 4; mi++) {
#pragma unroll
        for (int ni = 0; ni < 4; ni++) {
            const int row = m0 + warpM * 64 + mi * 16 + g;
            const int col = n0 + warpN * 32 + ni * 8 + tg * 2;
            float v0 = acc[mi][ni][0];
            float v1 = acc[mi][ni][1];
            float v2 = acc[mi][ni][2];
            float v3 = acc[mi][ni][3];
            if (MODE != 2) {
                const float b0 = bias[col], b1 = bias[col + 1];
                v0 += b0; v1 += b1; v2 += b0; v3 += b1;
            }
            if (MODE == 1) {
                v0 = 0.5f * v0 * (1.0f + erff(v0 * 0.70710678118654752f));
                v1 = 0.5f * v1 * (1.0f + erff(v1 * 0.70710678118654752f));
                v2 = 0.5f * v2 * (1.0f + erff(v2 * 0.70710678118654752f));
                v3 = 0.5f * v3 * (1.0f + erff(v3 * 0.70710678118654752f));
            }
            if (MODE == 2) {
                float* C = P.C[z];
                *(float2*)(C + (size_t)row * N + col)       = make_float2(v0, v1);
                *(float2*)(C + (size_t)(row + 8) * N + col) = make_float2(v2, v3);
            } else {
                __nv_bfloat16* Ch = P.Ch[z];
                __nv_bfloat16* Cl = P.Cl[z];
                uint32_t hw, lw;
                split2(v0, v1, hw, lw);
                *(uint32_t*)(Ch + (size_t)row * N + col) = hw;
                *(uint32_t*)(Cl + (size_t)row * N + col) = lw;
                split2(v2, v3, hw, lw);
                *(uint32_t*)(Ch + (size_t)(row + 8) * N + col) = hw;
                *(uint32_t*)(Cl + (size_t)(row + 8) * N + col) = lw;
            }
        }
    }
}

// ------- tensor-core flash attention: fragment-resident softmax, 3 CTAs/SM -------
#define ALD 72
#define ATT_SMEM (8*64*ALD*2 + (64 + 256 + 256)*4)   // 76032 B

__global__ __launch_bounds__(256, 3) void attention_kernel(
    const __nv_bfloat16* __restrict__ qh_g, const __nv_bfloat16* __restrict__ ql_g,
    const __nv_bfloat16* __restrict__ kh_g, const __nv_bfloat16* __restrict__ kl_g,
    const __nv_bfloat16* __restrict__ vh_g, const __nv_bfloat16* __restrict__ vl_g,
    const float* __restrict__ mask,
    __nv_bfloat16* __restrict__ ctx_h, __nv_bfloat16* __restrict__ ctx_l)
{
    extern __shared__ char smraw[];
    __nv_bfloat16* Qh = (__nv_bfloat16*)smraw;
    __nv_bfloat16* Ql = Qh + 64 * ALD;
    __nv_bfloat16* Kh = Ql + 64 * ALD;
    __nv_bfloat16* Kl = Kh + 64 * ALD;
    __nv_bfloat16* Vh = Kl + 64 * ALD;
    __nv_bfloat16* Vl = Vh + 64 * ALD;
    __nv_bfloat16* Ph = Vl + 64 * ALD;
    __nv_bfloat16* Pl = Ph + 64 * ALD;
    float* am   = (float*)(Pl + 64 * ALD);
    float* wmax = am + 64;
    float* wsum = wmax + 256;

    const int tid  = threadIdx.x;
    const int lane = tid & 31;
    const int warp = tid >> 5;
    const int warpM = warp >> 2;
    const int warpN = warp & 3;
    const int g  = lane >> 2;
    const int tg = lane & 3;
    const int bh = blockIdx.y;
    const int b = bh / NHz, h = bh % NHz;
    const int i0 = blockIdx.x * 64;
    const float scale = 0.125f;

#pragma unroll
    for (int p = 0; p < 2; p++) {
        const int u = tid + p * 256;
        const int row = u >> 3, c16 = (u & 7) * 8;
        const size_t go = (size_t)(b * Tz + i0 + row) * Hz + h * HDz + c16;
        *(uint4*)&Qh[row * ALD + c16] = *(const uint4*)(qh_g + go);
        *(uint4*)&Ql[row * ALD + c16] = *(const uint4*)(ql_g + go);
    }

    float rm_loc[4], rl_loc[4];
#pragma unroll
    for (int i = 0; i < 4; i++) { rm_loc[i] = -1e30f; rl_loc[i] = 0.0f; }

    float acco[2][2][4] = {};

    for (int jc = 0; jc < Tz / 64; jc++) {
        const int j0 = jc * 64;
        __syncthreads();

#pragma unroll
        for (int p = 0; p < 2; p++) {
            const int u = tid + p * 256;
            const int row = u >> 3, c16 = (u & 7) * 8;
            const size_t go = (size_t)(b * Tz + j0 + row) * Hz + h * HDz + c16;
            *(uint4*)&Kh[row * ALD + c16] = *(const uint4*)(kh_g + go);
            *(uint4*)&Kl[row * ALD + c16] = *(const uint4*)(kl_g + go);
            *(uint4*)&Vh[row * ALD + c16] = *(const uint4*)(vh_g + go);
            *(uint4*)&Vl[row * ALD + c16] = *(const uint4*)(vl_g + go);
        }
        if (tid < 64) am[tid] = (1.0f - mask[b * Tz + j0 + tid]) * -10000.0f;
        __syncthreads();

        float accs[2][2][4] = {};
#pragma unroll
        for (int kk = 0; kk < 4; kk++) {
            const int colk = kk * 16 + (lane >> 4) * 8;
            uint32_t qh[2][4], ql[2][4];
#pragma unroll
            for (int mi = 0; mi < 2; mi++) {
                const int r = warpM * 32 + mi * 16 + (lane & 15);
                ldsm4(qh[mi], &Qh[r * ALD + colk]);
                ldsm4(ql[mi], &Ql[r * ALD + colk]);
            }
            uint32_t kh[2][2], kl[2][2];
            {
                const int r = warpN * 16 + (lane & 15);
                uint32_t t[4];
                ldsm4(t, &Kh[r * ALD + colk]);
                kh[0][0] = t[0]; kh[0][1] = t[2]; kh[1][0] = t[1]; kh[1][1] = t[3];
                ldsm4(t, &Kl[r * ALD + colk]);
                kl[0][0] = t[0]; kl[0][1] = t[2]; kl[1][0] = t[1]; kl[1][1] = t[3];
            }
#pragma unroll
            for (int mi = 0; mi < 2; mi++)
#pragma unroll
                for (int ni = 0; ni < 2; ni++) {
                    mma16816(accs[mi][ni], qh[mi], kh[ni]);
                    mma16816(accs[mi][ni], qh[mi], kl[ni]);
                    mma16816(accs[mi][ni], ql[mi], kh[ni]);
                }
        }

        float cmax[4];
#pragma unroll
        for (int i = 0; i < 4; i++) cmax[i] = -1e30f;
#pragma unroll
        for (int mi = 0; mi < 2; mi++)
#pragma unroll
            for (int ni = 0; ni < 2; ni++) {
                const int col = warpN * 16 + ni * 8 + tg * 2;
                const float m0v = am[col], m1v = am[col + 1];
                accs[mi][ni][0] = accs[mi][ni][0] * scale + m0v;
                accs[mi][ni][1] = accs[mi][ni][1] * scale + m1v;
                accs[mi][ni][2] = accs[mi][ni][2] * scale + m0v;
                accs[mi][ni][3] = accs[mi][ni][3] * scale + m1v;
                cmax[mi * 2]     = fmaxf(cmax[mi * 2],     fmaxf(accs[mi][ni][0], accs[mi][ni][1]));
                cmax[mi * 2 + 1] = fmaxf(cmax[mi * 2 + 1], fmaxf(accs[mi][ni][2], accs[mi][ni][3]));
            }
#pragma unroll
        for (int i = 0; i < 4; i++) {
            cmax[i] = fmaxf(cmax[i], __shfl_xor_sync(0xffffffffu, cmax[i], 1));
            cmax[i] = fmaxf(cmax[i], __shfl_xor_sync(0xffffffffu, cmax[i], 2));
        }
        if (tg == 0) {
#pragma unroll
            for (int i = 0; i < 4; i++)
                wmax[(warpM * 32 + g + 8 * i) * 4 + warpN] = cmax[i];
        }
        __syncthreads();

        float nm[4], sc[4], rsum[4];
#pragma unroll
        for (int i = 0; i < 4; i++) {
            const int row = warpM * 32 + g + 8 * i;
            float m = fmaxf(fmaxf(wmax[row * 4 + 0], wmax[row * 4 + 1]),
                            fmaxf(wmax[row * 4 + 2], wmax[row * 4 + 3]));
            nm[i] = fmaxf(rm_loc[i], m);
            sc[i] = __expf(rm_loc[i] - nm[i]);
            rsum[i] = 0.0f;
        }
#pragma unroll
        for (int mi = 0; mi < 2; mi++)
#pragma unroll
            for (int ni = 0; ni < 2; ni++) {
#pragma unroll
                for (int hf = 0; hf < 2; hf++) {
                    const int i = mi * 2 + hf;
                    float p0 = __expf(accs[mi][ni][hf * 2]     - nm[i]);
                    float p1 = __expf(accs[mi][ni][hf * 2 + 1] - nm[i]);
                    rsum[i] += p0 + p1;
                    uint32_t hw, lw;
                    split2(p0, p1, hw, lw);
                    const int row = warpM * 32 + mi * 16 + hf * 8 + g;
                    const int col = warpN * 16 + ni * 8 + tg * 2;
                    *(uint32_t*)&Ph[row * ALD + col] = hw;
                    *(uint32_t*)&Pl[row * ALD + col] = lw;
                }
            }
#pragma unroll
        for (int i = 0; i < 4; i++) {
            rsum[i] += __shfl_xor_sync(0xffffffffu, rsum[i], 1);
            rsum[i] += __shfl_xor_sync(0xffffffffu, rsum[i], 2);
        }
        if (tg == 0) {
#pragma unroll
            for (int i = 0; i < 4; i++)
                wsum[(warpM * 32 + g + 8 * i) * 4 + warpN] = rsum[i];
        }
        __syncthreads();

#pragma unroll
        for (int i = 0; i < 4; i++) {
            const int row = warpM * 32 + g + 8 * i;
            const float tot = wsum[row * 4 + 0] + wsum[row * 4 + 1]
                            + wsum[row * 4 + 2] + wsum[row * 4 + 3];
            rl_loc[i] = rl_loc[i] * sc[i] + tot;
            rm_loc[i] = nm[i];
        }
#pragma unroll
        for (int mi = 0; mi < 2; mi++)
#pragma unroll
            for (int ni = 0; ni < 2; ni++) {
                acco[mi][ni][0] *= sc[mi * 2];     acco[mi][ni][1] *= sc[mi * 2];
                acco[mi][ni][2] *= sc[mi * 2 + 1]; acco[mi][ni][3] *= sc[mi * 2 + 1];
            }

#pragma unroll
        for (int kk = 0; kk < 4; kk++) {
            const int colk = kk * 16 + (lane >> 4) * 8;
            uint32_t ph[2][4], pl[2][4];
#pragma unroll
            for (int mi = 0; mi < 2; mi++) {
                const int r = warpM * 32 + mi * 16 + (lane & 15);
                ldsm4(ph[mi], &Ph[r * ALD + colk]);
                ldsm4(pl[mi], &Pl[r * ALD + colk]);
            }
            uint32_t vh[2][2], vl[2][2];
            {
                const int r = kk * 16 + (lane & 15);
                const int c = warpN * 16 + (lane >> 4) * 8;
                uint32_t t[4];
                ldsm4t(t, &Vh[r * ALD + c]);
                vh[0][0] = t[0]; vh[0][1] = t[1]; vh[1][0] = t[2]; vh[1][1] = t[3];
                ldsm4t(t, &Vl[r * ALD + c]);
                vl[0][0] = t[0]; vl[0][1] = t[1]; vl[1][0] = t[2]; vl[1][1] = t[3];
            }
#pragma unroll
            for (int mi = 0; mi < 2; mi++)
#pragma unroll
                for (int ni = 0; ni < 2; ni++) {
                    mma16816(acco[mi][ni], ph[mi], vh[ni]);
                    mma16816(acco[mi][ni], pl[mi], vh[ni]);
                    mma16816(acco[mi][ni], ph[mi], vl[ni]);
                }
        }
    }

#pragma unroll
    for (int mi = 0; mi < 2; mi++) {
        const int row = warpM * 32 + mi * 16 + g;
        const float inv1 = 1.0f / rl_loc[mi * 2];
        const float inv2 = 1.0f / rl_loc[mi * 2 + 1];
#pragma unroll
        for (int ni = 0; ni < 2; ni++) {
            const int col = warpN * 16 + ni * 8 + tg * 2;
            size_t off = (size_t)(b * Tz + i0 + row) * Hz + h * HDz + col;
            uint32_t hw, lw;
            split2(acco[mi][ni][0] * inv1, acco[mi][ni][1] * inv1, hw, lw);
            *(uint32_t*)(ctx_h + off) = hw;
            *(uint32_t*)(ctx_l + off) = lw;
            off = (size_t)(b * Tz + i0 + row + 8) * Hz + h * HDz + col;
            split2(acco[mi][ni][2] * inv2, acco[mi][ni][3] * inv2, hw, lw);
            *(uint32_t*)(ctx_h + off) = hw;
            *(uint32_t*)(ctx_l + off) = lw;
        }
    }
}

// ---- register-resident LayerNorm: 192 threads (1 float4 each), fused reduction ----
template<int NP>
__global__ __launch_bounds__(192) void ln_kernel(
    const float* __restrict__ p0, const float* __restrict__ p1,
    const float* __restrict__ p2, const float* __restrict__ p3,
    const float* __restrict__ gb, const float* __restrict__ res,
    const float* __restrict__ g, const float* __restrict__ bb,
    float* __restrict__ out,
    __nv_bfloat16* __restrict__ oh, __nv_bfloat16* __restrict__ ol)
{
    __shared__ float2 red2[6];
    const int row = blockIdx.x;
    const size_t ro = (size_t)row * Hz;
    const int i4 = threadIdx.x * 4;          // 192 threads * 4 = 768, all active
    const int lane = threadIdx.x & 31, w = threadIdx.x >> 5;

    float4 a0 = *(const float4*)(p0 + ro + i4);
    float4 a1 = *(const float4*)(p1 + ro + i4);
    float4 rr = *(const float4*)(res + ro + i4);
    float4 gg = *(const float4*)(gb + i4);
    float4 xv;
    xv.x = a0.x + a1.x + rr.x + gg.x;
    xv.y = a0.y + a1.y + rr.y + gg.y;
    xv.z = a0.z + a1.z + rr.z + gg.z;
    xv.w = a0.w + a1.w + rr.w + gg.w;
    if (NP >= 3) {
        float4 a2 = *(const float4*)(p2 + ro + i4);
        xv.x += a2.x; xv.y += a2.y; xv.z += a2.z; xv.w += a2.w;
    }
    if (NP >= 4) {
        float4 a3 = *(const float4*)(p3 + ro + i4);
        xv.x += a3.x; xv.y += a3.y; xv.z += a3.z; xv.w += a3.w;
    }
    float s  = xv.x + xv.y + xv.z + xv.w;
    float sq = xv.x * xv.x + xv.y * xv.y + xv.z * xv.z + xv.w * xv.w;
#pragma unroll
    for (int o = 16; o > 0; o >>= 1) {
        s  += __shfl_down_sync(0xffffffffu, s, o);
        sq += __shfl_down_sync(0xffffffffu, sq, o);
    }
    if (lane == 0) red2[w] = make_float2(s, sq);
    __syncthreads();
    if (w == 0) {
        float2 t = (lane < 6) ? red2[lane] : make_float2(0.f, 0.f);
#pragma unroll
        for (int o = 4; o > 0; o >>= 1) {
            t.x += __shfl_down_sync(0xffffffffu, t.x, o);
            t.y += __shfl_down_sync(0xffffffffu, t.y, o);
        }
        if (lane == 0) red2[0] = t;
    }
    __syncthreads();
    const float mean = red2[0].x * (1.0f / Hz);
    const float var  = red2[0].y * (1.0f / Hz) - mean * mean;
    const float rstd = rsqrtf(var + 1e-12f);

    float4 gv = *(const float4*)(g + i4);
    float4 bv = *(const float4*)(bb + i4);
    float4 y;
    y.x = (xv.x - mean) * rstd * gv.x + bv.x;
    y.y = (xv.y - mean) * rstd * gv.y + bv.y;
    y.z = (xv.z - mean) * rstd * gv.z + bv.z;
    y.w = (xv.w - mean) * rstd * gv.w + bv.w;
    *(float4*)(out + ro + i4) = y;
    uint32_t h01, l01, h23, l23;
    split2(y.x, y.y, h01, l01);
    split2(y.z, y.w, h23, l23);
    *(uint2*)(oh + ro + i4) = make_uint2(h01, h23);
    *(uint2*)(ol + ro + i4) = make_uint2(l01, l23);
}

// ---------------- launch ----------------
extern "C" void kernel_launch(void* const* d_in, const int* in_sizes, int n_in,
                              void* d_out, int out_size)
{
    const float* hidden = (const float*)d_in[0];
    const float* mask   = (const float*)d_in[1];
    const float* Wq  = (const float*)d_in[2];   const float* bq  = (const float*)d_in[3];
    const float* Wk  = (const float*)d_in[4];   const float* bk  = (const float*)d_in[5];
    const float* Wv  = (const float*)d_in[6];   const float* bv  = (const float*)d_in[7];
    const float* Wao = (const float*)d_in[8];   const float* bao = (const float*)d_in[9];
    const float* g1  = (const float*)d_in[10];  const float* b1  = (const float*)d_in[11];
    const float* Wi  = (const float*)d_in[12];  const float* bi  = (const float*)d_in[13];
    const float* Wo  = (const float*)d_in[14];  const float* bo  = (const float*)d_in[15];
    const float* g2  = (const float*)d_in[16];  const float* b2  = (const float*)d_in[17];
    float* out = (float*)d_out;

    float *p0, *p1, *p2, *p3, *attn, *xb;
    cudaGetSymbolAddress((void**)&p0, g_p0);
    cudaGetSymbolAddress((void**)&p1, g_p1);
    cudaGetSymbolAddress((void**)&p2, g_p2);
    cudaGetSymbolAddress((void**)&p3, g_p3);
    cudaGetSymbolAddress((void**)&attn, g_attn);
    cudaGetSymbolAddress((void**)&xb, g_x);

    __nv_bfloat16 *qh, *ql, *kh, *kl, *vh, *vl;
    cudaGetSymbolAddress((void**)&qh, g_qh); cudaGetSymbolAddress((void**)&ql, g_ql);
    cudaGetSymbolAddress((void**)&kh, g_kh); cudaGetSymbolAddress((void**)&kl, g_kl);
    cudaGetSymbolAddress((void**)&vh, g_vh); cudaGetSymbolAddress((void**)&vl, g_vl);

    __nv_bfloat16 *xh, *xl, *ath, *atl, *cth, *ctl, *ffh, *ffl;
    cudaGetSymbolAddress((void**)&xh,  g_x_h);    cudaGetSymbolAddress((void**)&xl,  g_x_l);
    cudaGetSymbolAddress((void**)&ath, g_attn_h); cudaGetSymbolAddress((void**)&atl, g_attn_l);
    cudaGetSymbolAddress((void**)&cth, g_ctx_h);  cudaGetSymbolAddress((void**)&ctl, g_ctx_l);
    cudaGetSymbolAddress((void**)&ffh, g_ff_h);   cudaGetSymbolAddress((void**)&ffl, g_ff_l);

    __nv_bfloat16 *wqh, *wql, *wkh, *wkl, *wvh, *wvl, *waoh, *waol, *wih, *wil, *woh, *wol;
    cudaGetSymbolAddress((void**)&wqh,  g_wq_h);  cudaGetSymbolAddress((void**)&wql,  g_wq_l);
    cudaGetSymbolAddress((void**)&wkh,  g_wk_h);  cudaGetSymbolAddress((void**)&wkl,  g_wk_l);
    cudaGetSymbolAddress((void**)&wvh,  g_wv_h);  cudaGetSymbolAddress((void**)&wvl,  g_wv_l);
    cudaGetSymbolAddress((void**)&waoh, g_wao_h); cudaGetSymbolAddress((void**)&waol, g_wao_l);
    cudaGetSymbolAddress((void**)&wih,  g_wi_h);  cudaGetSymbolAddress((void**)&wil,  g_wi_l);
    cudaGetSymbolAddress((void**)&woh,  g_wo_h);  cudaGetSymbolAddress((void**)&wol,  g_wo_l);

    // merged prepass: ONE launch splits all weights + input (512 float4/block)
    {
        const int nHH = Lz * Hz * Hz, nHF = Lz * Hz * FFz, nX = Mz * Hz;
        SplitArgs A;
        A.in[0] = Wq;  A.h[0] = wqh;  A.l[0] = wql;  A.nblk[0] = nHH / 2048;
        A.in[1] = Wk;  A.h[1] = wkh;  A.l[1] = wkl;  A.nblk[1] = nHH / 2048;
        A.in[2] = Wv;  A.h[2] = wvh;  A.l[2] = wvl;  A.nblk[2] = nHH / 2048;
        A.in[3] = Wao; A.h[3] = waoh; A.l[3] = waol; A.nblk[3] = nHH / 2048;
        A.in[4] = Wi;  A.h[4] = wih;  A.l[4] = wil;  A.nblk[4] = nHF / 2048;
        A.in[5] = Wo;  A.h[5] = woh;  A.l[5] = wol;  A.nblk[5] = nHF / 2048;
        A.in[6] = hidden; A.h[6] = xh; A.l[6] = xl;  A.nblk[6] = nX / 2048;
        int total = 4 * (nHH / 2048) + 2 * (nHF / 2048) + nX / 2048;
        split_all_kernel<<<total, 256>>>(A);
    }

    cudaFuncSetAttribute(attention_kernel,
                         cudaFuncAttributeMaxDynamicSharedMemorySize, ATT_SMEM);
    cudaFuncSetAttribute(gemm_bf16x3<0>,
                         cudaFuncAttributeMaxDynamicSharedMemorySize, GEMM_SMEM);
    cudaFuncSetAttribute(gemm_bf16x3<1>,
                         cudaFuncAttributeMaxDynamicSharedMemorySize, GEMM_SMEM);
    cudaFuncSetAttribute(gemm_bf16x3<2>,
                         cudaFuncAttributeMaxDynamicSharedMemorySize, GEMM_SMEM);

    dim3 gAtt(Tz / 64, Bz * NHz);

    for (int l = 0; l < Lz; l++) {
        const float* xres = (l == 0) ? hidden : xb;
        const size_t oHH = (size_t)l * Hz * Hz;
        const size_t oHF = (size_t)l * Hz * FFz;
        const size_t oH  = (size_t)l * Hz;
        const size_t oF  = (size_t)l * FFz;

        {   // fused QKV -> split bf16 q/k/v directly
            GemmArgs P = {};
            P.Ah[0] = P.Ah[1] = P.Ah[2] = xh;
            P.Al[0] = P.Al[1] = P.Al[2] = xl;
            P.Bh[0] = wqh + oHH; P.Bl[0] = wql + oHH;
            P.Bh[1] = wkh + oHH; P.Bl[1] = wkl + oHH;
            P.Bh[2] = wvh + oHH; P.Bl[2] = wvl + oHH;
            P.bias[0] = bq + oH; P.bias[1] = bk + oH; P.bias[2] = bv + oH;
            P.Ch[0] = qh; P.Cl[0] = ql;
            P.Ch[1] = kh; P.Cl[1] = kl;
            P.Ch[2] = vh; P.Cl[2] = vl;
            gemm_bf16x3<0><<<dim3(Hz / BN, Mz / BM, 3), 256, GEMM_SMEM>>>(P, Hz, Hz, Hz);
        }

        attention_kernel<<<gAtt, 256, ATT_SMEM>>>(qh, ql, kh, kl, vh, vl, mask, cth, ctl);

        {   // AO projection: split-K x3
            GemmArgs P = {};
#pragma unroll
            for (int sK = 0; sK < 3; sK++) {
                P.Ah[sK] = cth + sK * 256;
                P.Al[sK] = ctl + sK * 256;
                P.Bh[sK] = waoh + oHH + (size_t)sK * 256 * Hz;
                P.Bl[sK] = waol + oHH + (size_t)sK * 256 * Hz;
            }
            P.C[0] = p0; P.C[1] = p1; P.C[2] = p2;
            gemm_bf16x3<2><<<dim3(Hz / BN, Mz / BM, 3), 256, GEMM_SMEM>>>(P, Hz, 256, Hz);
        }
        ln_kernel<3><<<Mz, 192>>>(p0, p1, p2, p3, bao + oH, xres, g1 + oH, b1 + oH,
                                  attn, ath, atl);

        {   // FF1 + GELU
            GemmArgs P = {};
            P.Ah[0] = ath; P.Al[0] = atl;
            P.Bh[0] = wih + oHF; P.Bl[0] = wil + oHF;
            P.bias[0] = bi + oF;
            P.Ch[0] = ffh; P.Cl[0] = ffl;
            gemm_bf16x3<1><<<dim3(FFz / BN, Mz / BM, 1), 256, GEMM_SMEM>>>(P, Hz, Hz, FFz);
        }
        {   // FF2: split-K x4
            GemmArgs P = {};
#pragma unroll
            for (int sK = 0; sK < 4; sK++) {
                P.Ah[sK] = ffh + sK * 768;
                P.Al[sK] = ffl + sK * 768;
                P.Bh[sK] = woh + oHF + (size_t)sK * 768 * Hz;
                P.Bl[sK] = wol + oHF + (size_t)sK * 768 * Hz;
            }
            P.C[0] = p0; P.C[1] = p1; P.C[2] = p2; P.C[3] = p3;
            gemm_bf16x3<2><<<dim3(Hz / BN, Mz / BM, 4), 256, GEMM_SMEM>>>(P, FFz, 768, Hz);
        }
        ln_kernel<4><<<Mz, 192>>>(p0, p1, p2, p3, bo + oH, attn, g2 + oH, b2 + oH,
                                  (l == Lz - 1) ? out : xb, xh, xl);
    }
}